// round 5
// baseline (speedup 1.0000x reference)
#include <cuda_runtime.h>
#include <cuda_bf16.h>
#include <cstdint>

#define BATCH 4
#define SEQL  1024
#define CH    512
#define KW    5
#define DI    1024
#define DS    16
#define DTR   32
#define BL    (BATCH*SEQL)
#define XZW   (2*DI)

#define BK  32
#define KST 40   // BK + 8 pad (bf16 elems), 80B row stride

typedef __nv_bfloat16 bf;

// ---------------- scratch ----------------
__device__ bf    g_h[BL*CH];
__device__ float g_tmp[BL*CH];
__device__ bf    g_xz[2ull*BL*XZW];
__device__ bf    g_u[2ull*BL*DI];
__device__ float g_delta[2ull*BL*DI];
__device__ float g_xdbc[2ull*BL*64];
__device__ bf    g_y[2ull*BL*DI];
__device__ bf    g_comb[BL*2*CH];
__device__ bf    g_cwt[3ull*KW*CH*CH];     // [layer][k][co][ci]
__device__ bf    g_inw[2ull*XZW*CH];
__device__ bf    g_xw[2ull*64*DI];
__device__ bf    g_outw[2ull*CH*DI];
__device__ bf    g_projw[(size_t)CH*2*CH];

// ---------------- helpers ----------------
__device__ __forceinline__ float siluf(float x) { return x / (1.0f + __expf(-x)); }
__device__ __forceinline__ float softplusf(float x) {
    return fmaxf(x, 0.0f) + log1pf(__expf(-fabsf(x)));
}
__device__ __forceinline__ void cp16u(uint32_t d, const void* s) {
    asm volatile("cp.async.cg.shared.global [%0], [%1], 16;" :: "r"(d), "l"(s));
}
__device__ __forceinline__ void cp16z(uint32_t d, const void* s, int valid) {
    int sz = valid ? 16 : 0;
    asm volatile("cp.async.cg.shared.global [%0], [%1], 16, %2;" :: "r"(d), "l"(s), "r"(sz));
}
__device__ __forceinline__ void cpcommit() { asm volatile("cp.async.commit_group;"); }
template<int N> __device__ __forceinline__ void cpwait() {
    asm volatile("cp.async.wait_group %0;" :: "n"(N));
}
__device__ __forceinline__ void ldsm4(uint32_t* r, uint32_t a) {
    asm volatile("ldmatrix.sync.aligned.m8n8.x4.shared.b16 {%0,%1,%2,%3}, [%4];"
        : "=r"(r[0]), "=r"(r[1]), "=r"(r[2]), "=r"(r[3]) : "r"(a));
}
__device__ __forceinline__ void mma16(float* d, const uint32_t* a, const uint32_t* b) {
    asm volatile(
        "mma.sync.aligned.m16n8k16.row.col.f32.bf16.bf16.f32 "
        "{%0,%1,%2,%3}, {%4,%5,%6,%7}, {%8,%9}, {%0,%1,%2,%3};"
        : "+f"(d[0]), "+f"(d[1]), "+f"(d[2]), "+f"(d[3])
        : "r"(a[0]), "r"(a[1]), "r"(a[2]), "r"(a[3]), "r"(b[0]), "r"(b[1]));
}

// ---------------- weight conversion ----------------
__global__ void convT_k(const float* __restrict__ w) {
    int blk = blockIdx.x;             // layer*512 + co
    int co = blk & 511, layer = blk >> 9;
    __shared__ float s[CH*KW];
    const float* src = w + (size_t)blk * (CH*KW);
    for (int i = threadIdx.x; i < CH*KW; i += 256) s[i] = src[i];
    __syncthreads();
    bf* dst = g_cwt + (size_t)layer * KW * CH * CH;
    for (int i = threadIdx.x; i < CH*KW; i += 256) {
        int k = i >> 9, ci = i & 511;
        dst[(size_t)k*CH*CH + (size_t)co*CH + ci] = __float2bfloat16(s[ci*KW + k]);
    }
}

struct CvtP { const float* s[7]; bf* d[7]; };
__global__ void f2bf_all(CvtP p) {
    const int sz[7] = {262144, 262144, 16384, 16384, 131072, 131072, 131072};
    int i = blockIdx.x * 256 + threadIdx.x;
    int seg = 0;
#pragma unroll
    for (int s = 0; s < 7; s++) {
        if (seg == s && i >= sz[s]) { i -= sz[s]; seg = s + 1; }
    }
    if (seg >= 7) return;
    float4 v = ((const float4*)p.s[seg])[i];
    __nv_bfloat162* o = (__nv_bfloat162*)p.d[seg];
    o[i*2]   = __floats2bfloat162_rn(v.x, v.y);
    o[i*2+1] = __floats2bfloat162_rn(v.z, v.w);
}

// ---------------- embedding ----------------
__global__ void embed_k(const int* __restrict__ x, const float* __restrict__ emb,
                        bf* __restrict__ out) {
    int i = blockIdx.x * blockDim.x + threadIdx.x;
    if (i >= BL * CH) return;
    int row = i >> 9, c = i & (CH - 1);
    out[i] = __float2bfloat16(emb[x[row] * CH + c]);
}

// ---------------- generic bf16 MMA GEMM, 64xBNT tile, 3-stage pipeline ----------------
// EPI: 0 bf16 out, 1 fp32 out, 2 fp32 + bias + mask
template <int BNT, int EPI>
__global__ __launch_bounds__(256, 2)
void gemm_bf(const bf* __restrict__ A, const bf* __restrict__ Wt,
             const float* __restrict__ bias, void* __restrict__ OutV,
             int K, int lda, int ldo, int revz,
             const unsigned char* __restrict__ mask,
             size_t az, size_t wz, size_t oz) {
    constexpr int BMT = 64;
    constexpr int NWN = BNT / 32;
    constexpr int NWM = 8 / NWN;
    constexpr int WTM = BMT / NWM;
    constexpr int MF  = WTM / 16;
    constexpr int SST = (BMT + BNT) * KST * 2;   // stage stride bytes
    __shared__ __align__(16) bf sm[3 * (BMT + BNT) * KST];

    const int t = threadIdx.x, lane = t & 31, warp = t >> 5;
    const int wm = warp / NWN, wn = warp % NWN;
    const int m0 = blockIdx.y * BMT, n0 = blockIdx.x * BNT;
    const int dir = blockIdx.z;
    A  += (size_t)dir * az;
    Wt += (size_t)dir * wz;
    const int rev = revz && dir;

    float acc[MF][4][4];
#pragma unroll
    for (int i = 0; i < MF; i++)
#pragma unroll
        for (int j = 0; j < 4; j++)
#pragma unroll
            for (int q = 0; q < 4; q++) acc[i][j][q] = 0.0f;

    const int lrow = t >> 2;         // 0..63
    const int koff = (t & 3) * 8;
    int ga;
    {
        int r = m0 + lrow;
        ga = rev ? ((r & ~(SEQL-1)) + (SEQL-1) - (r & (SEQL-1))) : r;
    }
    const uint32_t base = (uint32_t)__cvta_generic_to_shared(&sm[0]);
    const uint32_t a_st = base + lrow * (KST*2) + koff*2;
    const uint32_t b_st = base + BMT*(KST*2) + lrow * (KST*2) + koff*2;
    const uint32_t a_off = ((wm*WTM + ((lane>>3)&1)*8 + (lane&7)) * KST + (lane>>4)*8) * 2;
    const uint32_t b_off = (BMT*KST + (wn*32 + ((lane>>4)&1)*8 + (lane&7)) * KST
                            + ((lane>>3)&1)*8) * 2;

    auto load = [&](int st, int k0) {
        cp16u(a_st + st*SST, A + (size_t)ga*lda + k0 + koff);
#pragma unroll
        for (int j = 0; j < BNT/64; j++)
            cp16u(b_st + j*64*(KST*2) + st*SST,
                  Wt + (size_t)(n0 + lrow + j*64)*K + k0 + koff);
        cpcommit();
    };
    load(0, 0);
    load(1, BK);
    const int nch = K >> 5;
    for (int ch = 0; ch < nch; ch++) {
        cpwait<1>();
        __syncthreads();
        if (ch + 2 < nch) load((ch + 2) % 3, (ch + 2) * BK);
        const uint32_t sb = base + (ch % 3) * SST;
#pragma unroll
        for (int ks = 0; ks < 2; ks++) {
            uint32_t af[MF][4], bfr[2][4];
#pragma unroll
            for (int mf = 0; mf < MF; mf++)
                ldsm4(af[mf], sb - base + base + a_off + mf*16*KST*2 + ks*32 + (ch%3)*SST - (ch%3)*SST + (sb - base) - (sb - base) + (sb - base));
            // clean recompute (the line above folds to the same constant-offset form):
#pragma unroll
            for (int mf = 0; mf < MF; mf++)
                ldsm4(af[mf], sb + a_off + mf*16*KST*2 + ks*32);
            ldsm4(bfr[0], sb + b_off + ks*32);
            ldsm4(bfr[1], sb + b_off + 16*KST*2 + ks*32);
#pragma unroll
            for (int mf = 0; mf < MF; mf++)
#pragma unroll
                for (int nf = 0; nf < 4; nf++)
                    mma16(acc[mf][nf], af[mf], &bfr[nf>>1][(nf&1)*2]);
        }
    }
    __syncthreads();
    // epilogue
#pragma unroll
    for (int mf = 0; mf < MF; mf++) {
#pragma unroll
        for (int half = 0; half < 2; half++) {
            int r = m0 + wm*WTM + mf*16 + (lane>>2) + half*8;
            unsigned char mm = (EPI == 2) ? mask[r] : 0;
#pragma unroll
            for (int nf = 0; nf < 4; nf++) {
                int c = n0 + wn*32 + nf*8 + (lane&3)*2;
                float v0 = acc[mf][nf][half*2], v1 = acc[mf][nf][half*2+1];
                if (EPI == 0) {
                    bf* Ob = (bf*)OutV + (size_t)dir*oz;
                    *(__nv_bfloat162*)(Ob + (size_t)r*ldo + c) =
                        __floats2bfloat162_rn(v0, v1);
                } else if (EPI == 1) {
                    float* Of = (float*)OutV + (size_t)dir*oz;
                    float2 f = {v0, v1};
                    *(float2*)(Of + (size_t)r*ldo + c) = f;
                } else {
                    float* Of = (float*)OutV;
                    v0 += bias[c]; v1 += bias[c+1];
                    if (mm) { v0 = 0.0f; v1 = 0.0f; }
                    float2 f = {v0, v1};
                    *(float2*)(Of + (size_t)r*ldo + c) = f;
                }
            }
        }
    }
}

// ---------------- conv1d as shifted-row bf16 GEMM, 64x128 tile, 3-stage ----------------
__global__ __launch_bounds__(256, 2)
void conv_bf(const bf* __restrict__ In, const bf* __restrict__ Wl,
             const float* __restrict__ bias, float* __restrict__ Out) {
    constexpr int BMT = 64, BNT = 128;
    constexpr int SST = (BMT + BNT) * KST * 2;
    __shared__ __align__(16) bf sm[3 * (BMT + BNT) * KST];

    const int t = threadIdx.x, lane = t & 31, warp = t >> 5;
    const int wm = warp >> 2, wn = warp & 3;   // 2 x 4, warp tile 32x32
    const int m0 = blockIdx.y * BMT, n0 = blockIdx.x * BNT;

    float acc[2][4][4];
#pragma unroll
    for (int i = 0; i < 2; i++)
#pragma unroll
        for (int j = 0; j < 4; j++)
#pragma unroll
            for (int q = 0; q < 4; q++) acc[i][j][q] = 0.0f;

    const int lrow = t >> 2;
    const int koff = (t & 3) * 8;
    const int gr = m0 + lrow;
    const int l0 = gr & (SEQL - 1);

    const uint32_t base = (uint32_t)__cvta_generic_to_shared(&sm[0]);
    const uint32_t a_st = base + lrow * (KST*2) + koff*2;
    const uint32_t b_st = base + BMT*(KST*2) + lrow * (KST*2) + koff*2;
    const uint32_t a_off = ((wm*32 + ((lane>>3)&1)*8 + (lane&7)) * KST + (lane>>4)*8) * 2;
    const uint32_t b_off = (BMT*KST + (wn*32 + ((lane>>4)&1)*8 + (lane&7)) * KST
                            + ((lane>>3)&1)*8) * 2;

    auto load = [&](int st, int ch) {
        int kk = ch >> 4, ci0 = (ch & 15) << 5;
        int sh = kk - 2;
        int v0 = (unsigned)(l0 + sh) < (unsigned)SEQL;
        int rr = v0 ? gr + sh : gr;
        cp16z(a_st + st*SST, In + (size_t)rr*CH + ci0 + koff, v0);
#pragma unroll
        for (int j = 0; j < 2; j++)
            cp16u(b_st + j*64*(KST*2) + st*SST,
                  Wl + ((size_t)kk*CH + n0 + lrow + j*64)*CH + ci0 + koff);
        cpcommit();
    };
    load(0, 0);
    load(1, 1);
    const int nch = KW * (CH/BK);   // 80
    for (int ch = 0; ch < nch; ch++) {
        cpwait<1>();
        __syncthreads();
        if (ch + 2 < nch) load((ch + 2) % 3, ch + 2);
        const uint32_t sb = base + (ch % 3) * SST;
#pragma unroll
        for (int ks = 0; ks < 2; ks++) {
            uint32_t af[2][4], bfr[2][4];
#pragma unroll
            for (int mf = 0; mf < 2; mf++)
                ldsm4(af[mf], sb + a_off + mf*16*KST*2 + ks*32);
            ldsm4(bfr[0], sb + b_off + ks*32);
            ldsm4(bfr[1], sb + b_off + 16*KST*2 + ks*32);
#pragma unroll
            for (int mf = 0; mf < 2; mf++)
#pragma unroll
                for (int nf = 0; nf < 4; nf++)
                    mma16(acc[mf][nf], af[mf], &bfr[nf>>1][(nf&1)*2]);
        }
    }
    __syncthreads();
#pragma unroll
    for (int mf = 0; mf < 2; mf++) {
#pragma unroll
        for (int half = 0; half < 2; half++) {
            int r = m0 + wm*32 + mf*16 + (lane>>2) + half*8;
#pragma unroll
            for (int nf = 0; nf < 4; nf++) {
                int c = n0 + wn*32 + nf*8 + (lane&3)*2;
                float2 f = {acc[mf][nf][half*2] + bias[c],
                            acc[mf][nf][half*2+1] + bias[c+1]};
                *(float2*)(Out + (size_t)r*CH + c) = f;
            }
        }
    }
}

// ---------------- channel LayerNorm + LeakyReLU + mask ----------------
__global__ void ln_k(const float* __restrict__ In, const float* __restrict__ gamma,
                     const float* __restrict__ beta, const unsigned char* __restrict__ m,
                     bf* __restrict__ Out) {
    int row = blockIdx.x;
    int t = threadIdx.x;   // 128
    float v[4];
    float s = 0.0f;
#pragma unroll
    for (int i = 0; i < 4; i++) {
        v[i] = In[(size_t)row * CH + t + i * 128];
        s += v[i];
    }
    __shared__ float sm[4];
    for (int o = 16; o > 0; o >>= 1) s += __shfl_xor_sync(~0u, s, o);
    if ((t & 31) == 0) sm[t >> 5] = s;
    __syncthreads();
    float mean = (sm[0] + sm[1] + sm[2] + sm[3]) * (1.0f / CH);
    __syncthreads();
    float s2 = 0.0f;
#pragma unroll
    for (int i = 0; i < 4; i++) { float d = v[i] - mean; s2 += d * d; }
    for (int o = 16; o > 0; o >>= 1) s2 += __shfl_xor_sync(~0u, s2, o);
    if ((t & 31) == 0) sm[t >> 5] = s2;
    __syncthreads();
    float var = (sm[0] + sm[1] + sm[2] + sm[3]) * (1.0f / CH);
    float rstd = rsqrtf(var + 1e-5f);
    unsigned char mm = m[row];
#pragma unroll
    for (int i = 0; i < 4; i++) {
        int c = t + i * 128;
        float h = (v[i] - mean) * rstd * gamma[c] + beta[c];
        h = (h > 0.0f) ? h : 0.2f * h;
        if (mm) h = 0.0f;
        Out[(size_t)row * CH + c] = __float2bfloat16(h);
    }
}

// ---------------- causal depthwise conv + SiLU (both dirs) ----------------
__global__ void dwconv_k(const bf* __restrict__ xz,
                         const float* __restrict__ cwf, const float* __restrict__ cbf,
                         const float* __restrict__ cwb, const float* __restrict__ cbb,
                         bf* __restrict__ out) {
    int idx = blockIdx.x * blockDim.x + threadIdx.x;
    if (idx >= 2*BL*DI) return;
    int dir = idx >> 22;
    int r = idx & ((1 << 22) - 1);
    int d = r & (DI - 1);
    int row = r >> 10;
    int l = row & (SEQL - 1);
    const bf* xzd = xz + ((size_t)dir << 23);
    const float* cw = dir ? cwb : cwf;
    float acc = (dir ? cbb : cbf)[d];
#pragma unroll
    for (int k = 0; k < 4; k++) {
        int lp = l - 3 + k;
        if (lp >= 0)
            acc = fmaf(cw[d*4 + k], __bfloat162float(xzd[(size_t)(row - l + lp)*XZW + d]), acc);
    }
    out[((size_t)dir << 22) + r] = __float2bfloat16(siluf(acc));
}

// ---------------- delta = softplus(xdbc[:, :32] @ dt_w.T + dt_b), both dirs ----------------
__global__ __launch_bounds__(256)
void dt_k(const float* __restrict__ xdbc,
          const float* __restrict__ wf, const float* __restrict__ dbf,
          const float* __restrict__ wb, const float* __restrict__ dbb,
          float* __restrict__ delta) {
    int dir = blockIdx.z;
    xdbc  += (size_t)dir * BL * 64;
    delta += (size_t)dir * BL * DI;
    const float* dt_w = dir ? wb : wf;
    const float* dt_b = dir ? dbb : dbf;
    __shared__ float xs[32][32];
    int t = threadIdx.x;
    int d0 = blockIdx.x * 256, m0 = blockIdx.y * 32;
#pragma unroll
    for (int i = 0; i < 4; i++) {
        int idx = t + i * 256;
        xs[idx >> 5][idx & 31] = xdbc[(size_t)(m0 + (idx >> 5)) * 64 + (idx & 31)];
    }
    int d = d0 + t;
    float4 wr[8];
#pragma unroll
    for (int j = 0; j < 8; j++) wr[j] = *(const float4*)(dt_w + (size_t)d*DTR + j*4);
    float b = dt_b[d];
    __syncthreads();
#pragma unroll 4
    for (int row = 0; row < 32; row++) {
        float acc = b;
#pragma unroll
        for (int j = 0; j < 8; j++) {
            float4 x4 = *(const float4*)&xs[row][j*4];
            acc = fmaf(wr[j].x, x4.x, acc);
            acc = fmaf(wr[j].y, x4.y, acc);
            acc = fmaf(wr[j].z, x4.z, acc);
            acc = fmaf(wr[j].w, x4.w, acc);
        }
        delta[(size_t)(m0 + row) * DI + d] = softplusf(acc);
    }
}

// ---------------- selective scan + gate (both dirs, prefetch depth 2) ----------------
__global__ void scan_k(const float* __restrict__ delta, const bf* __restrict__ u,
                       const float* __restrict__ xdbc, const bf* __restrict__ xz,
                       const float* __restrict__ Af, const float* __restrict__ Df,
                       const float* __restrict__ Ab, const float* __restrict__ Db,
                       bf* __restrict__ y) {
    int dir = blockIdx.z;
    delta += (size_t)dir * BL * DI;
    u     += (size_t)dir * BL * DI;
    xdbc  += (size_t)dir * BL * 64;
    xz    += (size_t)dir * BL * XZW;
    y     += (size_t)dir * BL * DI;
    const float* A_log = dir ? Ab : Af;
    const float* Dv    = dir ? Db : Df;
    int t = threadIdx.x;            // 256
    int n = t & 15, dd = t >> 4;
    int d = blockIdx.x * 16 + dd;
    int b = blockIdx.y;
    float a  = -__expf(A_log[d * DS + n]);
    float Dd = Dv[d];
    float h = 0.0f;
    int base = b * SEQL;
    float de0 = delta[(size_t)base * DI + d];
    float uu0 = __bfloat162float(u[(size_t)base * DI + d]);
    float Bv0 = xdbc[base * 64 + DTR + n];
    float Cv0 = xdbc[base * 64 + DTR + DS + n];
    float de1 = delta[(size_t)(base+1) * DI + d];
    float uu1 = __bfloat162float(u[(size_t)(base+1) * DI + d]);
    float Bv1 = xdbc[(base+1) * 64 + DTR + n];
    float Cv1 = xdbc[(base+1) * 64 + DTR + DS + n];
    for (int l = 0; l < SEQL; l++) {
        int row = base + l;
        int rn = (l + 2 < SEQL) ? row + 2 : row;
        float de2 = delta[(size_t)rn * DI + d];
        float uu2 = __bfloat162float(u[(size_t)rn * DI + d]);
        float Bv2 = xdbc[rn * 64 + DTR + n];
        float Cv2 = xdbc[rn * 64 + DTR + DS + n];
        float dA = __expf(de0 * a);
        h = fmaf(dA, h, de0 * Bv0 * uu0);
        float c = h * Cv0;
        c += __shfl_xor_sync(0xffffffffu, c, 1, 16);
        c += __shfl_xor_sync(0xffffffffu, c, 2, 16);
        c += __shfl_xor_sync(0xffffffffu, c, 4, 16);
        c += __shfl_xor_sync(0xffffffffu, c, 8, 16);
        if (n == 0) {
            float z = __bfloat162float(xz[(size_t)row * XZW + DI + d]);
            y[(size_t)row * DI + d] = __float2bfloat16((c + uu0 * Dd) * siluf(z));
        }
        de0 = de1; uu0 = uu1; Bv0 = Bv1; Cv0 = Cv1;
        de1 = de2; uu1 = uu2; Bv1 = Bv2; Cv1 = Cv2;
    }
}

// ---------------- launch ----------------
template <typename T>
static T* symp(const void* sym) {
    void* p = nullptr;
    cudaGetSymbolAddress(&p, sym);
    return (T*)p;
}

extern "C" void kernel_launch(void* const* d_in, const int* in_sizes, int n_in,
                              void* d_out, int out_size) {
    const int*           x      = (const int*)d_in[0];
    const unsigned char* m      = (const unsigned char*)d_in[2];
    const float*         emb    = (const float*)d_in[3];
    const float*         conv_w = (const float*)d_in[4];
    const float*         conv_b = (const float*)d_in[5];
    const float*         ln_g   = (const float*)d_in[6];
    const float*         ln_b   = (const float*)d_in[7];
    const float*         proj_b = (const float*)d_in[9];
    float* out = (float*)d_out;

    bf*    h    = symp<bf>(g_h);
    float* tmp  = symp<float>(g_tmp);
    bf*    xz   = symp<bf>(g_xz);
    bf*    u    = symp<bf>(g_u);
    float* dl   = symp<float>(g_delta);
    float* xdbc = symp<float>(g_xdbc);
    bf*    y    = symp<bf>(g_y);
    bf*    comb = symp<bf>(g_comb);
    bf*    cwt  = symp<bf>(g_cwt);
    bf*    inw  = symp<bf>(g_inw);
    bf*    xw   = symp<bf>(g_xw);
    bf*    outw = symp<bf>(g_outw);
    bf*    prw  = symp<bf>(g_projw);

    // 1: conv weight transpose, 2: all fp32->bf16 conversions
    convT_k<<<3*CH, 256>>>(conv_w);
    {
        CvtP p;
        p.s[0] = (const float*)d_in[10];  p.d[0] = inw;
        p.s[1] = (const float*)d_in[19];  p.d[1] = inw + (size_t)XZW*CH;
        p.s[2] = (const float*)d_in[13];  p.d[2] = xw;
        p.s[3] = (const float*)d_in[22];  p.d[3] = xw + (size_t)64*DI;
        p.s[4] = (const float*)d_in[18];  p.d[4] = outw;
        p.s[5] = (const float*)d_in[27];  p.d[5] = outw + (size_t)CH*DI;
        p.s[6] = (const float*)d_in[8];   p.d[6] = prw;
        f2bf_all<<<3712, 256>>>(p);
    }
    // 3: embedding
    embed_k<<<(BL*CH + 255)/256, 256>>>(x, emb, h);

    // 4-9: conv stack (launch #6 = conv layer 1 for ncu capture)
    for (int layer = 0; layer < 3; layer++) {
        conv_bf<<<dim3(CH/128, BL/64), 256>>>(
            h, cwt + (size_t)layer*KW*CH*CH, conv_b + layer*CH, tmp);
        ln_k<<<BL, 128>>>(tmp, ln_g + layer*CH, ln_b + layer*CH, m, h);
    }

    const float* mcwf = (const float*)d_in[11];
    const float* mcbf = (const float*)d_in[12];
    const float* mcwb = (const float*)d_in[20];
    const float* mcbb = (const float*)d_in[21];
    const float* dtwf = (const float*)d_in[14];
    const float* dtbf = (const float*)d_in[15];
    const float* dtwb = (const float*)d_in[23];
    const float* dtbb = (const float*)d_in[24];
    const float* Alf  = (const float*)d_in[16];
    const float* Dvf  = (const float*)d_in[17];
    const float* Alb  = (const float*)d_in[25];
    const float* Dvb  = (const float*)d_in[26];

    // in-proj: xz[dir] = h(rev if dir) @ inw[dir]^T
    gemm_bf<128, 0><<<dim3(XZW/128, BL/64, 2), 256>>>(
        h, inw, nullptr, xz, CH, CH, XZW, 1, nullptr,
        0, (size_t)XZW*CH, (size_t)BL*XZW);
    // depthwise conv + silu
    dwconv_k<<<(2*BL*DI + 255)/256, 256>>>(xz, mcwf, mcbf, mcwb, mcbb, u);
    // xdbc = u @ xw^T
    gemm_bf<64, 1><<<dim3(1, BL/64, 2), 256>>>(
        u, xw, nullptr, xdbc, DI, DI, 64, 0, nullptr,
        (size_t)BL*DI, (size_t)64*DI, (size_t)BL*64);
    // delta
    dt_k<<<dim3(DI/256, BL/32, 2), 256>>>(xdbc, dtwf, dtbf, dtwb, dtbb, dl);
    // selective scan + gate
    scan_k<<<dim3(DI/16, BATCH, 2), 256>>>(dl, u, xdbc, xz, Alf, Dvf, Alb, Dvb, y);
    // out-proj -> comb halves
    gemm_bf<128, 0><<<dim3(CH/128, BL/64, 2), 256>>>(
        y, outw, nullptr, comb, DI, DI, 2*CH, 0, nullptr,
        (size_t)BL*DI, (size_t)CH*DI, (size_t)CH);

    // final projection + bias + mask
    gemm_bf<128, 2><<<dim3(CH/128, BL/64, 1), 256>>>(
        comb, prw, proj_b, out, 2*CH, 2*CH, CH, 0, m, 0, 0, 0);
}

// round 7
// speedup vs baseline: 1.0473x; 1.0473x over previous
#include <cuda_runtime.h>
#include <cuda_bf16.h>
#include <cstdint>

#define BATCH 4
#define SEQL  1024
#define CH    512
#define KW    5
#define DI    1024
#define DS    16
#define DTR   32
#define BL    (BATCH*SEQL)
#define XZW   (2*DI)

#define BK  32
#define KST 40   // BK + 8 pad (bf16 elems), 80B row stride

typedef __nv_bfloat16 bf;

// ---------------- scratch ----------------
__device__ bf    g_h[BL*CH];
__device__ float g_tmp[BL*CH];
__device__ bf    g_xz[2ull*BL*XZW];
__device__ bf    g_u[2ull*BL*DI];
__device__ float g_delta[2ull*BL*DI];
__device__ float g_xdbc[2ull*BL*64];
__device__ bf    g_y[2ull*BL*DI];
__device__ bf    g_comb[BL*2*CH];
__device__ bf    g_cwt[3ull*KW*CH*CH];     // [layer][k][co][ci]
__device__ bf    g_inw[2ull*XZW*CH];
__device__ bf    g_xw[2ull*64*DI];
__device__ bf    g_outw[2ull*CH*DI];
__device__ bf    g_projw[(size_t)CH*2*CH];

// ---------------- helpers ----------------
__device__ __forceinline__ float siluf(float x) { return x / (1.0f + __expf(-x)); }
__device__ __forceinline__ float softplusf(float x) {
    return fmaxf(x, 0.0f) + log1pf(__expf(-fabsf(x)));
}
__device__ __forceinline__ void cp16u(uint32_t d, const void* s) {
    asm volatile("cp.async.cg.shared.global [%0], [%1], 16;" :: "r"(d), "l"(s));
}
__device__ __forceinline__ void cp16z(uint32_t d, const void* s, int valid) {
    int sz = valid ? 16 : 0;
    asm volatile("cp.async.cg.shared.global [%0], [%1], 16, %2;" :: "r"(d), "l"(s), "r"(sz));
}
__device__ __forceinline__ void cpcommit() { asm volatile("cp.async.commit_group;"); }
template<int N> __device__ __forceinline__ void cpwait() {
    asm volatile("cp.async.wait_group %0;" :: "n"(N));
}
__device__ __forceinline__ void ldsm4(uint32_t* r, uint32_t a) {
    asm volatile("ldmatrix.sync.aligned.m8n8.x4.shared.b16 {%0,%1,%2,%3}, [%4];"
        : "=r"(r[0]), "=r"(r[1]), "=r"(r[2]), "=r"(r[3]) : "r"(a));
}
__device__ __forceinline__ void mma16(float* d, const uint32_t* a, const uint32_t* b) {
    asm volatile(
        "mma.sync.aligned.m16n8k16.row.col.f32.bf16.bf16.f32 "
        "{%0,%1,%2,%3}, {%4,%5,%6,%7}, {%8,%9}, {%0,%1,%2,%3};"
        : "+f"(d[0]), "+f"(d[1]), "+f"(d[2]), "+f"(d[3])
        : "r"(a[0]), "r"(a[1]), "r"(a[2]), "r"(a[3]), "r"(b[0]), "r"(b[1]));
}

// ---------------- weight conversion ----------------
__global__ void convT_k(const float* __restrict__ w) {
    int blk = blockIdx.x;             // layer*512 + co
    int co = blk & 511, layer = blk >> 9;
    __shared__ float s[CH*KW];
    const float* src = w + (size_t)blk * (CH*KW);
    for (int i = threadIdx.x; i < CH*KW; i += 256) s[i] = src[i];
    __syncthreads();
    bf* dst = g_cwt + (size_t)layer * KW * CH * CH;
    for (int i = threadIdx.x; i < CH*KW; i += 256) {
        int k = i >> 9, ci = i & 511;
        dst[(size_t)k*CH*CH + (size_t)co*CH + ci] = __float2bfloat16(s[ci*KW + k]);
    }
}

struct CvtP { const float* s[7]; bf* d[7]; };
__global__ void f2bf_all(CvtP p) {
    const int sz[7] = {262144, 262144, 16384, 16384, 131072, 131072, 131072};
    int i = blockIdx.x * 256 + threadIdx.x;
    int seg = 0;
#pragma unroll
    for (int s = 0; s < 7; s++) {
        if (seg == s && i >= sz[s]) { i -= sz[s]; seg = s + 1; }
    }
    if (seg >= 7) return;
    float4 v = ((const float4*)p.s[seg])[i];
    __nv_bfloat162* o = (__nv_bfloat162*)p.d[seg];
    o[i*2]   = __floats2bfloat162_rn(v.x, v.y);
    o[i*2+1] = __floats2bfloat162_rn(v.z, v.w);
}

// ---------------- embedding ----------------
__global__ void embed_k(const int* __restrict__ x, const float* __restrict__ emb,
                        bf* __restrict__ out) {
    int i = blockIdx.x * blockDim.x + threadIdx.x;
    if (i >= BL * CH) return;
    int row = i >> 9, c = i & (CH - 1);
    out[i] = __float2bfloat16(emb[x[row] * CH + c]);
}

// ======== bf16 MMA GEMM, 128xBNT CTA tile, 4 warps (warp tile WTMx64) ========
// EPI: 0 bf16 out, 1 fp32 out, 2 fp32 + bias + mask
template <int BNT, int EPI>
__global__ __launch_bounds__(128, 2)
void gemm_bf(const bf* __restrict__ A, const bf* __restrict__ Wt,
             const float* __restrict__ bias, void* __restrict__ OutV,
             int K, int lda, int ldo, int revz,
             const unsigned char* __restrict__ mask,
             size_t az, size_t wz, size_t oz) {
    constexpr int NWN = BNT / 64;        // warps along N (1 or 2)
    constexpr int WTM = 128 / (4 / NWN); // 64 (BNT=128) or 32 (BNT=64)
    constexpr int MF  = WTM / 16;
    constexpr int SST = (128 + BNT) * KST * 2;   // stage stride bytes
    extern __shared__ char smem[];

    const int t = threadIdx.x, lane = t & 31, warp = t >> 5;
    const int wm = warp / NWN, wn = warp % NWN;
    const int m0 = blockIdx.y * 128, n0 = blockIdx.x * BNT;
    const int dir = blockIdx.z;
    A  += (size_t)dir * az;
    Wt += (size_t)dir * wz;
    const int rev = revz && dir;

    float acc[MF][8][4];
#pragma unroll
    for (int i = 0; i < MF; i++)
#pragma unroll
        for (int j = 0; j < 8; j++)
#pragma unroll
            for (int q = 0; q < 4; q++) acc[i][j][q] = 0.0f;

    const int lr0  = t >> 2;         // 0..31, rows lr0 + 32*i
    const int koff = (t & 3) * 8;
    int ga[4];
#pragma unroll
    for (int i = 0; i < 4; i++) {
        int r = m0 + lr0 + 32*i;
        ga[i] = rev ? ((r & ~(SEQL-1)) + (SEQL-1) - (r & (SEQL-1))) : r;
    }
    const uint32_t base = (uint32_t)__cvta_generic_to_shared(smem);
    const uint32_t a_st = base + lr0 * (KST*2) + koff*2;
    const uint32_t b_st = base + 128*(KST*2) + lr0 * (KST*2) + koff*2;
    const uint32_t a_off = ((wm*WTM + ((lane>>3)&1)*8 + (lane&7)) * KST + (lane>>4)*8) * 2;
    const uint32_t b_off = (128*KST + (wn*64 + ((lane>>4)&1)*8 + (lane&7)) * KST
                            + ((lane>>3)&1)*8) * 2;

    auto load = [&](int st, int k0) {
#pragma unroll
        for (int i = 0; i < 4; i++)
            cp16u(a_st + i*32*(KST*2) + st*SST, A + (size_t)ga[i]*lda + k0 + koff);
#pragma unroll
        for (int i = 0; i < BNT/32; i++)
            cp16u(b_st + i*32*(KST*2) + st*SST,
                  Wt + (size_t)(n0 + lr0 + i*32)*K + k0 + koff);
        cpcommit();
    };
    load(0, 0);
    load(1, BK);
    const int nch = K >> 5;
    for (int ch = 0; ch < nch; ch++) {
        cpwait<1>();
        __syncthreads();
        if (ch + 2 < nch) load((ch + 2) % 3, (ch + 2) * BK);
        const uint32_t sb = base + (ch % 3) * SST;
#pragma unroll
        for (int ks = 0; ks < 2; ks++) {
            uint32_t af[MF][4], bfr[4][4];
#pragma unroll
            for (int mf = 0; mf < MF; mf++)
                ldsm4(af[mf], sb + a_off + mf*16*KST*2 + ks*32);
#pragma unroll
            for (int g = 0; g < 4; g++)
                ldsm4(bfr[g], sb + b_off + g*16*KST*2 + ks*32);
#pragma unroll
            for (int mf = 0; mf < MF; mf++)
#pragma unroll
                for (int nf = 0; nf < 8; nf++)
                    mma16(acc[mf][nf], af[mf], &bfr[nf>>1][(nf&1)*2]);
        }
    }
    __syncthreads();
    // epilogue: warp covers rows [wm*WTM, +WTM), cols [wn*64, +64)
#pragma unroll
    for (int mf = 0; mf < MF; mf++) {
#pragma unroll
        for (int half = 0; half < 2; half++) {
            int r = m0 + wm*WTM + mf*16 + (lane>>2) + half*8;
            unsigned char mm = (EPI == 2) ? mask[r] : 0;
#pragma unroll
            for (int nf = 0; nf < 8; nf++) {
                int c = n0 + wn*64 + nf*8 + (lane&3)*2;
                float v0 = acc[mf][nf][half*2], v1 = acc[mf][nf][half*2+1];
                if (EPI == 0) {
                    bf* Ob = (bf*)OutV + (size_t)dir*oz;
                    *(__nv_bfloat162*)(Ob + (size_t)r*ldo + c) =
                        __floats2bfloat162_rn(v0, v1);
                } else if (EPI == 1) {
                    float* Of = (float*)OutV + (size_t)dir*oz;
                    float2 f = {v0, v1};
                    *(float2*)(Of + (size_t)r*ldo + c) = f;
                } else {
                    float* Of = (float*)OutV;
                    v0 += bias[c]; v1 += bias[c+1];
                    if (mm) { v0 = 0.0f; v1 = 0.0f; }
                    float2 f = {v0, v1};
                    *(float2*)(Of + (size_t)r*ldo + c) = f;
                }
            }
        }
    }
}

// ======== conv1d as shifted-row bf16 GEMM, 128x128 tile, 4 warps 64x64 ========
__global__ __launch_bounds__(128, 2)
void conv_bf(const bf* __restrict__ In, const bf* __restrict__ Wl,
             const float* __restrict__ bias, float* __restrict__ Out) {
    constexpr int SST = 256 * KST * 2;
    extern __shared__ char smem[];
    const int t = threadIdx.x, lane = t & 31, warp = t >> 5;
    const int wm = warp >> 1, wn = warp & 1;       // 2x2, warp tile 64x64
    const int m0 = blockIdx.y * 128, n0 = blockIdx.x * 128;

    float acc[4][8][4];
#pragma unroll
    for (int i = 0; i < 4; i++)
#pragma unroll
        for (int j = 0; j < 8; j++)
#pragma unroll
            for (int q = 0; q < 4; q++) acc[i][j][q] = 0.0f;

    const int lr0  = t >> 2;
    const int koff = (t & 3) * 8;
    int gr[4], lc[4];
#pragma unroll
    for (int i = 0; i < 4; i++) {
        gr[i] = m0 + lr0 + 32*i;
        lc[i] = gr[i] & (SEQL - 1);
    }
    const uint32_t base = (uint32_t)__cvta_generic_to_shared(smem);
    const uint32_t a_st = base + lr0 * (KST*2) + koff*2;
    const uint32_t b_st = base + 128*(KST*2) + lr0 * (KST*2) + koff*2;
    const uint32_t a_off = ((wm*64 + ((lane>>3)&1)*8 + (lane&7)) * KST + (lane>>4)*8) * 2;
    const uint32_t b_off = (128*KST + (wn*64 + ((lane>>4)&1)*8 + (lane&7)) * KST
                            + ((lane>>3)&1)*8) * 2;

    auto load = [&](int st, int ch) {
        int kk = ch >> 4, ci0 = (ch & 15) << 5;
        int sh = kk - 2;
#pragma unroll
        for (int i = 0; i < 4; i++) {
            int v = (unsigned)(lc[i] + sh) < (unsigned)SEQL;
            int rr = v ? gr[i] + sh : gr[i];
            cp16z(a_st + i*32*(KST*2) + st*SST, In + (size_t)rr*CH + ci0 + koff, v);
        }
#pragma unroll
        for (int i = 0; i < 4; i++)
            cp16u(b_st + i*32*(KST*2) + st*SST,
                  Wl + ((size_t)kk*CH + n0 + lr0 + i*32)*CH + ci0 + koff);
        cpcommit();
    };
    load(0, 0);
    load(1, 1);
    const int nch = KW * (CH/BK);    // 80
    for (int ch = 0; ch < nch; ch++) {
        cpwait<1>();
        __syncthreads();
        if (ch + 2 < nch) load((ch + 2) % 3, ch + 2);
        const uint32_t sb = base + (ch % 3) * SST;
#pragma unroll
        for (int ks = 0; ks < 2; ks++) {
            uint32_t af[4][4], bfr[4][4];
#pragma unroll
            for (int mf = 0; mf < 4; mf++)
                ldsm4(af[mf], sb + a_off + mf*16*KST*2 + ks*32);
#pragma unroll
            for (int g = 0; g < 4; g++)
                ldsm4(bfr[g], sb + b_off + g*16*KST*2 + ks*32);
#pragma unroll
            for (int mf = 0; mf < 4; mf++)
#pragma unroll
                for (int nf = 0; nf < 8; nf++)
                    mma16(acc[mf][nf], af[mf], &bfr[nf>>1][(nf&1)*2]);
        }
    }
    __syncthreads();
#pragma unroll
    for (int mf = 0; mf < 4; mf++) {
#pragma unroll
        for (int half = 0; half < 2; half++) {
            int r = m0 + wm*64 + mf*16 + (lane>>2) + half*8;
#pragma unroll
            for (int nf = 0; nf < 8; nf++) {
                int c = n0 + wn*64 + nf*8 + (lane&3)*2;
                float2 f = {acc[mf][nf][half*2] + bias[c],
                            acc[mf][nf][half*2+1] + bias[c+1]};
                *(float2*)(Out + (size_t)r*CH + c) = f;
            }
        }
    }
}

// ---------------- channel LayerNorm + LeakyReLU + mask ----------------
__global__ void ln_k(const float* __restrict__ In, const float* __restrict__ gamma,
                     const float* __restrict__ beta, const unsigned char* __restrict__ m,
                     bf* __restrict__ Out) {
    int row = blockIdx.x;
    int t = threadIdx.x;   // 128
    float v[4];
    float s = 0.0f;
#pragma unroll
    for (int i = 0; i < 4; i++) {
        v[i] = In[(size_t)row * CH + t + i * 128];
        s += v[i];
    }
    __shared__ float sm[4];
    for (int o = 16; o > 0; o >>= 1) s += __shfl_xor_sync(~0u, s, o);
    if ((t & 31) == 0) sm[t >> 5] = s;
    __syncthreads();
    float mean = (sm[0] + sm[1] + sm[2] + sm[3]) * (1.0f / CH);
    __syncthreads();
    float s2 = 0.0f;
#pragma unroll
    for (int i = 0; i < 4; i++) { float d = v[i] - mean; s2 += d * d; }
    for (int o = 16; o > 0; o >>= 1) s2 += __shfl_xor_sync(~0u, s2, o);
    if ((t & 31) == 0) sm[t >> 5] = s2;
    __syncthreads();
    float var = (sm[0] + sm[1] + sm[2] + sm[3]) * (1.0f / CH);
    float rstd = rsqrtf(var + 1e-5f);
    unsigned char mm = m[row];
#pragma unroll
    for (int i = 0; i < 4; i++) {
        int c = t + i * 128;
        float h = (v[i] - mean) * rstd * gamma[c] + beta[c];
        h = (h > 0.0f) ? h : 0.2f * h;
        if (mm) h = 0.0f;
        Out[(size_t)row * CH + c] = __float2bfloat16(h);
    }
}

// ---------------- causal depthwise conv + SiLU (both dirs) ----------------
__global__ void dwconv_k(const bf* __restrict__ xz,
                         const float* __restrict__ cwf, const float* __restrict__ cbf,
                         const float* __restrict__ cwb, const float* __restrict__ cbb,
                         bf* __restrict__ out) {
    int idx = blockIdx.x * blockDim.x + threadIdx.x;
    if (idx >= 2*BL*DI) return;
    int dir = idx >> 22;
    int r = idx & ((1 << 22) - 1);
    int d = r & (DI - 1);
    int row = r >> 10;
    int l = row & (SEQL - 1);
    const bf* xzd = xz + ((size_t)dir << 23);
    const float* cw = dir ? cwb : cwf;
    float acc = (dir ? cbb : cbf)[d];
#pragma unroll
    for (int k = 0; k < 4; k++) {
        int lp = l - 3 + k;
        if (lp >= 0)
            acc = fmaf(cw[d*4 + k], __bfloat162float(xzd[(size_t)(row - l + lp)*XZW + d]), acc);
    }
    out[((size_t)dir << 22) + r] = __float2bfloat16(siluf(acc));
}

// ---------------- delta = softplus(xdbc[:, :32] @ dt_w.T + dt_b), both dirs ----------------
__global__ __launch_bounds__(256)
void dt_k(const float* __restrict__ xdbc,
          const float* __restrict__ wf, const float* __restrict__ dbf,
          const float* __restrict__ wb, const float* __restrict__ dbb,
          float* __restrict__ delta) {
    int dir = blockIdx.z;
    xdbc  += (size_t)dir * BL * 64;
    delta += (size_t)dir * BL * DI;
    const float* dt_w = dir ? wb : wf;
    const float* dt_b = dir ? dbb : dbf;
    __shared__ float xs[32][32];
    int t = threadIdx.x;
    int d0 = blockIdx.x * 256, m0 = blockIdx.y * 32;
#pragma unroll
    for (int i = 0; i < 4; i++) {
        int idx = t + i * 256;
        xs[idx >> 5][idx & 31] = xdbc[(size_t)(m0 + (idx >> 5)) * 64 + (idx & 31)];
    }
    int d = d0 + t;
    float4 wr[8];
#pragma unroll
    for (int j = 0; j < 8; j++) wr[j] = *(const float4*)(dt_w + (size_t)d*DTR + j*4);
    float b = dt_b[d];
    __syncthreads();
#pragma unroll 4
    for (int row = 0; row < 32; row++) {
        float acc = b;
#pragma unroll
        for (int j = 0; j < 8; j++) {
            float4 x4 = *(const float4*)&xs[row][j*4];
            acc = fmaf(wr[j].x, x4.x, acc);
            acc = fmaf(wr[j].y, x4.y, acc);
            acc = fmaf(wr[j].z, x4.z, acc);
            acc = fmaf(wr[j].w, x4.w, acc);
        }
        delta[(size_t)(m0 + row) * DI + d] = softplusf(acc);
    }
}

// ---------------- selective scan + gate (both dirs) ----------------
__global__ void scan_k(const float* __restrict__ delta, const bf* __restrict__ u,
                       const float* __restrict__ xdbc, const bf* __restrict__ xz,
                       const float* __restrict__ Af, const float* __restrict__ Df,
                       const float* __restrict__ Ab, const float* __restrict__ Db,
                       bf* __restrict__ y) {
    int dir = blockIdx.z;
    delta += (size_t)dir * BL * DI;
    u     += (size_t)dir * BL * DI;
    xdbc  += (size_t)dir * BL * 64;
    xz    += (size_t)dir * BL * XZW;
    y     += (size_t)dir * BL * DI;
    const float* A_log = dir ? Ab : Af;
    const float* Dv    = dir ? Db : Df;
    int t = threadIdx.x;            // 256
    int n = t & 15, dd = t >> 4;
    int d = blockIdx.x * 16 + dd;
    int b = blockIdx.y;
    float a  = -__expf(A_log[d * DS + n]);
    float Dd = Dv[d];
    float h = 0.0f;
    int base = b * SEQL;
    float de = delta[(size_t)base * DI + d];
    float uu = __bfloat162float(u[(size_t)base * DI + d]);
    float Bv = xdbc[base * 64 + DTR + n];
    float Cv = xdbc[base * 64 + DTR + DS + n];
    for (int l = 0; l < SEQL; l++) {
        int row = base + l;
        int rn = (l + 1 < SEQL) ? row + 1 : row;
        float de_n = delta[(size_t)rn * DI + d];
        float uu_n = __bfloat162float(u[(size_t)rn * DI + d]);
        float Bv_n = xdbc[rn * 64 + DTR + n];
        float Cv_n = xdbc[rn * 64 + DTR + DS + n];
        float dA = __expf(de * a);
        h = fmaf(dA, h, de * Bv * uu);
        float c = h * Cv;
        c += __shfl_xor_sync(0xffffffffu, c, 1, 16);
        c += __shfl_xor_sync(0xffffffffu, c, 2, 16);
        c += __shfl_xor_sync(0xffffffffu, c, 4, 16);
        c += __shfl_xor_sync(0xffffffffu, c, 8, 16);
        if (n == 0) {
            float z = __bfloat162float(xz[(size_t)row * XZW + DI + d]);
            y[(size_t)row * DI + d] = __float2bfloat16((c + uu * Dd) * siluf(z));
        }
        de = de_n; uu = uu_n; Bv = Bv_n; Cv = Cv_n;
    }
}

// ---------------- launch ----------------
template <typename T>
static T* symp(const void* sym) {
    void* p = nullptr;
    cudaGetSymbolAddress(&p, sym);
    return (T*)p;
}

#define SMEM3_128 (3 * 256 * KST * 2)   // 61440
#define SMEM3_64  (3 * 192 * KST * 2)   // 46080

extern "C" void kernel_launch(void* const* d_in, const int* in_sizes, int n_in,
                              void* d_out, int out_size) {
    const int*           x      = (const int*)d_in[0];
    const unsigned char* m      = (const unsigned char*)d_in[2];
    const float*         emb    = (const float*)d_in[3];
    const float*         conv_w = (const float*)d_in[4];
    const float*         conv_b = (const float*)d_in[5];
    const float*         ln_g   = (const float*)d_in[6];
    const float*         ln_b   = (const float*)d_in[7];
    const float*         proj_b = (const float*)d_in[9];
    float* out = (float*)d_out;

    bf*    h    = symp<bf>(g_h);
    float* tmp  = symp<float>(g_tmp);
    bf*    xz   = symp<bf>(g_xz);
    bf*    u    = symp<bf>(g_u);
    float* dl   = symp<float>(g_delta);
    float* xdbc = symp<float>(g_xdbc);
    bf*    y    = symp<bf>(g_y);
    bf*    comb = symp<bf>(g_comb);
    bf*    cwt  = symp<bf>(g_cwt);
    bf*    inw  = symp<bf>(g_inw);
    bf*    xw   = symp<bf>(g_xw);
    bf*    outw = symp<bf>(g_outw);
    bf*    prw  = symp<bf>(g_projw);

    cudaFuncSetAttribute(conv_bf, cudaFuncAttributeMaxDynamicSharedMemorySize, SMEM3_128);
    cudaFuncSetAttribute(gemm_bf<128, 0>, cudaFuncAttributeMaxDynamicSharedMemorySize, SMEM3_128);
    cudaFuncSetAttribute(gemm_bf<128, 2>, cudaFuncAttributeMaxDynamicSharedMemorySize, SMEM3_128);
    cudaFuncSetAttribute(gemm_bf<64, 1>,  cudaFuncAttributeMaxDynamicSharedMemorySize, SMEM3_64);

    // 1: conv weight transpose, 2: all fp32->bf16 conversions
    convT_k<<<3*CH, 256>>>(conv_w);
    {
        CvtP p;
        p.s[0] = (const float*)d_in[10];  p.d[0] = inw;
        p.s[1] = (const float*)d_in[19];  p.d[1] = inw + (size_t)XZW*CH;
        p.s[2] = (const float*)d_in[13];  p.d[2] = xw;
        p.s[3] = (const float*)d_in[22];  p.d[3] = xw + (size_t)64*DI;
        p.s[4] = (const float*)d_in[18];  p.d[4] = outw;
        p.s[5] = (const float*)d_in[27];  p.d[5] = outw + (size_t)CH*DI;
        p.s[6] = (const float*)d_in[8];   p.d[6] = prw;
        f2bf_all<<<3712, 256>>>(p);
    }
    // 3: embedding
    embed_k<<<(BL*CH + 255)/256, 256>>>(x, emb, h);

    // 4-9: conv stack (launch #6 = conv layer 2 for ncu capture)
    for (int layer = 0; layer < 3; layer++) {
        conv_bf<<<dim3(CH/128, BL/128), 128, SMEM3_128>>>(
            h, cwt + (size_t)layer*KW*CH*CH, conv_b + layer*CH, tmp);
        ln_k<<<BL, 128>>>(tmp, ln_g + layer*CH, ln_b + layer*CH, m, h);
    }

    const float* mcwf = (const float*)d_in[11];
    const float* mcbf = (const float*)d_in[12];
    const float* mcwb = (const float*)d_in[20];
    const float* mcbb = (const float*)d_in[21];
    const float* dtwf = (const float*)d_in[14];
    const float* dtbf = (const float*)d_in[15];
    const float* dtwb = (const float*)d_in[23];
    const float* dtbb = (const float*)d_in[24];
    const float* Alf  = (const float*)d_in[16];
    const float* Dvf  = (const float*)d_in[17];
    const float* Alb  = (const float*)d_in[25];
    const float* Dvb  = (const float*)d_in[26];

    // in-proj: xz[dir] = h(rev if dir) @ inw[dir]^T
    gemm_bf<128, 0><<<dim3(XZW/128, BL/128, 2), 128, SMEM3_128>>>(
        h, inw, nullptr, xz, CH, CH, XZW, 1, nullptr,
        0, (size_t)XZW*CH, (size_t)BL*XZW);
    // depthwise conv + silu
    dwconv_k<<<(2*BL*DI + 255)/256, 256>>>(xz, mcwf, mcbf, mcwb, mcbb, u);
    // xdbc = u @ xw^T
    gemm_bf<64, 1><<<dim3(1, BL/128, 2), 128, SMEM3_64>>>(
        u, xw, nullptr, xdbc, DI, DI, 64, 0, nullptr,
        (size_t)BL*DI, (size_t)64*DI, (size_t)BL*64);
    // delta
    dt_k<<<dim3(DI/256, BL/32, 2), 256>>>(xdbc, dtwf, dtbf, dtwb, dtbb, dl);
    // selective scan + gate
    scan_k<<<dim3(DI/16, BATCH, 2), 256>>>(dl, u, xdbc, xz, Alf, Dvf, Alb, Dvb, y);
    // out-proj -> comb halves
    gemm_bf<128, 0><<<dim3(CH/128, BL/128, 2), 128, SMEM3_128>>>(
        y, outw, nullptr, comb, DI, DI, 2*CH, 0, nullptr,
        (size_t)BL*DI, (size_t)CH*DI, (size_t)CH);

    // final projection + bias + mask
    gemm_bf<128, 2><<<dim3(CH/128, BL/128, 1), 128, SMEM3_128>>>(
        comb, prw, proj_b, out, 2*CH, 2*CH, CH, 0, m, 0, 0, 0);
}

// round 8
// speedup vs baseline: 1.2165x; 1.1615x over previous
#include <cuda_runtime.h>
#include <cuda_bf16.h>
#include <cstdint>

#define BATCH 4
#define SEQL  1024
#define CH    512
#define KW    5
#define DI    1024
#define DS    16
#define DTR   32
#define BL    (BATCH*SEQL)
#define XZW   (2*DI)

#define BK  32
#define KST 40   // BK + 8 pad (bf16 elems), 80B row stride

typedef __nv_bfloat16 bf;

// ---------------- scratch ----------------
__device__ bf    g_h[BL*CH];
__device__ float g_tmp[BL*CH];
__device__ bf    g_xz[2ull*BL*XZW];
__device__ bf    g_u[2ull*BL*DI];
__device__ float g_delta[2ull*BL*DI];
__device__ float g_xdbc[2ull*BL*64];
__device__ bf    g_y[2ull*BL*DI];
__device__ bf    g_comb[BL*2*CH];
__device__ bf    g_cwt[3ull*KW*CH*CH];     // [layer][k][co][ci]
__device__ bf    g_inw[2ull*XZW*CH];
__device__ bf    g_xw[2ull*64*DI];
__device__ bf    g_outw[2ull*CH*DI];
__device__ bf    g_projw[(size_t)CH*2*CH];

// ---------------- helpers ----------------
__device__ __forceinline__ float siluf(float x) { return x / (1.0f + __expf(-x)); }
__device__ __forceinline__ float softplusf(float x) {
    return fmaxf(x, 0.0f) + log1pf(__expf(-fabsf(x)));
}
__device__ __forceinline__ void cp16u(uint32_t d, const void* s) {
    asm volatile("cp.async.cg.shared.global [%0], [%1], 16;" :: "r"(d), "l"(s));
}
__device__ __forceinline__ void cp16z(uint32_t d, const void* s, int valid) {
    int sz = valid ? 16 : 0;
    asm volatile("cp.async.cg.shared.global [%0], [%1], 16, %2;" :: "r"(d), "l"(s), "r"(sz));
}
__device__ __forceinline__ void cpcommit() { asm volatile("cp.async.commit_group;"); }
template<int N> __device__ __forceinline__ void cpwait() {
    asm volatile("cp.async.wait_group %0;" :: "n"(N));
}
__device__ __forceinline__ void ldsm4(uint32_t* r, uint32_t a) {
    asm volatile("ldmatrix.sync.aligned.m8n8.x4.shared.b16 {%0,%1,%2,%3}, [%4];"
        : "=r"(r[0]), "=r"(r[1]), "=r"(r[2]), "=r"(r[3]) : "r"(a));
}
__device__ __forceinline__ void mma16(float* d, const uint32_t* a, const uint32_t* b) {
    asm volatile(
        "mma.sync.aligned.m16n8k16.row.col.f32.bf16.bf16.f32 "
        "{%0,%1,%2,%3}, {%4,%5,%6,%7}, {%8,%9}, {%0,%1,%2,%3};"
        : "+f"(d[0]), "+f"(d[1]), "+f"(d[2]), "+f"(d[3])
        : "r"(a[0]), "r"(a[1]), "r"(a[2]), "r"(a[3]), "r"(b[0]), "r"(b[1]));
}

// ---------------- merged weight conversion (convT + all f2bf) ----------------
struct CvtP { const float* s[7]; bf* d[7]; };
__global__ void cvt_all(const float* __restrict__ conv_w, CvtP p) {
    int bx = blockIdx.x;
    if (bx < 3*CH) {
        // conv weight transpose: [co][ci][k] -> [layer][k][co][ci], bf16
        int co = bx & 511, layer = bx >> 9;
        __shared__ float s[CH*KW];
        const float* src = conv_w + (size_t)bx * (CH*KW);
        for (int i = threadIdx.x; i < CH*KW; i += 256) s[i] = src[i];
        __syncthreads();
        bf* dst = g_cwt + (size_t)layer * KW * CH * CH;
        for (int i = threadIdx.x; i < CH*KW; i += 256) {
            int k = i >> 9, ci = i & 511;
            dst[(size_t)k*CH*CH + (size_t)co*CH + ci] = __float2bfloat16(s[ci*KW + k]);
        }
    } else {
        const int sz[7] = {262144, 262144, 16384, 16384, 131072, 131072, 131072};
        int i = (bx - 3*CH) * 256 + threadIdx.x;
        int seg = 0;
#pragma unroll
        for (int s = 0; s < 7; s++) {
            if (seg == s && i >= sz[s]) { i -= sz[s]; seg = s + 1; }
        }
        if (seg >= 7) return;
        float4 v = ((const float4*)p.s[seg])[i];
        __nv_bfloat162* o = (__nv_bfloat162*)p.d[seg];
        o[i*2]   = __floats2bfloat162_rn(v.x, v.y);
        o[i*2+1] = __floats2bfloat162_rn(v.z, v.w);
    }
}

// ---------------- embedding ----------------
__global__ void embed_k(const int* __restrict__ x, const float* __restrict__ emb,
                        bf* __restrict__ out) {
    int i = blockIdx.x * blockDim.x + threadIdx.x;
    if (i >= BL * CH) return;
    int row = i >> 9, c = i & (CH - 1);
    out[i] = __float2bfloat16(emb[x[row] * CH + c]);
}

// ======== bf16 MMA GEMM, 128xBNT CTA tile, 4 warps (warp tile WTMx64) ========
// EPI: 0 bf16 out, 1 fp32 out, 2 fp32 + bias + mask
template <int BNT, int EPI>
__global__ __launch_bounds__(128, 2)
void gemm_bf(const bf* __restrict__ A, const bf* __restrict__ Wt,
             const float* __restrict__ bias, void* __restrict__ OutV,
             int K, int lda, int ldo, int revz,
             const unsigned char* __restrict__ mask,
             size_t az, size_t wz, size_t oz) {
    constexpr int NWN = BNT / 64;
    constexpr int WTM = 128 / (4 / NWN);
    constexpr int MF  = WTM / 16;
    constexpr int SST = (128 + BNT) * KST * 2;
    extern __shared__ char smem[];

    const int t = threadIdx.x, lane = t & 31, warp = t >> 5;
    const int wm = warp / NWN, wn = warp % NWN;
    const int m0 = blockIdx.y * 128, n0 = blockIdx.x * BNT;
    const int dir = blockIdx.z;
    A  += (size_t)dir * az;
    Wt += (size_t)dir * wz;
    const int rev = revz && dir;

    float acc[MF][8][4];
#pragma unroll
    for (int i = 0; i < MF; i++)
#pragma unroll
        for (int j = 0; j < 8; j++)
#pragma unroll
            for (int q = 0; q < 4; q++) acc[i][j][q] = 0.0f;

    const int lr0  = t >> 2;
    const int koff = (t & 3) * 8;
    int ga[4];
#pragma unroll
    for (int i = 0; i < 4; i++) {
        int r = m0 + lr0 + 32*i;
        ga[i] = rev ? ((r & ~(SEQL-1)) + (SEQL-1) - (r & (SEQL-1))) : r;
    }
    const uint32_t base = (uint32_t)__cvta_generic_to_shared(smem);
    const uint32_t a_st = base + lr0 * (KST*2) + koff*2;
    const uint32_t b_st = base + 128*(KST*2) + lr0 * (KST*2) + koff*2;
    const uint32_t a_off = ((wm*WTM + ((lane>>3)&1)*8 + (lane&7)) * KST + (lane>>4)*8) * 2;
    const uint32_t b_off = (128*KST + (wn*64 + ((lane>>4)&1)*8 + (lane&7)) * KST
                            + ((lane>>3)&1)*8) * 2;

    auto load = [&](int st, int k0) {
#pragma unroll
        for (int i = 0; i < 4; i++)
            cp16u(a_st + i*32*(KST*2) + st*SST, A + (size_t)ga[i]*lda + k0 + koff);
#pragma unroll
        for (int i = 0; i < BNT/32; i++)
            cp16u(b_st + i*32*(KST*2) + st*SST,
                  Wt + (size_t)(n0 + lr0 + i*32)*K + k0 + koff);
        cpcommit();
    };
    load(0, 0);
    load(1, BK);
    const int nch = K >> 5;
    for (int ch = 0; ch < nch; ch++) {
        cpwait<1>();
        __syncthreads();
        if (ch + 2 < nch) load((ch + 2) % 3, (ch + 2) * BK);
        const uint32_t sb = base + (ch % 3) * SST;
#pragma unroll
        for (int ks = 0; ks < 2; ks++) {
            uint32_t af[MF][4], bfr[4][4];
#pragma unroll
            for (int mf = 0; mf < MF; mf++)
                ldsm4(af[mf], sb + a_off + mf*16*KST*2 + ks*32);
#pragma unroll
            for (int g = 0; g < 4; g++)
                ldsm4(bfr[g], sb + b_off + g*16*KST*2 + ks*32);
#pragma unroll
            for (int mf = 0; mf < MF; mf++)
#pragma unroll
                for (int nf = 0; nf < 8; nf++)
                    mma16(acc[mf][nf], af[mf], &bfr[nf>>1][(nf&1)*2]);
        }
    }
    __syncthreads();
#pragma unroll
    for (int mf = 0; mf < MF; mf++) {
#pragma unroll
        for (int half = 0; half < 2; half++) {
            int r = m0 + wm*WTM + mf*16 + (lane>>2) + half*8;
            unsigned char mm = (EPI == 2) ? mask[r] : 0;
#pragma unroll
            for (int nf = 0; nf < 8; nf++) {
                int c = n0 + wn*64 + nf*8 + (lane&3)*2;
                float v0 = acc[mf][nf][half*2], v1 = acc[mf][nf][half*2+1];
                if (EPI == 0) {
                    bf* Ob = (bf*)OutV + (size_t)dir*oz;
                    *(__nv_bfloat162*)(Ob + (size_t)r*ldo + c) =
                        __floats2bfloat162_rn(v0, v1);
                } else if (EPI == 1) {
                    float* Of = (float*)OutV + (size_t)dir*oz;
                    float2 f = {v0, v1};
                    *(float2*)(Of + (size_t)r*ldo + c) = f;
                } else {
                    float* Of = (float*)OutV;
                    v0 += bias[c]; v1 += bias[c+1];
                    if (mm) { v0 = 0.0f; v1 = 0.0f; }
                    float2 f = {v0, v1};
                    *(float2*)(Of + (size_t)r*ldo + c) = f;
                }
            }
        }
    }
}

// ======== conv1d as shifted-row bf16 GEMM, 128x128 tile, 4 warps 64x64 ========
__global__ __launch_bounds__(128, 2)
void conv_bf(const bf* __restrict__ In, const bf* __restrict__ Wl,
             const float* __restrict__ bias, float* __restrict__ Out) {
    constexpr int SST = 256 * KST * 2;
    extern __shared__ char smem[];
    const int t = threadIdx.x, lane = t & 31, warp = t >> 5;
    const int wm = warp >> 1, wn = warp & 1;
    const int m0 = blockIdx.y * 128, n0 = blockIdx.x * 128;

    float acc[4][8][4];
#pragma unroll
    for (int i = 0; i < 4; i++)
#pragma unroll
        for (int j = 0; j < 8; j++)
#pragma unroll
            for (int q = 0; q < 4; q++) acc[i][j][q] = 0.0f;

    const int lr0  = t >> 2;
    const int koff = (t & 3) * 8;
    int gr[4], lc[4];
#pragma unroll
    for (int i = 0; i < 4; i++) {
        gr[i] = m0 + lr0 + 32*i;
        lc[i] = gr[i] & (SEQL - 1);
    }
    const uint32_t base = (uint32_t)__cvta_generic_to_shared(smem);
    const uint32_t a_st = base + lr0 * (KST*2) + koff*2;
    const uint32_t b_st = base + 128*(KST*2) + lr0 * (KST*2) + koff*2;
    const uint32_t a_off = ((wm*64 + ((lane>>3)&1)*8 + (lane&7)) * KST + (lane>>4)*8) * 2;
    const uint32_t b_off = (128*KST + (wn*64 + ((lane>>4)&1)*8 + (lane&7)) * KST
                            + ((lane>>3)&1)*8) * 2;

    auto load = [&](int st, int ch) {
        int kk = ch >> 4, ci0 = (ch & 15) << 5;
        int sh = kk - 2;
#pragma unroll
        for (int i = 0; i < 4; i++) {
            int v = (unsigned)(lc[i] + sh) < (unsigned)SEQL;
            int rr = v ? gr[i] + sh : gr[i];
            cp16z(a_st + i*32*(KST*2) + st*SST, In + (size_t)rr*CH + ci0 + koff, v);
        }
#pragma unroll
        for (int i = 0; i < 4; i++)
            cp16u(b_st + i*32*(KST*2) + st*SST,
                  Wl + ((size_t)kk*CH + n0 + lr0 + i*32)*CH + ci0 + koff);
        cpcommit();
    };
    load(0, 0);
    load(1, 1);
    const int nch = KW * (CH/BK);    // 80
    for (int ch = 0; ch < nch; ch++) {
        cpwait<1>();
        __syncthreads();
        if (ch + 2 < nch) load((ch + 2) % 3, ch + 2);
        const uint32_t sb = base + (ch % 3) * SST;
#pragma unroll
        for (int ks = 0; ks < 2; ks++) {
            uint32_t af[4][4], bfr[4][4];
#pragma unroll
            for (int mf = 0; mf < 4; mf++)
                ldsm4(af[mf], sb + a_off + mf*16*KST*2 + ks*32);
#pragma unroll
            for (int g = 0; g < 4; g++)
                ldsm4(bfr[g], sb + b_off + g*16*KST*2 + ks*32);
#pragma unroll
            for (int mf = 0; mf < 4; mf++)
#pragma unroll
                for (int nf = 0; nf < 8; nf++)
                    mma16(acc[mf][nf], af[mf], &bfr[nf>>1][(nf&1)*2]);
        }
    }
    __syncthreads();
#pragma unroll
    for (int mf = 0; mf < 4; mf++) {
#pragma unroll
        for (int half = 0; half < 2; half++) {
            int r = m0 + wm*64 + mf*16 + (lane>>2) + half*8;
#pragma unroll
            for (int nf = 0; nf < 8; nf++) {
                int c = n0 + wn*64 + nf*8 + (lane&3)*2;
                float2 f = {acc[mf][nf][half*2] + bias[c],
                            acc[mf][nf][half*2+1] + bias[c+1]};
                *(float2*)(Out + (size_t)r*CH + c) = f;
            }
        }
    }
}

// ---------------- channel LayerNorm + LeakyReLU + mask ----------------
__global__ void ln_k(const float* __restrict__ In, const float* __restrict__ gamma,
                     const float* __restrict__ beta, const unsigned char* __restrict__ m,
                     bf* __restrict__ Out) {
    int row = blockIdx.x;
    int t = threadIdx.x;   // 128
    float v[4];
    float s = 0.0f;
#pragma unroll
    for (int i = 0; i < 4; i++) {
        v[i] = In[(size_t)row * CH + t + i * 128];
        s += v[i];
    }
    __shared__ float sm[4];
    for (int o = 16; o > 0; o >>= 1) s += __shfl_xor_sync(~0u, s, o);
    if ((t & 31) == 0) sm[t >> 5] = s;
    __syncthreads();
    float mean = (sm[0] + sm[1] + sm[2] + sm[3]) * (1.0f / CH);
    __syncthreads();
    float s2 = 0.0f;
#pragma unroll
    for (int i = 0; i < 4; i++) { float d = v[i] - mean; s2 += d * d; }
    for (int o = 16; o > 0; o >>= 1) s2 += __shfl_xor_sync(~0u, s2, o);
    if ((t & 31) == 0) sm[t >> 5] = s2;
    __syncthreads();
    float var = (sm[0] + sm[1] + sm[2] + sm[3]) * (1.0f / CH);
    float rstd = rsqrtf(var + 1e-5f);
    unsigned char mm = m[row];
#pragma unroll
    for (int i = 0; i < 4; i++) {
        int c = t + i * 128;
        float h = (v[i] - mean) * rstd * gamma[c] + beta[c];
        h = (h > 0.0f) ? h : 0.2f * h;
        if (mm) h = 0.0f;
        Out[(size_t)row * CH + c] = __float2bfloat16(h);
    }
}

// ---------------- causal depthwise conv + SiLU (both dirs) ----------------
__global__ void dwconv_k(const bf* __restrict__ xz,
                         const float* __restrict__ cwf, const float* __restrict__ cbf,
                         const float* __restrict__ cwb, const float* __restrict__ cbb,
                         bf* __restrict__ out) {
    int idx = blockIdx.x * blockDim.x + threadIdx.x;
    if (idx >= 2*BL*DI) return;
    int dir = idx >> 22;
    int r = idx & ((1 << 22) - 1);
    int d = r & (DI - 1);
    int row = r >> 10;
    int l = row & (SEQL - 1);
    const bf* xzd = xz + ((size_t)dir << 23);
    const float* cw = dir ? cwb : cwf;
    float acc = (dir ? cbb : cbf)[d];
#pragma unroll
    for (int k = 0; k < 4; k++) {
        int lp = l - 3 + k;
        if (lp >= 0)
            acc = fmaf(cw[d*4 + k], __bfloat162float(xzd[(size_t)(row - l + lp)*XZW + d]), acc);
    }
    out[((size_t)dir << 22) + r] = __float2bfloat16(siluf(acc));
}

// ---------------- delta = softplus(xdbc[:, :32] @ dt_w.T + dt_b), both dirs ----------------
__global__ __launch_bounds__(256)
void dt_k(const float* __restrict__ xdbc,
          const float* __restrict__ wf, const float* __restrict__ dbf,
          const float* __restrict__ wb, const float* __restrict__ dbb,
          float* __restrict__ delta) {
    int dir = blockIdx.z;
    xdbc  += (size_t)dir * BL * 64;
    delta += (size_t)dir * BL * DI;
    const float* dt_w = dir ? wb : wf;
    const float* dt_b = dir ? dbb : dbf;
    __shared__ float xs[32][32];
    int t = threadIdx.x;
    int d0 = blockIdx.x * 256, m0 = blockIdx.y * 32;
#pragma unroll
    for (int i = 0; i < 4; i++) {
        int idx = t + i * 256;
        xs[idx >> 5][idx & 31] = xdbc[(size_t)(m0 + (idx >> 5)) * 64 + (idx & 31)];
    }
    int d = d0 + t;
    float4 wr[8];
#pragma unroll
    for (int j = 0; j < 8; j++) wr[j] = *(const float4*)(dt_w + (size_t)d*DTR + j*4);
    float b = dt_b[d];
    __syncthreads();
#pragma unroll 4
    for (int row = 0; row < 32; row++) {
        float acc = b;
#pragma unroll
        for (int j = 0; j < 8; j++) {
            float4 x4 = *(const float4*)&xs[row][j*4];
            acc = fmaf(wr[j].x, x4.x, acc);
            acc = fmaf(wr[j].y, x4.y, acc);
            acc = fmaf(wr[j].z, x4.z, acc);
            acc = fmaf(wr[j].w, x4.w, acc);
        }
        delta[(size_t)(m0 + row) * DI + d] = softplusf(acc);
    }
}

// ======== selective scan + gate: thread = (dir, b, d), 16 states in regs ========
__global__ __launch_bounds__(128)
void scan_k(const float* __restrict__ delta, const bf* __restrict__ u,
            const float* __restrict__ xdbc, const bf* __restrict__ xz,
            const float* __restrict__ Af, const float* __restrict__ Df,
            const float* __restrict__ Ab, const float* __restrict__ Db,
            bf* __restrict__ y) {
    int dir = blockIdx.z;
    delta += (size_t)dir * BL * DI;
    u     += (size_t)dir * BL * DI;
    xdbc  += (size_t)dir * BL * 64;
    xz    += (size_t)dir * BL * XZW;
    y     += (size_t)dir * BL * DI;
    const float* A_log = dir ? Ab : Af;
    const float* Dv    = dir ? Db : Df;
    int d = blockIdx.x * 128 + threadIdx.x;
    int b = blockIdx.y;

    float aa[16];
#pragma unroll
    for (int n = 0; n < 16; n++)
        aa[n] = -__expf(A_log[d * DS + n]) * 1.4426950408889634f;   // log2(e) fold
    float Dd = Dv[d];
    float h[16];
#pragma unroll
    for (int n = 0; n < 16; n++) h[n] = 0.0f;

    int base = b * SEQL;
    const float* pd = delta + (size_t)base * DI + d;
    const bf*    pu = u     + (size_t)base * DI + d;
    const bf*    pz = xz    + (size_t)base * XZW + DI + d;
    const float* pb = xdbc  + (size_t)base * 64;
    bf*          py = y     + (size_t)base * DI + d;

    // software pipeline: scalars depth-2, B/C rows depth-1
    float de0 = pd[0], de1 = pd[DI];
    float uu0 = __bfloat162float(pu[0]), uu1 = __bfloat162float(pu[DI]);
    float z0  = __bfloat162float(pz[0]), z1  = __bfloat162float(pz[XZW]);
    float4 Bv[4], Cv[4];
#pragma unroll
    for (int j = 0; j < 4; j++) {
        Bv[j] = *(const float4*)(pb + 32 + 4*j);
        Cv[j] = *(const float4*)(pb + 48 + 4*j);
    }
    for (int l = 0; l < SEQL; l++) {
        float de2 = 0.0f, uu2 = 0.0f, z2 = 0.0f;
        if (l + 2 < SEQL) {
            de2 = pd[2*DI];
            uu2 = __bfloat162float(pu[2*DI]);
            z2  = __bfloat162float(pz[2*XZW]);
        }
        float4 Bn[4], Cn[4];
        {
            const float* pb1 = pb + ((l + 1 < SEQL) ? 64 : 0);
#pragma unroll
            for (int j = 0; j < 4; j++) {
                Bn[j] = *(const float4*)(pb1 + 32 + 4*j);
                Cn[j] = *(const float4*)(pb1 + 48 + 4*j);
            }
        }
        float du = de0 * uu0;
        const float* Bf = (const float*)Bv;
        const float* Cf = (const float*)Cv;
        float a0 = 0.0f, a1 = 0.0f, a2 = 0.0f, a3 = 0.0f;
#pragma unroll
        for (int n = 0; n < 16; n++) {
            float dA = exp2f(de0 * aa[n]);
            h[n] = fmaf(dA, h[n], du * Bf[n]);
            float tt = h[n] * Cf[n];
            if ((n & 3) == 0) a0 += tt;
            else if ((n & 3) == 1) a1 += tt;
            else if ((n & 3) == 2) a2 += tt;
            else a3 += tt;
        }
        float yy = (a0 + a1) + (a2 + a3) + uu0 * Dd;
        float sg = z0 / (1.0f + __expf(-z0));
        py[0] = __float2bfloat16(yy * sg);

        pd += DI; pu += DI; pz += XZW; pb += 64; py += DI;
        de0 = de1; de1 = de2;
        uu0 = uu1; uu1 = uu2;
        z0 = z1;   z1 = z2;
#pragma unroll
        for (int j = 0; j < 4; j++) { Bv[j] = Bn[j]; Cv[j] = Cn[j]; }
    }
}

// ---------------- launch ----------------
template <typename T>
static T* symp(const void* sym) {
    void* p = nullptr;
    cudaGetSymbolAddress(&p, sym);
    return (T*)p;
}

#define SMEM3_128 (3 * 256 * KST * 2)   // 61440
#define SMEM3_64  (3 * 192 * KST * 2)   // 46080

extern "C" void kernel_launch(void* const* d_in, const int* in_sizes, int n_in,
                              void* d_out, int out_size) {
    const int*           x      = (const int*)d_in[0];
    const unsigned char* m      = (const unsigned char*)d_in[2];
    const float*         emb    = (const float*)d_in[3];
    const float*         conv_w = (const float*)d_in[4];
    const float*         conv_b = (const float*)d_in[5];
    const float*         ln_g   = (const float*)d_in[6];
    const float*         ln_b   = (const float*)d_in[7];
    const float*         proj_b = (const float*)d_in[9];
    float* out = (float*)d_out;

    bf*    h    = symp<bf>(g_h);
    float* tmp  = symp<float>(g_tmp);
    bf*    xz   = symp<bf>(g_xz);
    bf*    u    = symp<bf>(g_u);
    float* dl   = symp<float>(g_delta);
    float* xdbc = symp<float>(g_xdbc);
    bf*    y    = symp<bf>(g_y);
    bf*    comb = symp<bf>(g_comb);
    bf*    cwt  = symp<bf>(g_cwt);
    bf*    inw  = symp<bf>(g_inw);
    bf*    xw   = symp<bf>(g_xw);
    bf*    outw = symp<bf>(g_outw);
    bf*    prw  = symp<bf>(g_projw);

    cudaFuncSetAttribute(conv_bf, cudaFuncAttributeMaxDynamicSharedMemorySize, SMEM3_128);
    cudaFuncSetAttribute(gemm_bf<128, 0>, cudaFuncAttributeMaxDynamicSharedMemorySize, SMEM3_128);
    cudaFuncSetAttribute(gemm_bf<128, 2>, cudaFuncAttributeMaxDynamicSharedMemorySize, SMEM3_128);
    cudaFuncSetAttribute(gemm_bf<64, 1>,  cudaFuncAttributeMaxDynamicSharedMemorySize, SMEM3_64);

    // 1: merged weight conversion (convT + f2bf)
    {
        CvtP p;
        p.s[0] = (const float*)d_in[10];  p.d[0] = inw;
        p.s[1] = (const float*)d_in[19];  p.d[1] = inw + (size_t)XZW*CH;
        p.s[2] = (const float*)d_in[13];  p.d[2] = xw;
        p.s[3] = (const float*)d_in[22];  p.d[3] = xw + (size_t)64*DI;
        p.s[4] = (const float*)d_in[18];  p.d[4] = outw;
        p.s[5] = (const float*)d_in[27];  p.d[5] = outw + (size_t)CH*DI;
        p.s[6] = (const float*)d_in[8];   p.d[6] = prw;
        cvt_all<<<3*CH + 3712, 256>>>(conv_w, p);
    }
    // 2: embedding
    embed_k<<<(BL*CH + 255)/256, 256>>>(x, emb, h);

    // 3-8: conv stack (launch #6 = ln_k layer 1 for ncu capture)
    for (int layer = 0; layer < 3; layer++) {
        conv_bf<<<dim3(CH/128, BL/128), 128, SMEM3_128>>>(
            h, cwt + (size_t)layer*KW*CH*CH, conv_b + layer*CH, tmp);
        ln_k<<<BL, 128>>>(tmp, ln_g + layer*CH, ln_b + layer*CH, m, h);
    }

    const float* mcwf = (const float*)d_in[11];
    const float* mcbf = (const float*)d_in[12];
    const float* mcwb = (const float*)d_in[20];
    const float* mcbb = (const float*)d_in[21];
    const float* dtwf = (const float*)d_in[14];
    const float* dtbf = (const float*)d_in[15];
    const float* dtwb = (const float*)d_in[23];
    const float* dtbb = (const float*)d_in[24];
    const float* Alf  = (const float*)d_in[16];
    const float* Dvf  = (const float*)d_in[17];
    const float* Alb  = (const float*)d_in[25];
    const float* Dvb  = (const float*)d_in[26];

    // in-proj: xz[dir] = h(rev if dir) @ inw[dir]^T
    gemm_bf<128, 0><<<dim3(XZW/128, BL/128, 2), 128, SMEM3_128>>>(
        h, inw, nullptr, xz, CH, CH, XZW, 1, nullptr,
        0, (size_t)XZW*CH, (size_t)BL*XZW);
    // depthwise conv + silu
    dwconv_k<<<(2*BL*DI + 255)/256, 256>>>(xz, mcwf, mcbf, mcwb, mcbb, u);
    // xdbc = u @ xw^T
    gemm_bf<64, 1><<<dim3(1, BL/128, 2), 128, SMEM3_64>>>(
        u, xw, nullptr, xdbc, DI, DI, 64, 0, nullptr,
        (size_t)BL*DI, (size_t)64*DI, (size_t)BL*64);
    // delta
    dt_k<<<dim3(DI/256, BL/32, 2), 256>>>(xdbc, dtwf, dtbf, dtwb, dtbb, dl);
    // selective scan + gate (register-state version)
    scan_k<<<dim3(DI/128, BATCH, 2), 128>>>(dl, u, xdbc, xz, Alf, Dvf, Alb, Dvb, y);
    // out-proj -> comb halves
    gemm_bf<128, 0><<<dim3(CH/128, BL/128, 2), 128, SMEM3_128>>>(
        y, outw, nullptr, comb, DI, DI, 2*CH, 0, nullptr,
        (size_t)BL*DI, (size_t)CH*DI, (size_t)CH);

    // final projection + bias + mask
    gemm_bf<128, 2><<<dim3(CH/128, BL/128, 1), 128, SMEM3_128>>>(
        comb, prw, proj_b, out, 2*CH, 2*CH, CH, 0, m, 0, 0, 0);
}

// round 9
// speedup vs baseline: 1.3138x; 1.0800x over previous
#include <cuda_runtime.h>
#include <cuda_bf16.h>
#include <cstdint>

#define BATCH 4
#define SEQL  1024
#define CH    512
#define KW    5
#define DI    1024
#define DS    16
#define DTR   32
#define BL    (BATCH*SEQL)
#define XZW   (2*DI)

#define BK  64
#define KST 72   // BK + 8 pad (bf16 elems), 144B row stride

typedef __nv_bfloat16 bf;

// ---------------- scratch ----------------
__device__ bf    g_h[BL*CH];
__device__ float g_tmp[BL*CH];
__device__ bf    g_xz[2ull*BL*XZW];
__device__ bf    g_u[2ull*BL*DI];
__device__ float g_delta[2ull*BL*DI];
__device__ float g_xdbc[2ull*BL*64];
__device__ bf    g_y[(size_t)BL*2048];        // [row][dir*1024+d]
__device__ bf    g_cwt[3ull*KW*CH*CH];        // [layer][k][co][ci]
__device__ bf    g_inw[2ull*XZW*CH];
__device__ bf    g_xw[2ull*64*DI];
__device__ bf    g_owT[2ull*DI*CH];           // transposed out-proj weights [dir][e][k]
__device__ bf    g_projw[(size_t)CH*2*CH];
__device__ bf    g_wfuse[(size_t)CH*2048];    // [c][dir*1024+e]

// ---------------- helpers ----------------
__device__ __forceinline__ float siluf(float x) { return x / (1.0f + __expf(-x)); }
__device__ __forceinline__ float softplusf(float x) {
    return fmaxf(x, 0.0f) + log1pf(__expf(-fabsf(x)));
}
__device__ __forceinline__ void cp16u(uint32_t d, const void* s) {
    asm volatile("cp.async.cg.shared.global [%0], [%1], 16;" :: "r"(d), "l"(s));
}
__device__ __forceinline__ void cp16z(uint32_t d, const void* s, int valid) {
    int sz = valid ? 16 : 0;
    asm volatile("cp.async.cg.shared.global [%0], [%1], 16, %2;" :: "r"(d), "l"(s), "r"(sz));
}
__device__ __forceinline__ void cpcommit() { asm volatile("cp.async.commit_group;"); }
template<int N> __device__ __forceinline__ void cpwait() {
    asm volatile("cp.async.wait_group %0;" :: "n"(N));
}
__device__ __forceinline__ void ldsm4(uint32_t* r, uint32_t a) {
    asm volatile("ldmatrix.sync.aligned.m8n8.x4.shared.b16 {%0,%1,%2,%3}, [%4];"
        : "=r"(r[0]), "=r"(r[1]), "=r"(r[2]), "=r"(r[3]) : "r"(a));
}
__device__ __forceinline__ void mma16(float* d, const uint32_t* a, const uint32_t* b) {
    asm volatile(
        "mma.sync.aligned.m16n8k16.row.col.f32.bf16.bf16.f32 "
        "{%0,%1,%2,%3}, {%4,%5,%6,%7}, {%8,%9}, {%0,%1,%2,%3};"
        : "+f"(d[0]), "+f"(d[1]), "+f"(d[2]), "+f"(d[3])
        : "r"(a[0]), "r"(a[1]), "r"(a[2]), "r"(a[3]), "r"(b[0]), "r"(b[1]));
}

// ---------------- merged weight conversion ----------------
struct CvtP { const float* s[5]; bf* d[5]; const float* owf; const float* owb; };
__global__ void cvt_all(const float* __restrict__ conv_w, CvtP p) {
    __shared__ float s[64*65];
    int bx = blockIdx.x;
    if (bx < 3*CH) {
        // conv weight transpose: [co][ci][k] -> [layer][k][co][ci], bf16
        int co = bx & 511, layer = bx >> 9;
        const float* src = conv_w + (size_t)bx * (CH*KW);
        for (int i = threadIdx.x; i < CH*KW; i += 256) s[i] = src[i];
        __syncthreads();
        bf* dst = g_cwt + (size_t)layer * KW * CH * CH;
        for (int i = threadIdx.x; i < CH*KW; i += 256) {
            int k = i >> 9, ci = i & 511;
            dst[(size_t)k*CH*CH + (size_t)co*CH + ci] = __float2bfloat16(s[ci*KW + k]);
        }
    } else if (bx < 3*CH + 256) {
        // out-proj transpose: ow[512][1024] fp32 -> owT[dir][1024][512] bf16 (64x64 tiles)
        int idx = bx - 3*CH;
        int dir = idx >> 7;
        int te = (idx & 127) >> 3, tk = idx & 7;
        const float* ow = dir ? p.owb : p.owf;
        for (int i = threadIdx.x; i < 4096; i += 256) {
            int kk = i >> 6, ee = i & 63;
            s[kk*65 + ee] = ow[(size_t)(tk*64 + kk)*DI + te*64 + ee];
        }
        __syncthreads();
        bf* dst = g_owT + (size_t)dir*DI*CH;
        for (int i = threadIdx.x; i < 4096; i += 256) {
            int ee = i >> 6, kk = i & 63;
            dst[(size_t)(te*64 + ee)*CH + tk*64 + kk] = __float2bfloat16(s[kk*65 + ee]);
        }
    } else {
        const int sz[5] = {262144, 262144, 16384, 16384, 131072};
        int i = (bx - 3*CH - 256) * 256 + threadIdx.x;
        int seg = 0;
#pragma unroll
        for (int q = 0; q < 5; q++) {
            if (seg == q && i >= sz[q]) { i -= sz[q]; seg = q + 1; }
        }
        if (seg >= 5) return;
        float4 v = ((const float4*)p.s[seg])[i];
        __nv_bfloat162* o = (__nv_bfloat162*)p.d[seg];
        o[i*2]   = __floats2bfloat162_rn(v.x, v.y);
        o[i*2+1] = __floats2bfloat162_rn(v.z, v.w);
    }
}

// ---------------- embedding ----------------
__global__ void embed_k(const int* __restrict__ x, const float* __restrict__ emb,
                        bf* __restrict__ out) {
    int i = blockIdx.x * blockDim.x + threadIdx.x;
    if (i >= BL * CH) return;
    int row = i >> 9, c = i & (CH - 1);
    out[i] = __float2bfloat16(emb[x[row] * CH + c]);
}

// ======== bf16 MMA GEMM, 128xBNT CTA tile, 4 warps, BK=64, 3-stage ========
// EPI: 0 bf16 out, 1 fp32 out, 2 fp32 + bias + mask
template <int BNT, int EPI>
__global__ __launch_bounds__(128, 2)
void gemm_bf(const bf* __restrict__ A, const bf* __restrict__ Wt,
             const float* __restrict__ bias, void* __restrict__ OutV,
             int K, int lda, int ldo, int revz,
             const unsigned char* __restrict__ mask,
             size_t az, size_t wz, size_t oz) {
    constexpr int NWN = BNT / 64;
    constexpr int WTM = 128 / (4 / NWN);
    constexpr int MF  = WTM / 16;
    constexpr int SST = (128 + BNT) * KST * 2;
    extern __shared__ char smem[];

    const int t = threadIdx.x, lane = t & 31, warp = t >> 5;
    const int wm = warp / NWN, wn = warp % NWN;
    const int m0 = blockIdx.y * 128, n0 = blockIdx.x * BNT;
    const int dir = blockIdx.z;
    A  += (size_t)dir * az;
    Wt += (size_t)dir * wz;
    const int rev = revz && dir;

    float acc[MF][8][4];
#pragma unroll
    for (int i = 0; i < MF; i++)
#pragma unroll
        for (int j = 0; j < 8; j++)
#pragma unroll
            for (int q = 0; q < 4; q++) acc[i][j][q] = 0.0f;

    const int lr   = t >> 3;         // 0..15, rows lr + 16*i
    const int koff = (t & 7) * 8;    // 0..56
    int ga[8];
#pragma unroll
    for (int i = 0; i < 8; i++) {
        int r = m0 + lr + 16*i;
        ga[i] = rev ? ((r & ~(SEQL-1)) + (SEQL-1) - (r & (SEQL-1))) : r;
    }
    const uint32_t base = (uint32_t)__cvta_generic_to_shared(smem);
    const uint32_t a_st = base + lr * (KST*2) + koff*2;
    const uint32_t b_st = base + 128*(KST*2) + lr * (KST*2) + koff*2;
    const uint32_t a_off = ((wm*WTM + ((lane>>3)&1)*8 + (lane&7)) * KST + (lane>>4)*8) * 2;
    const uint32_t b_off = (128*KST + (wn*64 + ((lane>>4)&1)*8 + (lane&7)) * KST
                            + ((lane>>3)&1)*8) * 2;

    auto load = [&](int st, int k0) {
#pragma unroll
        for (int i = 0; i < 8; i++)
            cp16u(a_st + i*16*(KST*2) + st*SST, A + (size_t)ga[i]*lda + k0 + koff);
#pragma unroll
        for (int i = 0; i < BNT/16; i++)
            cp16u(b_st + i*16*(KST*2) + st*SST,
                  Wt + (size_t)(n0 + lr + i*16)*K + k0 + koff);
        cpcommit();
    };
    load(0, 0);
    load(1, BK);
    const int nch = K >> 6;
    for (int ch = 0; ch < nch; ch++) {
        cpwait<1>();
        __syncthreads();
        if (ch + 2 < nch) load((ch + 2) % 3, (ch + 2) * BK);
        const uint32_t sb = base + (ch % 3) * SST;
#pragma unroll
        for (int ks = 0; ks < 4; ks++) {
            uint32_t af[MF][4], bfr[4][4];
#pragma unroll
            for (int mf = 0; mf < MF; mf++)
                ldsm4(af[mf], sb + a_off + mf*16*KST*2 + ks*32);
#pragma unroll
            for (int g = 0; g < 4; g++)
                ldsm4(bfr[g], sb + b_off + g*16*KST*2 + ks*32);
#pragma unroll
            for (int mf = 0; mf < MF; mf++)
#pragma unroll
                for (int nf = 0; nf < 8; nf++)
                    mma16(acc[mf][nf], af[mf], &bfr[nf>>1][(nf&1)*2]);
        }
    }
    __syncthreads();
#pragma unroll
    for (int mf = 0; mf < MF; mf++) {
#pragma unroll
        for (int half = 0; half < 2; half++) {
            int r = m0 + wm*WTM + mf*16 + (lane>>2) + half*8;
            unsigned char mm = (EPI == 2) ? mask[r] : 0;
#pragma unroll
            for (int nf = 0; nf < 8; nf++) {
                int c = n0 + wn*64 + nf*8 + (lane&3)*2;
                float v0 = acc[mf][nf][half*2], v1 = acc[mf][nf][half*2+1];
                if (EPI == 0) {
                    bf* Ob = (bf*)OutV + (size_t)dir*oz;
                    *(__nv_bfloat162*)(Ob + (size_t)r*ldo + c) =
                        __floats2bfloat162_rn(v0, v1);
                } else if (EPI == 1) {
                    float* Of = (float*)OutV + (size_t)dir*oz;
                    float2 f = {v0, v1};
                    *(float2*)(Of + (size_t)r*ldo + c) = f;
                } else {
                    float* Of = (float*)OutV;
                    v0 += bias[c]; v1 += bias[c+1];
                    if (mm) { v0 = 0.0f; v1 = 0.0f; }
                    float2 f = {v0, v1};
                    *(float2*)(Of + (size_t)r*ldo + c) = f;
                }
            }
        }
    }
}

// ======== conv1d as shifted-row bf16 GEMM, 128x128 tile, BK=64 ========
__global__ __launch_bounds__(128, 2)
void conv_bf(const bf* __restrict__ In, const bf* __restrict__ Wl,
             const float* __restrict__ bias, float* __restrict__ Out) {
    constexpr int SST = 256 * KST * 2;
    extern __shared__ char smem[];
    const int t = threadIdx.x, lane = t & 31, warp = t >> 5;
    const int wm = warp >> 1, wn = warp & 1;
    const int m0 = blockIdx.y * 128, n0 = blockIdx.x * 128;

    float acc[4][8][4];
#pragma unroll
    for (int i = 0; i < 4; i++)
#pragma unroll
        for (int j = 0; j < 8; j++)
#pragma unroll
            for (int q = 0; q < 4; q++) acc[i][j][q] = 0.0f;

    const int lr   = t >> 3;
    const int koff = (t & 7) * 8;
    int gr[8], lc[8];
#pragma unroll
    for (int i = 0; i < 8; i++) {
        gr[i] = m0 + lr + 16*i;
        lc[i] = gr[i] & (SEQL - 1);
    }
    const uint32_t base = (uint32_t)__cvta_generic_to_shared(smem);
    const uint32_t a_st = base + lr * (KST*2) + koff*2;
    const uint32_t b_st = base + 128*(KST*2) + lr * (KST*2) + koff*2;
    const uint32_t a_off = ((wm*64 + ((lane>>3)&1)*8 + (lane&7)) * KST + (lane>>4)*8) * 2;
    const uint32_t b_off = (128*KST + (wn*64 + ((lane>>4)&1)*8 + (lane&7)) * KST
                            + ((lane>>3)&1)*8) * 2;

    auto load = [&](int st, int ch) {
        int kk = ch >> 3, ci0 = (ch & 7) << 6;
        int sh = kk - 2;
#pragma unroll
        for (int i = 0; i < 8; i++) {
            int v = (unsigned)(lc[i] + sh) < (unsigned)SEQL;
            int rr = v ? gr[i] + sh : gr[i];
            cp16z(a_st + i*16*(KST*2) + st*SST, In + (size_t)rr*CH + ci0 + koff, v);
        }
#pragma unroll
        for (int i = 0; i < 8; i++)
            cp16u(b_st + i*16*(KST*2) + st*SST,
                  Wl + ((size_t)kk*CH + n0 + lr + i*16)*CH + ci0 + koff);
        cpcommit();
    };
    load(0, 0);
    load(1, 1);
    const int nch = KW * (CH/BK);    // 40
    for (int ch = 0; ch < nch; ch++) {
        cpwait<1>();
        __syncthreads();
        if (ch + 2 < nch) load((ch + 2) % 3, ch + 2);
        const uint32_t sb = base + (ch % 3) * SST;
#pragma unroll
        for (int ks = 0; ks < 4; ks++) {
            uint32_t af[4][4], bfr[4][4];
#pragma unroll
            for (int mf = 0; mf < 4; mf++)
                ldsm4(af[mf], sb + a_off + mf*16*KST*2 + ks*32);
#pragma unroll
            for (int g = 0; g < 4; g++)
                ldsm4(bfr[g], sb + b_off + g*16*KST*2 + ks*32);
#pragma unroll
            for (int mf = 0; mf < 4; mf++)
#pragma unroll
                for (int nf = 0; nf < 8; nf++)
                    mma16(acc[mf][nf], af[mf], &bfr[nf>>1][(nf&1)*2]);
        }
    }
    __syncthreads();
#pragma unroll
    for (int mf = 0; mf < 4; mf++) {
#pragma unroll
        for (int half = 0; half < 2; half++) {
            int r = m0 + wm*64 + mf*16 + (lane>>2) + half*8;
#pragma unroll
            for (int nf = 0; nf < 8; nf++) {
                int c = n0 + wn*64 + nf*8 + (lane&3)*2;
                float2 f = {acc[mf][nf][half*2] + bias[c],
                            acc[mf][nf][half*2+1] + bias[c+1]};
                *(float2*)(Out + (size_t)r*CH + c) = f;
            }
        }
    }
}

// ---------------- channel LayerNorm + LeakyReLU + mask ----------------
__global__ void ln_k(const float* __restrict__ In, const float* __restrict__ gamma,
                     const float* __restrict__ beta, const unsigned char* __restrict__ m,
                     bf* __restrict__ Out) {
    int row = blockIdx.x;
    int t = threadIdx.x;   // 128
    float v[4];
    float s = 0.0f;
#pragma unroll
    for (int i = 0; i < 4; i++) {
        v[i] = In[(size_t)row * CH + t + i * 128];
        s += v[i];
    }
    __shared__ float sm[4];
    for (int o = 16; o > 0; o >>= 1) s += __shfl_xor_sync(~0u, s, o);
    if ((t & 31) == 0) sm[t >> 5] = s;
    __syncthreads();
    float mean = (sm[0] + sm[1] + sm[2] + sm[3]) * (1.0f / CH);
    __syncthreads();
    float s2 = 0.0f;
#pragma unroll
    for (int i = 0; i < 4; i++) { float d = v[i] - mean; s2 += d * d; }
    for (int o = 16; o > 0; o >>= 1) s2 += __shfl_xor_sync(~0u, s2, o);
    if ((t & 31) == 0) sm[t >> 5] = s2;
    __syncthreads();
    float var = (sm[0] + sm[1] + sm[2] + sm[3]) * (1.0f / CH);
    float rstd = rsqrtf(var + 1e-5f);
    unsigned char mm = m[row];
#pragma unroll
    for (int i = 0; i < 4; i++) {
        int c = t + i * 128;
        float h = (v[i] - mean) * rstd * gamma[c] + beta[c];
        h = (h > 0.0f) ? h : 0.2f * h;
        if (mm) h = 0.0f;
        Out[(size_t)row * CH + c] = __float2bfloat16(h);
    }
}

// ---------------- causal depthwise conv + SiLU (both dirs) ----------------
__global__ void dwconv_k(const bf* __restrict__ xz,
                         const float* __restrict__ cwf, const float* __restrict__ cbf,
                         const float* __restrict__ cwb, const float* __restrict__ cbb,
                         bf* __restrict__ out) {
    int idx = blockIdx.x * blockDim.x + threadIdx.x;
    if (idx >= 2*BL*DI) return;
    int dir = idx >> 22;
    int r = idx & ((1 << 22) - 1);
    int d = r & (DI - 1);
    int row = r >> 10;
    int l = row & (SEQL - 1);
    const bf* xzd = xz + ((size_t)dir << 23);
    const float* cw = dir ? cwb : cwf;
    float acc = (dir ? cbb : cbf)[d];
#pragma unroll
    for (int k = 0; k < 4; k++) {
        int lp = l - 3 + k;
        if (lp >= 0)
            acc = fmaf(cw[d*4 + k], __bfloat162float(xzd[(size_t)(row - l + lp)*XZW + d]), acc);
    }
    out[((size_t)dir << 22) + r] = __float2bfloat16(siluf(acc));
}

// ---------------- delta = softplus(xdbc[:, :32] @ dt_w.T + dt_b), both dirs ----------------
__global__ __launch_bounds__(256)
void dt_k(const float* __restrict__ xdbc,
          const float* __restrict__ wf, const float* __restrict__ dbf,
          const float* __restrict__ wb, const float* __restrict__ dbb,
          float* __restrict__ delta) {
    int dir = blockIdx.z;
    xdbc  += (size_t)dir * BL * 64;
    delta += (size_t)dir * BL * DI;
    const float* dt_w = dir ? wb : wf;
    const float* dt_b = dir ? dbb : dbf;
    __shared__ float xs[32][32];
    int t = threadIdx.x;
    int d0 = blockIdx.x * 256, m0 = blockIdx.y * 32;
#pragma unroll
    for (int i = 0; i < 4; i++) {
        int idx = t + i * 256;
        xs[idx >> 5][idx & 31] = xdbc[(size_t)(m0 + (idx >> 5)) * 64 + (idx & 31)];
    }
    int d = d0 + t;
    float4 wr[8];
#pragma unroll
    for (int j = 0; j < 8; j++) wr[j] = *(const float4*)(dt_w + (size_t)d*DTR + j*4);
    float b = dt_b[d];
    __syncthreads();
#pragma unroll 4
    for (int row = 0; row < 32; row++) {
        float acc = b;
#pragma unroll
        for (int j = 0; j < 8; j++) {
            float4 x4 = *(const float4*)&xs[row][j*4];
            acc = fmaf(wr[j].x, x4.x, acc);
            acc = fmaf(wr[j].y, x4.y, acc);
            acc = fmaf(wr[j].z, x4.z, acc);
            acc = fmaf(wr[j].w, x4.w, acc);
        }
        delta[(size_t)(m0 + row) * DI + d] = softplusf(acc);
    }
}

// ======== selective scan + gate: thread pair per d, 8 states each ========
__global__ __launch_bounds__(128)
void scan_k(const float* __restrict__ delta, const bf* __restrict__ u,
            const float* __restrict__ xdbc, const bf* __restrict__ xz,
            const float* __restrict__ Af, const float* __restrict__ Df,
            const float* __restrict__ Ab, const float* __restrict__ Db,
            bf* __restrict__ y) {
    int dir = blockIdx.z;
    delta += (size_t)dir * BL * DI;
    u     += (size_t)dir * BL * DI;
    xdbc  += (size_t)dir * BL * 64;
    xz    += (size_t)dir * BL * XZW;
    const float* A_log = dir ? Ab : Af;
    const float* Dv    = dir ? Db : Df;
    int t = threadIdx.x;
    int half = t & 1;
    int d = blockIdx.x * 64 + (t >> 1);
    int b = blockIdx.y;

    float aa[8];
#pragma unroll
    for (int n = 0; n < 8; n++)
        aa[n] = -__expf(A_log[d * DS + half*8 + n]) * 1.4426950408889634f;
    float Dd = Dv[d];
    float h[8];
#pragma unroll
    for (int n = 0; n < 8; n++) h[n] = 0.0f;

    int base = b * SEQL;
    const float* pd = delta + (size_t)base * DI + d;
    const bf*    pu = u     + (size_t)base * DI + d;
    const bf*    pz = xz    + (size_t)base * XZW + DI + d;
    const float* pb = xdbc  + (size_t)base * 64 + 32 + half*8;  // B slice; C at +16
    bf*          py = y + (size_t)base * 2048 + dir*1024 + d;

    float de0 = pd[0], de1 = pd[DI];
    float uu0 = __bfloat162float(pu[0]), uu1 = __bfloat162float(pu[DI]);
    float z0  = __bfloat162float(pz[0]), z1  = __bfloat162float(pz[XZW]);
    float4 Bv[2], Cv[2];
#pragma unroll
    for (int j = 0; j < 2; j++) {
        Bv[j] = *(const float4*)(pb + 4*j);
        Cv[j] = *(const float4*)(pb + 16 + 4*j);
    }
    for (int l = 0; l < SEQL; l++) {
        float de2 = 0.0f, uu2 = 0.0f, z2 = 0.0f;
        if (l + 2 < SEQL) {
            de2 = pd[2*DI];
            uu2 = __bfloat162float(pu[2*DI]);
            z2  = __bfloat162float(pz[2*XZW]);
        }
        float4 Bn[2], Cn[2];
        {
            const float* pb1 = pb + ((l + 1 < SEQL) ? 64 : 0);
#pragma unroll
            for (int j = 0; j < 2; j++) {
                Bn[j] = *(const float4*)(pb1 + 4*j);
                Cn[j] = *(const float4*)(pb1 + 16 + 4*j);
            }
        }
        float du = de0 * uu0;
        const float* Bf = (const float*)Bv;
        const float* Cf = (const float*)Cv;
        float a0 = 0.0f, a1 = 0.0f;
#pragma unroll
        for (int n = 0; n < 8; n++) {
            float dA = exp2f(de0 * aa[n]);
            h[n] = fmaf(dA, h[n], du * Bf[n]);
            float tt = h[n] * Cf[n];
            if (n & 1) a1 += tt; else a0 += tt;
        }
        float part = a0 + a1;
        part += __shfl_xor_sync(0xffffffffu, part, 1);
        if (half == 0) {
            float yy = part + uu0 * Dd;
            float sg = z0 / (1.0f + __expf(-z0));
            py[0] = __float2bfloat16(yy * sg);
        }
        pd += DI; pu += DI; pz += XZW; pb += 64; py += 2048;
        de0 = de1; de1 = de2;
        uu0 = uu1; uu1 = uu2;
        z0 = z1;   z1 = z2;
#pragma unroll
        for (int j = 0; j < 2; j++) { Bv[j] = Bn[j]; Cv[j] = Cn[j]; }
    }
}

// ---------------- launch ----------------
template <typename T>
static T* symp(const void* sym) {
    void* p = nullptr;
    cudaGetSymbolAddress(&p, sym);
    return (T*)p;
}

#define SMEM3_128 (3 * 256 * KST * 2)   // 110592
#define SMEM3_64  (3 * 192 * KST * 2)   // 82944

extern "C" void kernel_launch(void* const* d_in, const int* in_sizes, int n_in,
                              void* d_out, int out_size) {
    const int*           x      = (const int*)d_in[0];
    const unsigned char* m      = (const unsigned char*)d_in[2];
    const float*         emb    = (const float*)d_in[3];
    const float*         conv_w = (const float*)d_in[4];
    const float*         conv_b = (const float*)d_in[5];
    const float*         ln_g   = (const float*)d_in[6];
    const float*         ln_b   = (const float*)d_in[7];
    const float*         proj_b = (const float*)d_in[9];
    float* out = (float*)d_out;

    bf*    h    = symp<bf>(g_h);
    float* tmp  = symp<float>(g_tmp);
    bf*    xz   = symp<bf>(g_xz);
    bf*    u    = symp<bf>(g_u);
    float* dl   = symp<float>(g_delta);
    float* xdbc = symp<float>(g_xdbc);
    bf*    y    = symp<bf>(g_y);
    bf*    cwt  = symp<bf>(g_cwt);
    bf*    inw  = symp<bf>(g_inw);
    bf*    xw   = symp<bf>(g_xw);
    bf*    owT  = symp<bf>(g_owT);
    bf*    prw  = symp<bf>(g_projw);
    bf*    wfu  = symp<bf>(g_wfuse);

    cudaFuncSetAttribute(conv_bf, cudaFuncAttributeMaxDynamicSharedMemorySize, SMEM3_128);
    cudaFuncSetAttribute(gemm_bf<128, 0>, cudaFuncAttributeMaxDynamicSharedMemorySize, SMEM3_128);
    cudaFuncSetAttribute(gemm_bf<128, 2>, cudaFuncAttributeMaxDynamicSharedMemorySize, SMEM3_128);
    cudaFuncSetAttribute(gemm_bf<64, 1>,  cudaFuncAttributeMaxDynamicSharedMemorySize, SMEM3_64);

    // 1: merged weight conversion (conv transpose + owT transpose + f2bf)
    {
        CvtP p;
        p.s[0] = (const float*)d_in[10];  p.d[0] = inw;
        p.s[1] = (const float*)d_in[19];  p.d[1] = inw + (size_t)XZW*CH;
        p.s[2] = (const float*)d_in[13];  p.d[2] = xw;
        p.s[3] = (const float*)d_in[22];  p.d[3] = xw + (size_t)64*DI;
        p.s[4] = (const float*)d_in[8];   p.d[4] = prw;
        p.owf  = (const float*)d_in[18];
        p.owb  = (const float*)d_in[27];
        cvt_all<<<3*CH + 256 + 2768, 256>>>(conv_w, p);
    }
    // 2: Wfuse[c][dir*1024+e] = sum_k projw[c][dir*CH+k] * owT[dir][e][k]
    gemm_bf<128, 0><<<dim3(DI/128, CH/128, 2), 128, SMEM3_128>>>(
        prw, owT, nullptr, wfu, CH, 2*CH, 2048, 0, nullptr,
        (size_t)CH, (size_t)DI*CH, (size_t)DI);
    // 3: embedding
    embed_k<<<(BL*CH + 255)/256, 256>>>(x, emb, h);

    // 4-9: conv stack (launch #6 = conv layer 1, BK=64, for ncu capture)
    for (int layer = 0; layer < 3; layer++) {
        conv_bf<<<dim3(CH/128, BL/128), 128, SMEM3_128>>>(
            h, cwt + (size_t)layer*KW*CH*CH, conv_b + layer*CH, tmp);
        ln_k<<<BL, 128>>>(tmp, ln_g + layer*CH, ln_b + layer*CH, m, h);
    }

    const float* mcwf = (const float*)d_in[11];
    const float* mcbf = (const float*)d_in[12];
    const float* mcwb = (const float*)d_in[20];
    const float* mcbb = (const float*)d_in[21];
    const float* dtwf = (const float*)d_in[14];
    const float* dtbf = (const float*)d_in[15];
    const float* dtwb = (const float*)d_in[23];
    const float* dtbb = (const float*)d_in[24];
    const float* Alf  = (const float*)d_in[16];
    const float* Dvf  = (const float*)d_in[17];
    const float* Alb  = (const float*)d_in[25];
    const float* Dvb  = (const float*)d_in[26];

    // in-proj: xz[dir] = h(rev if dir) @ inw[dir]^T
    gemm_bf<128, 0><<<dim3(XZW/128, BL/128, 2), 128, SMEM3_128>>>(
        h, inw, nullptr, xz, CH, CH, XZW, 1, nullptr,
        0, (size_t)XZW*CH, (size_t)BL*XZW);
    // depthwise conv + silu
    dwconv_k<<<(2*BL*DI + 255)/256, 256>>>(xz, mcwf, mcbf, mcwb, mcbb, u);
    // xdbc = u @ xw^T
    gemm_bf<64, 1><<<dim3(1, BL/128, 2), 128, SMEM3_64>>>(
        u, xw, nullptr, xdbc, DI, DI, 64, 0, nullptr,
        (size_t)BL*DI, (size_t)64*DI, (size_t)BL*64);
    // delta
    dt_k<<<dim3(DI/256, BL/32, 2), 256>>>(xdbc, dtwf, dtbf, dtwb, dtbb, dl);
    // selective scan + gate -> y [row][dir*1024+d]
    scan_k<<<dim3(DI/64, BATCH, 2), 128>>>(dl, u, xdbc, xz, Alf, Dvf, Alb, Dvb, y);
    // fused out-proj + final projection: out = y @ Wfuse^T + bias, masked
    gemm_bf<128, 2><<<dim3(CH/128, BL/128, 1), 128, SMEM3_128>>>(
        y, wfu, proj_b, out, 2048, 2048, CH, 0, m, 0, 0, 0);
}

// round 11
// speedup vs baseline: 1.3533x; 1.0301x over previous
#include <cuda_runtime.h>
#include <cuda_bf16.h>
#include <cstdint>

#define BATCH 4
#define SEQL  1024
#define CH    512
#define KW    5
#define DI    1024
#define DS    16
#define DTR   32
#define BL    (BATCH*SEQL)
#define XZW   (2*DI)

#define BK  64
#define KST 72   // BK + 8 pad (bf16 elems), 144B row stride

typedef __nv_bfloat16 bf;

// ---------------- scratch ----------------
__device__ bf    g_h[BL*CH];
__device__ float g_tmp[2ull*BL*CH];           // split-K partials (conv / final)
__device__ bf    g_xz[2ull*BL*XZW];
__device__ bf    g_u[2ull*BL*DI];
__device__ float g_delta[2ull*BL*DI];
__device__ float g_xdbc[2ull*BL*64];
__device__ bf    g_y[(size_t)BL*2048];        // [row][dir*1024+d]
__device__ bf    g_cwt[3ull*KW*CH*CH];        // [layer][k][co][ci]
__device__ bf    g_inw[2ull*XZW*CH];
__device__ bf    g_xw[2ull*64*DI];
__device__ bf    g_owT[2ull*DI*CH];           // transposed out-proj weights [dir][e][k]
__device__ bf    g_projw[(size_t)CH*2*CH];
__device__ bf    g_wfuse[(size_t)CH*2048];    // [c][dir*1024+e]

// ---------------- helpers ----------------
__device__ __forceinline__ float siluf(float x) { return x / (1.0f + __expf(-x)); }
__device__ __forceinline__ float softplusf(float x) {
    return fmaxf(x, 0.0f) + log1pf(__expf(-fabsf(x)));
}
__device__ __forceinline__ void cp16u(uint32_t d, const void* s) {
    asm volatile("cp.async.cg.shared.global [%0], [%1], 16;" :: "r"(d), "l"(s));
}
__device__ __forceinline__ void cp16z(uint32_t d, const void* s, int valid) {
    int sz = valid ? 16 : 0;
    asm volatile("cp.async.cg.shared.global [%0], [%1], 16, %2;" :: "r"(d), "l"(s), "r"(sz));
}
__device__ __forceinline__ void cpcommit() { asm volatile("cp.async.commit_group;"); }
template<int N> __device__ __forceinline__ void cpwait() {
    asm volatile("cp.async.wait_group %0;" :: "n"(N));
}
__device__ __forceinline__ void ldsm4(uint32_t* r, uint32_t a) {
    asm volatile("ldmatrix.sync.aligned.m8n8.x4.shared.b16 {%0,%1,%2,%3}, [%4];"
        : "=r"(r[0]), "=r"(r[1]), "=r"(r[2]), "=r"(r[3]) : "r"(a));
}
__device__ __forceinline__ void mma16(float* d, const uint32_t* a, const uint32_t* b) {
    asm volatile(
        "mma.sync.aligned.m16n8k16.row.col.f32.bf16.bf16.f32 "
        "{%0,%1,%2,%3}, {%4,%5,%6,%7}, {%8,%9}, {%0,%1,%2,%3};"
        : "+f"(d[0]), "+f"(d[1]), "+f"(d[2]), "+f"(d[3])
        : "r"(a[0]), "r"(a[1]), "r"(a[2]), "r"(a[3]), "r"(b[0]), "r"(b[1]));
}

// ---------------- merged weight conversion ----------------
struct CvtP { const float* s[5]; bf* d[5]; const float* owf; const float* owb; };
__global__ void cvt_all(const float* __restrict__ conv_w, CvtP p) {
    __shared__ float s[64*65];
    int bx = blockIdx.x;
    if (bx < 3*CH) {
        int co = bx & 511, layer = bx >> 9;
        const float* src = conv_w + (size_t)bx * (CH*KW);
        for (int i = threadIdx.x; i < CH*KW; i += 256) s[i] = src[i];
        __syncthreads();
        bf* dst = g_cwt + (size_t)layer * KW * CH * CH;
        for (int i = threadIdx.x; i < CH*KW; i += 256) {
            int k = i >> 9, ci = i & 511;
            dst[(size_t)k*CH*CH + (size_t)co*CH + ci] = __float2bfloat16(s[ci*KW + k]);
        }
    } else if (bx < 3*CH + 256) {
        int idx = bx - 3*CH;
        int dir = idx >> 7;
        int te = (idx & 127) >> 3, tk = idx & 7;
        const float* ow = dir ? p.owb : p.owf;
        for (int i = threadIdx.x; i < 4096; i += 256) {
            int kk = i >> 6, ee = i & 63;
            s[kk*65 + ee] = ow[(size_t)(tk*64 + kk)*DI + te*64 + ee];
        }
        __syncthreads();
        bf* dst = g_owT + (size_t)dir*DI*CH;
        for (int i = threadIdx.x; i < 4096; i += 256) {
            int ee = i >> 6, kk = i & 63;
            dst[(size_t)(te*64 + ee)*CH + tk*64 + kk] = __float2bfloat16(s[kk*65 + ee]);
        }
    } else {
        const int sz[5] = {262144, 262144, 16384, 16384, 131072};
        int i = (bx - 3*CH - 256) * 256 + threadIdx.x;
        int seg = 0;
#pragma unroll
        for (int q = 0; q < 5; q++) {
            if (seg == q && i >= sz[q]) { i -= sz[q]; seg = q + 1; }
        }
        if (seg >= 5) return;
        float4 v = ((const float4*)p.s[seg])[i];
        __nv_bfloat162* o = (__nv_bfloat162*)p.d[seg];
        o[i*2]   = __floats2bfloat162_rn(v.x, v.y);
        o[i*2+1] = __floats2bfloat162_rn(v.z, v.w);
    }
}

// ---------------- embedding ----------------
__global__ void embed_k(const int* __restrict__ x, const float* __restrict__ emb,
                        bf* __restrict__ out) {
    int i = blockIdx.x * blockDim.x + threadIdx.x;
    if (i >= BL * CH) return;
    int row = i >> 9, c = i & (CH - 1);
    out[i] = __float2bfloat16(emb[x[row] * CH + c]);
}

// ======== bf16 MMA GEMM, 128xBNT tile, 4 warps (64x64 warp tile), 2-stage ========
// z-dim batches either direction (az/wz/oz offsets) or split-K (az=wz=K offset).
// EPI: 0 bf16 out, 1 fp32 out
template <int BNT, int EPI>
__global__ __launch_bounds__(128, 2)
void gemm_bf(const bf* __restrict__ A, const bf* __restrict__ Wt,
             void* __restrict__ OutV,
             int K, int lda, int ldw, int ldo, int revz,
             size_t az, size_t wz, size_t oz) {
    constexpr int NWN = BNT / 64;
    constexpr int WTM = 128 / (4 / NWN);
    constexpr int MF  = WTM / 16;
    constexpr int SST = (128 + BNT) * KST * 2;
    extern __shared__ char smem[];

    const int t = threadIdx.x, lane = t & 31, warp = t >> 5;
    const int wm = warp / NWN, wn = warp % NWN;
    const int m0 = blockIdx.y * 128, n0 = blockIdx.x * BNT;
    const int dir = blockIdx.z;
    A  += (size_t)dir * az;
    Wt += (size_t)dir * wz;
    const int rev = revz && dir;

    float acc[MF][8][4];
#pragma unroll
    for (int i = 0; i < MF; i++)
#pragma unroll
        for (int j = 0; j < 8; j++)
#pragma unroll
            for (int q = 0; q < 4; q++) acc[i][j][q] = 0.0f;

    const int lr   = t >> 3;
    const int koff = (t & 7) * 8;
    int ga[8];
#pragma unroll
    for (int i = 0; i < 8; i++) {
        int r = m0 + lr + 16*i;
        ga[i] = rev ? ((r & ~(SEQL-1)) + (SEQL-1) - (r & (SEQL-1))) : r;
    }
    const uint32_t base = (uint32_t)__cvta_generic_to_shared(smem);
    const uint32_t a_st = base + lr * (KST*2) + koff*2;
    const uint32_t b_st = base + 128*(KST*2) + lr * (KST*2) + koff*2;
    const uint32_t a_off = ((wm*WTM + ((lane>>3)&1)*8 + (lane&7)) * KST + (lane>>4)*8) * 2;
    const uint32_t b_off = (128*KST + (wn*64 + ((lane>>4)&1)*8 + (lane&7)) * KST
                            + ((lane>>3)&1)*8) * 2;

    auto load = [&](int st, int k0) {
#pragma unroll
        for (int i = 0; i < 8; i++)
            cp16u(a_st + i*16*(KST*2) + st*SST, A + (size_t)ga[i]*lda + k0 + koff);
#pragma unroll
        for (int i = 0; i < BNT/16; i++)
            cp16u(b_st + i*16*(KST*2) + st*SST,
                  Wt + (size_t)(n0 + lr + i*16)*ldw + k0 + koff);
        cpcommit();
    };
    load(0, 0);
    load(1, BK);
    const int nch = K >> 6;
    for (int ch = 0; ch < nch; ch++) {
        cpwait<1>();
        __syncthreads();
        const uint32_t sb = base + (ch & 1) * SST;
#pragma unroll
        for (int ks = 0; ks < 4; ks++) {
            uint32_t af[MF][4], bfr[4][4];
#pragma unroll
            for (int mf = 0; mf < MF; mf++)
                ldsm4(af[mf], sb + a_off + mf*16*KST*2 + ks*32);
#pragma unroll
            for (int g = 0; g < 4; g++)
                ldsm4(bfr[g], sb + b_off + g*16*KST*2 + ks*32);
#pragma unroll
            for (int mf = 0; mf < MF; mf++)
#pragma unroll
                for (int nf = 0; nf < 8; nf++)
                    mma16(acc[mf][nf], af[mf], &bfr[nf>>1][(nf&1)*2]);
        }
        __syncthreads();
        if (ch + 2 < nch) load(ch & 1, (ch + 2) * BK);
    }
#pragma unroll
    for (int mf = 0; mf < MF; mf++) {
#pragma unroll
        for (int half = 0; half < 2; half++) {
            int r = m0 + wm*WTM + mf*16 + (lane>>2) + half*8;
#pragma unroll
            for (int nf = 0; nf < 8; nf++) {
                int c = n0 + wn*64 + nf*8 + (lane&3)*2;
                float v0 = acc[mf][nf][half*2], v1 = acc[mf][nf][half*2+1];
                if (EPI == 0) {
                    bf* Ob = (bf*)OutV + (size_t)dir*oz;
                    *(__nv_bfloat162*)(Ob + (size_t)r*ldo + c) =
                        __floats2bfloat162_rn(v0, v1);
                } else {
                    float* Of = (float*)OutV + (size_t)dir*oz;
                    float2 f = {v0, v1};
                    *(float2*)(Of + (size_t)r*ldo + c) = f;
                }
            }
        }
    }
}

// ======== conv1d GEMM, split-K via blockIdx.z (2 halves of 20 chunks) ========
__global__ __launch_bounds__(128, 2)
void conv_bf(const bf* __restrict__ In, const bf* __restrict__ Wl,
             float* __restrict__ Out) {
    constexpr int SST = 256 * KST * 2;
    extern __shared__ char smem[];
    const int t = threadIdx.x, lane = t & 31, warp = t >> 5;
    const int wm = warp >> 1, wn = warp & 1;
    const int m0 = blockIdx.y * 128, n0 = blockIdx.x * 128;
    const int kh = blockIdx.z;          // K half
    Out += (size_t)kh * BL * CH;

    float acc[4][8][4];
#pragma unroll
    for (int i = 0; i < 4; i++)
#pragma unroll
        for (int j = 0; j < 8; j++)
#pragma unroll
            for (int q = 0; q < 4; q++) acc[i][j][q] = 0.0f;

    const int lr   = t >> 3;
    const int koff = (t & 7) * 8;
    int gr[8], lc[8];
#pragma unroll
    for (int i = 0; i < 8; i++) {
        gr[i] = m0 + lr + 16*i;
        lc[i] = gr[i] & (SEQL - 1);
    }
    const uint32_t base = (uint32_t)__cvta_generic_to_shared(smem);
    const uint32_t a_st = base + lr * (KST*2) + koff*2;
    const uint32_t b_st = base + 128*(KST*2) + lr * (KST*2) + koff*2;
    const uint32_t a_off = ((wm*64 + ((lane>>3)&1)*8 + (lane&7)) * KST + (lane>>4)*8) * 2;
    const uint32_t b_off = (128*KST + (wn*64 + ((lane>>4)&1)*8 + (lane&7)) * KST
                            + ((lane>>3)&1)*8) * 2;

    auto load = [&](int st, int chg) {
        int kk = chg >> 3, ci0 = (chg & 7) << 6;
        int sh = kk - 2;
#pragma unroll
        for (int i = 0; i < 8; i++) {
            int v = (unsigned)(lc[i] + sh) < (unsigned)SEQL;
            int rr = v ? gr[i] + sh : gr[i];
            cp16z(a_st + i*16*(KST*2) + st*SST, In + (size_t)rr*CH + ci0 + koff, v);
        }
#pragma unroll
        for (int i = 0; i < 8; i++)
            cp16u(b_st + i*16*(KST*2) + st*SST,
                  Wl + ((size_t)kk*CH + n0 + lr + i*16)*CH + ci0 + koff);
        cpcommit();
    };
    const int nch = 20;                 // per half; global chunk = kh*20 + ch
    const int cb = kh * 20;
    load(0, cb + 0);
    load(1, cb + 1);
    for (int ch = 0; ch < nch; ch++) {
        cpwait<1>();
        __syncthreads();
        const uint32_t sb = base + (ch & 1) * SST;
#pragma unroll
        for (int ks = 0; ks < 4; ks++) {
            uint32_t af[4][4], bfr[4][4];
#pragma unroll
            for (int mf = 0; mf < 4; mf++)
                ldsm4(af[mf], sb + a_off + mf*16*KST*2 + ks*32);
#pragma unroll
            for (int g = 0; g < 4; g++)
                ldsm4(bfr[g], sb + b_off + g*16*KST*2 + ks*32);
#pragma unroll
            for (int mf = 0; mf < 4; mf++)
#pragma unroll
                for (int nf = 0; nf < 8; nf++)
                    mma16(acc[mf][nf], af[mf], &bfr[nf>>1][(nf&1)*2]);
        }
        __syncthreads();
        if (ch + 2 < nch) load(ch & 1, cb + ch + 2);
    }
#pragma unroll
    for (int mf = 0; mf < 4; mf++) {
#pragma unroll
        for (int half = 0; half < 2; half++) {
            int r = m0 + wm*64 + mf*16 + (lane>>2) + half*8;
#pragma unroll
            for (int nf = 0; nf < 8; nf++) {
                int c = n0 + wn*64 + nf*8 + (lane&3)*2;
                float2 f = {acc[mf][nf][half*2], acc[mf][nf][half*2+1]};
                *(float2*)(Out + (size_t)r*CH + c) = f;
            }
        }
    }
}

// ---------------- channel LayerNorm + LeakyReLU + mask (sums split-K + bias) ----------------
__global__ void ln_k(const float* __restrict__ In, const float* __restrict__ cb,
                     const float* __restrict__ gamma, const float* __restrict__ beta,
                     const unsigned char* __restrict__ m, bf* __restrict__ Out) {
    int row = blockIdx.x;
    int t = threadIdx.x;   // 128
    float v[4];
    float s = 0.0f;
#pragma unroll
    for (int i = 0; i < 4; i++) {
        int c = t + i * 128;
        v[i] = In[(size_t)row * CH + c] + In[(size_t)BL*CH + (size_t)row * CH + c] + cb[c];
        s += v[i];
    }
    __shared__ float sm[4];
    for (int o = 16; o > 0; o >>= 1) s += __shfl_xor_sync(~0u, s, o);
    if ((t & 31) == 0) sm[t >> 5] = s;
    __syncthreads();
    float mean = (sm[0] + sm[1] + sm[2] + sm[3]) * (1.0f / CH);
    __syncthreads();
    float s2 = 0.0f;
#pragma unroll
    for (int i = 0; i < 4; i++) { float d = v[i] - mean; s2 += d * d; }
    for (int o = 16; o > 0; o >>= 1) s2 += __shfl_xor_sync(~0u, s2, o);
    if ((t & 31) == 0) sm[t >> 5] = s2;
    __syncthreads();
    float var = (sm[0] + sm[1] + sm[2] + sm[3]) * (1.0f / CH);
    float rstd = rsqrtf(var + 1e-5f);
    unsigned char mm = m[row];
#pragma unroll
    for (int i = 0; i < 4; i++) {
        int c = t + i * 128;
        float h = (v[i] - mean) * rstd * gamma[c] + beta[c];
        h = (h > 0.0f) ? h : 0.2f * h;
        if (mm) h = 0.0f;
        Out[(size_t)row * CH + c] = __float2bfloat16(h);
    }
}

// ---------------- final combine: out = p0 + p1 + bias, masked ----------------
__global__ void comb_k(const float* __restrict__ p, const float* __restrict__ bias,
                       const unsigned char* __restrict__ m, float* __restrict__ out) {
    int i = blockIdx.x * 256 + threadIdx.x;
    if (i >= BL * CH / 4) return;
    int r = i >> 7;              // 128 float4 per row
    int c4 = i & 127;
    float4 a = ((const float4*)p)[i];
    float4 b = ((const float4*)p)[BL*CH/4 + i];
    float4 bb = ((const float4*)bias)[c4];
    float4 v;
    v.x = a.x + b.x + bb.x; v.y = a.y + b.y + bb.y;
    v.z = a.z + b.z + bb.z; v.w = a.w + b.w + bb.w;
    if (m[r]) { v.x = 0.0f; v.y = 0.0f; v.z = 0.0f; v.w = 0.0f; }
    ((float4*)out)[i] = v;
}

// ---------------- causal depthwise conv + SiLU (both dirs) ----------------
__global__ void dwconv_k(const bf* __restrict__ xz,
                         const float* __restrict__ cwf, const float* __restrict__ cbf,
                         const float* __restrict__ cwb, const float* __restrict__ cbb,
                         bf* __restrict__ out) {
    int idx = blockIdx.x * blockDim.x + threadIdx.x;
    if (idx >= 2*BL*DI) return;
    int dir = idx >> 22;
    int r = idx & ((1 << 22) - 1);
    int d = r & (DI - 1);
    int row = r >> 10;
    int l = row & (SEQL - 1);
    const bf* xzd = xz + ((size_t)dir << 23);
    const float* cw = dir ? cwb : cwf;
    float acc = (dir ? cbb : cbf)[d];
#pragma unroll
    for (int k = 0; k < 4; k++) {
        int lp = l - 3 + k;
        if (lp >= 0)
            acc = fmaf(cw[d*4 + k], __bfloat162float(xzd[(size_t)(row - l + lp)*XZW + d]), acc);
    }
    out[((size_t)dir << 22) + r] = __float2bfloat16(siluf(acc));
}

// ---------------- delta = softplus(xdbc[:, :32] @ dt_w.T + dt_b), both dirs ----------------
__global__ __launch_bounds__(256)
void dt_k(const float* __restrict__ xdbc,
          const float* __restrict__ wf, const float* __restrict__ dbf,
          const float* __restrict__ wb, const float* __restrict__ dbb,
          float* __restrict__ delta) {
    int dir = blockIdx.z;
    xdbc  += (size_t)dir * BL * 64;
    delta += (size_t)dir * BL * DI;
    const float* dt_w = dir ? wb : wf;
    const float* dt_b = dir ? dbb : dbf;
    __shared__ float xs[32][32];
    int t = threadIdx.x;
    int d0 = blockIdx.x * 256, m0 = blockIdx.y * 32;
#pragma unroll
    for (int i = 0; i < 4; i++) {
        int idx = t + i * 256;
        xs[idx >> 5][idx & 31] = xdbc[(size_t)(m0 + (idx >> 5)) * 64 + (idx & 31)];
    }
    int d = d0 + t;
    float4 wr[8];
#pragma unroll
    for (int j = 0; j < 8; j++) wr[j] = *(const float4*)(dt_w + (size_t)d*DTR + j*4);
    float b = dt_b[d];
    __syncthreads();
#pragma unroll 4
    for (int row = 0; row < 32; row++) {
        float acc = b;
#pragma unroll
        for (int j = 0; j < 8; j++) {
            float4 x4 = *(const float4*)&xs[row][j*4];
            acc = fmaf(wr[j].x, x4.x, acc);
            acc = fmaf(wr[j].y, x4.y, acc);
            acc = fmaf(wr[j].z, x4.z, acc);
            acc = fmaf(wr[j].w, x4.w, acc);
        }
        delta[(size_t)(m0 + row) * DI + d] = softplusf(acc);
    }
}

// ======== selective scan + gate: thread pair per d, 8 states, depth-2 prefetch ========
__global__ __launch_bounds__(128)
void scan_k(const float* __restrict__ delta, const bf* __restrict__ u,
            const float* __restrict__ xdbc, const bf* __restrict__ xz,
            const float* __restrict__ Af, const float* __restrict__ Df,
            const float* __restrict__ Ab, const float* __restrict__ Db,
            bf* __restrict__ y) {
    int dir = blockIdx.z;
    delta += (size_t)dir * BL * DI;
    u     += (size_t)dir * BL * DI;
    xdbc  += (size_t)dir * BL * 64;
    xz    += (size_t)dir * BL * XZW;
    const float* A_log = dir ? Ab : Af;
    const float* Dv    = dir ? Db : Df;
    int t = threadIdx.x;
    int half = t & 1;
    int d = blockIdx.x * 64 + (t >> 1);
    int b = blockIdx.y;

    float aa[8];
#pragma unroll
    for (int n = 0; n < 8; n++)
        aa[n] = -__expf(A_log[d * DS + half*8 + n]) * 1.4426950408889634f;
    float Dd = Dv[d];
    float h[8];
#pragma unroll
    for (int n = 0; n < 8; n++) h[n] = 0.0f;

    int base = b * SEQL;
    const float* pd = delta + (size_t)base * DI + d;
    const bf*    pu = u     + (size_t)base * DI + d;
    const bf*    pz = xz    + (size_t)base * XZW + DI + d;
    const float* pb = xdbc  + (size_t)base * 64 + 32 + half*8;
    bf*          py = y + (size_t)base * 2048 + dir*1024 + d;

    float de0 = pd[0], de1 = pd[DI];
    float uu0 = __bfloat162float(pu[0]), uu1 = __bfloat162float(pu[DI]);
    float z0  = __bfloat162float(pz[0]), z1  = __bfloat162float(pz[XZW]);
    float4 B0[2], C0[2], B1[2], C1[2];
#pragma unroll
    for (int j = 0; j < 2; j++) {
        B0[j] = *(const float4*)(pb + 4*j);
        C0[j] = *(const float4*)(pb + 16 + 4*j);
        B1[j] = *(const float4*)(pb + 64 + 4*j);
        C1[j] = *(const float4*)(pb + 64 + 16 + 4*j);
    }
    for (int l = 0; l < SEQL; l++) {
        float de2 = 0.0f, uu2 = 0.0f, z2 = 0.0f;
        float4 B2[2], C2[2];
        if (l + 2 < SEQL) {
            de2 = pd[2*DI];
            uu2 = __bfloat162float(pu[2*DI]);
            z2  = __bfloat162float(pz[2*XZW]);
#pragma unroll
            for (int j = 0; j < 2; j++) {
                B2[j] = *(const float4*)(pb + 128 + 4*j);
                C2[j] = *(const float4*)(pb + 128 + 16 + 4*j);
            }
        } else {
#pragma unroll
            for (int j = 0; j < 2; j++) { B2[j] = B0[j]; C2[j] = C0[j]; }
        }
        float du = de0 * uu0;
        const float* Bf = (const float*)B0;
        const float* Cf = (const float*)C0;
        float a0 = 0.0f, a1 = 0.0f;
#pragma unroll
        for (int n = 0; n < 8; n++) {
            float dA = exp2f(de0 * aa[n]);
            h[n] = fmaf(dA, h[n], du * Bf[n]);
            float tt = h[n] * Cf[n];
            if (n & 1) a1 += tt; else a0 += tt;
        }
        float part = a0 + a1;
        part += __shfl_xor_sync(0xffffffffu, part, 1);
        if (half == 0) {
            float yy = part + uu0 * Dd;
            float sg = z0 / (1.0f + __expf(-z0));
            py[0] = __float2bfloat16(yy * sg);
        }
        pd += DI; pu += DI; pz += XZW; pb += 64; py += 2048;
        de0 = de1; de1 = de2;
        uu0 = uu1; uu1 = uu2;
        z0 = z1;   z1 = z2;
#pragma unroll
        for (int j = 0; j < 2; j++) {
            B0[j] = B1[j]; C0[j] = C1[j];
            B1[j] = B2[j]; C1[j] = C2[j];
        }
    }
}

// ---------------- launch ----------------
template <typename T>
static T* symp(const void* sym) {
    void* p = nullptr;
    cudaGetSymbolAddress(&p, sym);
    return (T*)p;
}

#define SMEM2_128 (2 * 256 * KST * 2)   // 73728
#define SMEM2_64  (2 * 192 * KST * 2)   // 55296

extern "C" void kernel_launch(void* const* d_in, const int* in_sizes, int n_in,
                              void* d_out, int out_size) {
    const int*           x      = (const int*)d_in[0];
    const unsigned char* m      = (const unsigned char*)d_in[2];
    const float*         emb    = (const float*)d_in[3];
    const float*         conv_w = (const float*)d_in[4];
    const float*         conv_b = (const float*)d_in[5];
    const float*         ln_g   = (const float*)d_in[6];
    const float*         ln_b   = (const float*)d_in[7];
    const float*         proj_b = (const float*)d_in[9];
    float* out = (float*)d_out;

    bf*    h    = symp<bf>(g_h);
    float* tmp  = symp<float>(g_tmp);
    bf*    xz   = symp<bf>(g_xz);
    bf*    u    = symp<bf>(g_u);
    float* dl   = symp<float>(g_delta);
    float* xdbc = symp<float>(g_xdbc);
    bf*    y    = symp<bf>(g_y);
    bf*    cwt  = symp<bf>(g_cwt);
    bf*    inw  = symp<bf>(g_inw);
    bf*    xw   = symp<bf>(g_xw);
    bf*    owT  = symp<bf>(g_owT);
    bf*    prw  = symp<bf>(g_projw);
    bf*    wfu  = symp<bf>(g_wfuse);

    cudaFuncSetAttribute(conv_bf, cudaFuncAttributeMaxDynamicSharedMemorySize, SMEM2_128);
    cudaFuncSetAttribute(gemm_bf<128, 0>, cudaFuncAttributeMaxDynamicSharedMemorySize, SMEM2_128);
    cudaFuncSetAttribute(gemm_bf<128, 1>, cudaFuncAttributeMaxDynamicSharedMemorySize, SMEM2_128);
    cudaFuncSetAttribute(gemm_bf<64, 1>,  cudaFuncAttributeMaxDynamicSharedMemorySize, SMEM2_64);

    // 1: merged weight conversion
    {
        CvtP p;
        p.s[0] = (const float*)d_in[10];  p.d[0] = inw;
        p.s[1] = (const float*)d_in[19];  p.d[1] = inw + (size_t)XZW*CH;
        p.s[2] = (const float*)d_in[13];  p.d[2] = xw;
        p.s[3] = (const float*)d_in[22];  p.d[3] = xw + (size_t)64*DI;
        p.s[4] = (const float*)d_in[8];   p.d[4] = prw;
        p.owf  = (const float*)d_in[18];
        p.owb  = (const float*)d_in[27];
        cvt_all<<<3*CH + 256 + 2768, 256>>>(conv_w, p);
    }
    // 2: Wfuse[c][dir*1024+e] = sum_k projw[c][dir*CH+k] * owT[dir][e][k]
    gemm_bf<128, 0><<<dim3(DI/128, CH/128, 2), 128, SMEM2_128>>>(
        prw, owT, wfu, CH, 2*CH, CH, 2048, 0,
        (size_t)CH, (size_t)DI*CH, (size_t)DI);
    // 3: embedding
    embed_k<<<(BL*CH + 255)/256, 256>>>(x, emb, h);

    // 4-9: conv stack (launch #6 = conv layer 1 for ncu capture)
    for (int layer = 0; layer < 3; layer++) {
        conv_bf<<<dim3(CH/128, BL/128, 2), 128, SMEM2_128>>>(
            h, cwt + (size_t)layer*KW*CH*CH, tmp);
        ln_k<<<BL, 128>>>(tmp, conv_b + layer*CH, ln_g + layer*CH, ln_b + layer*CH, m, h);
    }

    const float* mcwf = (const float*)d_in[11];
    const float* mcbf = (const float*)d_in[12];
    const float* mcwb = (const float*)d_in[20];
    const float* mcbb = (const float*)d_in[21];
    const float* dtwf = (const float*)d_in[14];
    const float* dtbf = (const float*)d_in[15];
    const float* dtwb = (const float*)d_in[23];
    const float* dtbb = (const float*)d_in[24];
    const float* Alf  = (const float*)d_in[16];
    const float* Dvf  = (const float*)d_in[17];
    const float* Alb  = (const float*)d_in[25];
    const float* Dvb  = (const float*)d_in[26];

    // in-proj: xz[dir] = h(rev if dir) @ inw[dir]^T
    gemm_bf<128, 0><<<dim3(XZW/128, BL/128, 2), 128, SMEM2_128>>>(
        h, inw, xz, CH, CH, CH, XZW, 1,
        0, (size_t)XZW*CH, (size_t)BL*XZW);
    // depthwise conv + silu
    dwconv_k<<<(2*BL*DI + 255)/256, 256>>>(xz, mcwf, mcbf, mcwb, mcbb, u);
    // xdbc = u @ xw^T
    gemm_bf<64, 1><<<dim3(1, BL/128, 2), 128, SMEM2_64>>>(
        u, xw, xdbc, DI, DI, DI, 64, 0,
        (size_t)BL*DI, (size_t)64*DI, (size_t)BL*64);
    // delta
    dt_k<<<dim3(DI/256, BL/32, 2), 256>>>(xdbc, dtwf, dtbf, dtwb, dtbb, dl);
    // selective scan + gate -> y [row][dir*1024+d]
    scan_k<<<dim3(DI/64, BATCH, 2), 128>>>(dl, u, xdbc, xz, Alf, Dvf, Alb, Dvb, y);
    // fused out-proj + final projection, split-K=2: partials into tmp
    gemm_bf<128, 1><<<dim3(CH/128, BL/128, 2), 128, SMEM2_128>>>(
        y, wfu, tmp, 1024, 2048, 2048, CH, 0,
        (size_t)1024, (size_t)1024, (size_t)BL*CH);
    // combine partials + bias + mask -> out
    comb_k<<<(BL*CH/4 + 255)/256, 256>>>(tmp, proj_b, m, out);
}

// round 12
// speedup vs baseline: 1.3832x; 1.0221x over previous
#include <cuda_runtime.h>
#include <cuda_bf16.h>
#include <cstdint>

#define BATCH 4
#define SEQL  1024
#define CH    512
#define KW    5
#define DI    1024
#define DS    16
#define DTR   32
#define BL    (BATCH*SEQL)
#define XZW   (2*DI)

#define BK  64
#define KST 72   // BK + 8 pad (bf16 elems), 144B row stride

typedef __nv_bfloat16 bf;

// ---------------- scratch ----------------
__device__ bf    g_h[BL*CH];
__device__ float g_tmp[2ull*BL*CH];           // split-K partials (conv / final)
__device__ bf    g_xz[2ull*BL*XZW];
__device__ bf    g_u[2ull*BL*DI];
__device__ float g_delta[2ull*BL*DI];
__device__ float g_xdbc[4ull*BL*64];          // [dir][kh][BL][64] split-K partials
__device__ float g_xs[2ull*BL*64];            // combined B/C for scan
__device__ bf    g_y[(size_t)BL*2048];        // [row][dir*1024+d]
__device__ bf    g_cwt[3ull*KW*CH*CH];        // [layer][k][co][ci]
__device__ bf    g_inw[2ull*XZW*CH];
__device__ bf    g_xw[2ull*64*DI];
__device__ bf    g_owT[2ull*DI*CH];           // transposed out-proj weights [dir][e][k]
__device__ bf    g_projw[(size_t)CH*2*CH];
__device__ bf    g_wfuse[(size_t)CH*2048];    // [c][dir*1024+e]

// ---------------- helpers ----------------
__device__ __forceinline__ float siluf(float x) { return x / (1.0f + __expf(-x)); }
__device__ __forceinline__ float softplusf(float x) {
    return fmaxf(x, 0.0f) + log1pf(__expf(-fabsf(x)));
}
__device__ __forceinline__ void cp16u(uint32_t d, const void* s) {
    asm volatile("cp.async.cg.shared.global [%0], [%1], 16;" :: "r"(d), "l"(s));
}
__device__ __forceinline__ void cp16z(uint32_t d, const void* s, int valid) {
    int sz = valid ? 16 : 0;
    asm volatile("cp.async.cg.shared.global [%0], [%1], 16, %2;" :: "r"(d), "l"(s), "r"(sz));
}
__device__ __forceinline__ void cpcommit() { asm volatile("cp.async.commit_group;"); }
template<int N> __device__ __forceinline__ void cpwait() {
    asm volatile("cp.async.wait_group %0;" :: "n"(N));
}
__device__ __forceinline__ void ldsm4(uint32_t* r, uint32_t a) {
    asm volatile("ldmatrix.sync.aligned.m8n8.x4.shared.b16 {%0,%1,%2,%3}, [%4];"
        : "=r"(r[0]), "=r"(r[1]), "=r"(r[2]), "=r"(r[3]) : "r"(a));
}
__device__ __forceinline__ void mma16(float* d, const uint32_t* a, const uint32_t* b) {
    asm volatile(
        "mma.sync.aligned.m16n8k16.row.col.f32.bf16.bf16.f32 "
        "{%0,%1,%2,%3}, {%4,%5,%6,%7}, {%8,%9}, {%0,%1,%2,%3};"
        : "+f"(d[0]), "+f"(d[1]), "+f"(d[2]), "+f"(d[3])
        : "r"(a[0]), "r"(a[1]), "r"(a[2]), "r"(a[3]), "r"(b[0]), "r"(b[1]));
}

// ---------------- merged weight conversion ----------------
struct CvtP { const float* s[5]; bf* d[5]; const float* owf; const float* owb; };
__global__ void cvt_all(const float* __restrict__ conv_w, CvtP p) {
    __shared__ float s[64*65];
    int bx = blockIdx.x;
    if (bx < 3*CH) {
        int co = bx & 511, layer = bx >> 9;
        const float* src = conv_w + (size_t)bx * (CH*KW);
        for (int i = threadIdx.x; i < CH*KW; i += 256) s[i] = src[i];
        __syncthreads();
        bf* dst = g_cwt + (size_t)layer * KW * CH * CH;
        for (int i = threadIdx.x; i < CH*KW; i += 256) {
            int k = i >> 9, ci = i & 511;
            dst[(size_t)k*CH*CH + (size_t)co*CH + ci] = __float2bfloat16(s[ci*KW + k]);
        }
    } else if (bx < 3*CH + 256) {
        int idx = bx - 3*CH;
        int dir = idx >> 7;
        int te = (idx & 127) >> 3, tk = idx & 7;
        const float* ow = dir ? p.owb : p.owf;
        for (int i = threadIdx.x; i < 4096; i += 256) {
            int kk = i >> 6, ee = i & 63;
            s[kk*65 + ee] = ow[(size_t)(tk*64 + kk)*DI + te*64 + ee];
        }
        __syncthreads();
        bf* dst = g_owT + (size_t)dir*DI*CH;
        for (int i = threadIdx.x; i < 4096; i += 256) {
            int ee = i >> 6, kk = i & 63;
            dst[(size_t)(te*64 + ee)*CH + tk*64 + kk] = __float2bfloat16(s[kk*65 + ee]);
        }
    } else {
        const int sz[5] = {262144, 262144, 16384, 16384, 131072};
        int i = (bx - 3*CH - 256) * 256 + threadIdx.x;
        int seg = 0;
#pragma unroll
        for (int q = 0; q < 5; q++) {
            if (seg == q && i >= sz[q]) { i -= sz[q]; seg = q + 1; }
        }
        if (seg >= 5) return;
        float4 v = ((const float4*)p.s[seg])[i];
        __nv_bfloat162* o = (__nv_bfloat162*)p.d[seg];
        o[i*2]   = __floats2bfloat162_rn(v.x, v.y);
        o[i*2+1] = __floats2bfloat162_rn(v.z, v.w);
    }
}

// ---------------- embedding ----------------
__global__ void embed_k(const int* __restrict__ x, const float* __restrict__ emb,
                        bf* __restrict__ out) {
    int i = blockIdx.x * blockDim.x + threadIdx.x;
    if (i >= BL * CH) return;
    int row = i >> 9, c = i & (CH - 1);
    out[i] = __float2bfloat16(emb[x[row] * CH + c]);
}

// ======== bf16 MMA GEMM, 128xBNT tile, 4 warps (64x64 warp tile), 2-stage ========
// z-dim: ZS=false -> z = dir (az/wz/oz offsets). ZS=true -> z = dir*2+kh
// (split-K: A/Wt shift by kh*K elems along k; Out shifts z*oz).
// EPI: 0 bf16 out, 1 fp32 out
template <int BNT, int EPI, bool ZS>
__global__ __launch_bounds__(128, 2)
void gemm_bf(const bf* __restrict__ A, const bf* __restrict__ Wt,
             void* __restrict__ OutV,
             int K, int lda, int ldw, int ldo, int revz,
             size_t az, size_t wz, size_t oz) {
    constexpr int NWN = BNT / 64;
    constexpr int WTM = 128 / (4 / NWN);
    constexpr int MF  = WTM / 16;
    constexpr int SST = (128 + BNT) * KST * 2;
    extern __shared__ char smem[];

    const int t = threadIdx.x, lane = t & 31, warp = t >> 5;
    const int wm = warp / NWN, wn = warp % NWN;
    const int m0 = blockIdx.y * 128, n0 = blockIdx.x * BNT;
    const int zz = blockIdx.z;
    const int dir = ZS ? (zz >> 1) : zz;
    A  += (size_t)dir * az + (ZS ? (size_t)(zz & 1) * K : 0);
    Wt += (size_t)dir * wz + (ZS ? (size_t)(zz & 1) * K : 0);
    const int rev = revz && dir;

    float acc[MF][8][4];
#pragma unroll
    for (int i = 0; i < MF; i++)
#pragma unroll
        for (int j = 0; j < 8; j++)
#pragma unroll
            for (int q = 0; q < 4; q++) acc[i][j][q] = 0.0f;

    const int lr   = t >> 3;
    const int koff = (t & 7) * 8;
    int ga[8];
#pragma unroll
    for (int i = 0; i < 8; i++) {
        int r = m0 + lr + 16*i;
        ga[i] = rev ? ((r & ~(SEQL-1)) + (SEQL-1) - (r & (SEQL-1))) : r;
    }
    const uint32_t base = (uint32_t)__cvta_generic_to_shared(smem);
    const uint32_t a_st = base + lr * (KST*2) + koff*2;
    const uint32_t b_st = base + 128*(KST*2) + lr * (KST*2) + koff*2;
    const uint32_t a_off = ((wm*WTM + ((lane>>3)&1)*8 + (lane&7)) * KST + (lane>>4)*8) * 2;
    const uint32_t b_off = (128*KST + (wn*64 + ((lane>>4)&1)*8 + (lane&7)) * KST
                            + ((lane>>3)&1)*8) * 2;

    auto load = [&](int st, int k0) {
#pragma unroll
        for (int i = 0; i < 8; i++)
            cp16u(a_st + i*16*(KST*2) + st*SST, A + (size_t)ga[i]*lda + k0 + koff);
#pragma unroll
        for (int i = 0; i < BNT/16; i++)
            cp16u(b_st + i*16*(KST*2) + st*SST,
                  Wt + (size_t)(n0 + lr + i*16)*ldw + k0 + koff);
        cpcommit();
    };
    load(0, 0);
    load(1, BK);
    const int nch = K >> 6;
    for (int ch = 0; ch < nch; ch++) {
        cpwait<1>();
        __syncthreads();
        const uint32_t sb = base + (ch & 1) * SST;
#pragma unroll
        for (int ks = 0; ks < 4; ks++) {
            uint32_t af[MF][4], bfr[4][4];
#pragma unroll
            for (int mf = 0; mf < MF; mf++)
                ldsm4(af[mf], sb + a_off + mf*16*KST*2 + ks*32);
#pragma unroll
            for (int g = 0; g < 4; g++)
                ldsm4(bfr[g], sb + b_off + g*16*KST*2 + ks*32);
#pragma unroll
            for (int mf = 0; mf < MF; mf++)
#pragma unroll
                for (int nf = 0; nf < 8; nf++)
                    mma16(acc[mf][nf], af[mf], &bfr[nf>>1][(nf&1)*2]);
        }
        __syncthreads();
        if (ch + 2 < nch) load(ch & 1, (ch + 2) * BK);
    }
#pragma unroll
    for (int mf = 0; mf < MF; mf++) {
#pragma unroll
        for (int half = 0; half < 2; half++) {
            int r = m0 + wm*WTM + mf*16 + (lane>>2) + half*8;
#pragma unroll
            for (int nf = 0; nf < 8; nf++) {
                int c = n0 + wn*64 + nf*8 + (lane&3)*2;
                float v0 = acc[mf][nf][half*2], v1 = acc[mf][nf][half*2+1];
                if (EPI == 0) {
                    bf* Ob = (bf*)OutV + (size_t)zz*oz;
                    *(__nv_bfloat162*)(Ob + (size_t)r*ldo + c) =
                        __floats2bfloat162_rn(v0, v1);
                } else {
                    float* Of = (float*)OutV + (size_t)zz*oz;
                    float2 f = {v0, v1};
                    *(float2*)(Of + (size_t)r*ldo + c) = f;
                }
            }
        }
    }
}

// ======== conv1d GEMM, split-K via blockIdx.z (2 halves of 20 chunks) ========
__global__ __launch_bounds__(128, 2)
void conv_bf(const bf* __restrict__ In, const bf* __restrict__ Wl,
             float* __restrict__ Out) {
    constexpr int SST = 256 * KST * 2;
    extern __shared__ char smem[];
    const int t = threadIdx.x, lane = t & 31, warp = t >> 5;
    const int wm = warp >> 1, wn = warp & 1;
    const int m0 = blockIdx.y * 128, n0 = blockIdx.x * 128;
    const int kh = blockIdx.z;          // K half
    Out += (size_t)kh * BL * CH;

    float acc[4][8][4];
#pragma unroll
    for (int i = 0; i < 4; i++)
#pragma unroll
        for (int j = 0; j < 8; j++)
#pragma unroll
            for (int q = 0; q < 4; q++) acc[i][j][q] = 0.0f;

    const int lr   = t >> 3;
    const int koff = (t & 7) * 8;
    int gr[8], lc[8];
#pragma unroll
    for (int i = 0; i < 8; i++) {
        gr[i] = m0 + lr + 16*i;
        lc[i] = gr[i] & (SEQL - 1);
    }
    const uint32_t base = (uint32_t)__cvta_generic_to_shared(smem);
    const uint32_t a_st = base + lr * (KST*2) + koff*2;
    const uint32_t b_st = base + 128*(KST*2) + lr * (KST*2) + koff*2;
    const uint32_t a_off = ((wm*64 + ((lane>>3)&1)*8 + (lane&7)) * KST + (lane>>4)*8) * 2;
    const uint32_t b_off = (128*KST + (wn*64 + ((lane>>4)&1)*8 + (lane&7)) * KST
                            + ((lane>>3)&1)*8) * 2;

    auto load = [&](int st, int chg) {
        int kk = chg >> 3, ci0 = (chg & 7) << 6;
        int sh = kk - 2;
#pragma unroll
        for (int i = 0; i < 8; i++) {
            int v = (unsigned)(lc[i] + sh) < (unsigned)SEQL;
            int rr = v ? gr[i] + sh : gr[i];
            cp16z(a_st + i*16*(KST*2) + st*SST, In + (size_t)rr*CH + ci0 + koff, v);
        }
#pragma unroll
        for (int i = 0; i < 8; i++)
            cp16u(b_st + i*16*(KST*2) + st*SST,
                  Wl + ((size_t)kk*CH + n0 + lr + i*16)*CH + ci0 + koff);
        cpcommit();
    };
    const int nch = 20;                 // per half; global chunk = kh*20 + ch
    const int cb = kh * 20;
    load(0, cb + 0);
    load(1, cb + 1);
    for (int ch = 0; ch < nch; ch++) {
        cpwait<1>();
        __syncthreads();
        const uint32_t sb = base + (ch & 1) * SST;
#pragma unroll
        for (int ks = 0; ks < 4; ks++) {
            uint32_t af[4][4], bfr[4][4];
#pragma unroll
            for (int mf = 0; mf < 4; mf++)
                ldsm4(af[mf], sb + a_off + mf*16*KST*2 + ks*32);
#pragma unroll
            for (int g = 0; g < 4; g++)
                ldsm4(bfr[g], sb + b_off + g*16*KST*2 + ks*32);
#pragma unroll
            for (int mf = 0; mf < 4; mf++)
#pragma unroll
                for (int nf = 0; nf < 8; nf++)
                    mma16(acc[mf][nf], af[mf], &bfr[nf>>1][(nf&1)*2]);
        }
        __syncthreads();
        if (ch + 2 < nch) load(ch & 1, cb + ch + 2);
    }
#pragma unroll
    for (int mf = 0; mf < 4; mf++) {
#pragma unroll
        for (int half = 0; half < 2; half++) {
            int r = m0 + wm*64 + mf*16 + (lane>>2) + half*8;
#pragma unroll
            for (int nf = 0; nf < 8; nf++) {
                int c = n0 + wn*64 + nf*8 + (lane&3)*2;
                float2 f = {acc[mf][nf][half*2], acc[mf][nf][half*2+1]};
                *(float2*)(Out + (size_t)r*CH + c) = f;
            }
        }
    }
}

// ---------------- channel LayerNorm + LeakyReLU + mask (sums split-K + bias) ----------------
__global__ void ln_k(const float* __restrict__ In, const float* __restrict__ cb,
                     const float* __restrict__ gamma, const float* __restrict__ beta,
                     const unsigned char* __restrict__ m, bf* __restrict__ Out) {
    int row = blockIdx.x;
    int t = threadIdx.x;   // 128
    float v[4];
    float s = 0.0f;
#pragma unroll
    for (int i = 0; i < 4; i++) {
        int c = t + i * 128;
        v[i] = In[(size_t)row * CH + c] + In[(size_t)BL*CH + (size_t)row * CH + c] + cb[c];
        s += v[i];
    }
    __shared__ float sm[4];
    for (int o = 16; o > 0; o >>= 1) s += __shfl_xor_sync(~0u, s, o);
    if ((t & 31) == 0) sm[t >> 5] = s;
    __syncthreads();
    float mean = (sm[0] + sm[1] + sm[2] + sm[3]) * (1.0f / CH);
    __syncthreads();
    float s2 = 0.0f;
#pragma unroll
    for (int i = 0; i < 4; i++) { float d = v[i] - mean; s2 += d * d; }
    for (int o = 16; o > 0; o >>= 1) s2 += __shfl_xor_sync(~0u, s2, o);
    if ((t & 31) == 0) sm[t >> 5] = s2;
    __syncthreads();
    float var = (sm[0] + sm[1] + sm[2] + sm[3]) * (1.0f / CH);
    float rstd = rsqrtf(var + 1e-5f);
    unsigned char mm = m[row];
#pragma unroll
    for (int i = 0; i < 4; i++) {
        int c = t + i * 128;
        float h = (v[i] - mean) * rstd * gamma[c] + beta[c];
        h = (h > 0.0f) ? h : 0.2f * h;
        if (mm) h = 0.0f;
        Out[(size_t)row * CH + c] = __float2bfloat16(h);
    }
}

// ---------------- final combine: out = p0 + p1 + bias, masked ----------------
__global__ void comb_k(const float* __restrict__ p, const float* __restrict__ bias,
                       const unsigned char* __restrict__ m, float* __restrict__ out) {
    int i = blockIdx.x * 256 + threadIdx.x;
    if (i >= BL * CH / 4) return;
    int r = i >> 7;              // 128 float4 per row
    int c4 = i & 127;
    float4 a = ((const float4*)p)[i];
    float4 b = ((const float4*)p)[BL*CH/4 + i];
    float4 bb = ((const float4*)bias)[c4];
    float4 v;
    v.x = a.x + b.x + bb.x; v.y = a.y + b.y + bb.y;
    v.z = a.z + b.z + bb.z; v.w = a.w + b.w + bb.w;
    if (m[r]) { v.x = 0.0f; v.y = 0.0f; v.z = 0.0f; v.w = 0.0f; }
    ((float4*)out)[i] = v;
}

// ---------------- causal depthwise conv + SiLU (both dirs) ----------------
__global__ void dwconv_k(const bf* __restrict__ xz,
                         const float* __restrict__ cwf, const float* __restrict__ cbf,
                         const float* __restrict__ cwb, const float* __restrict__ cbb,
                         bf* __restrict__ out) {
    int idx = blockIdx.x * blockDim.x + threadIdx.x;
    if (idx >= 2*BL*DI) return;
    int dir = idx >> 22;
    int r = idx & ((1 << 22) - 1);
    int d = r & (DI - 1);
    int row = r >> 10;
    int l = row & (SEQL - 1);
    const bf* xzd = xz + ((size_t)dir << 23);
    const float* cw = dir ? cwb : cwf;
    float acc = (dir ? cbb : cbf)[d];
#pragma unroll
    for (int k = 0; k < 4; k++) {
        int lp = l - 3 + k;
        if (lp >= 0)
            acc = fmaf(cw[d*4 + k], __bfloat162float(xzd[(size_t)(row - l + lp)*XZW + d]), acc);
    }
    out[((size_t)dir << 22) + r] = __float2bfloat16(siluf(acc));
}

// -------- delta = softplus(xdbc @ dt_w.T + dt_b); sums split-K partials;
// -------- blockIdx.x==0 also writes combined B/C columns for the scan --------
__global__ __launch_bounds__(256)
void dt_k(const float* __restrict__ xdbc,
          const float* __restrict__ wf, const float* __restrict__ dbf,
          const float* __restrict__ wb, const float* __restrict__ dbb,
          float* __restrict__ delta, float* __restrict__ xsum) {
    int dir = blockIdx.z;
    const float* x0 = xdbc + (size_t)dir * 2 * BL * 64;
    const float* x1 = x0 + (size_t)BL * 64;
    delta += (size_t)dir * BL * DI;
    xsum  += (size_t)dir * BL * 64;
    const float* dt_w = dir ? wb : wf;
    const float* dt_b = dir ? dbb : dbf;
    __shared__ float xs[32][32];
    int t = threadIdx.x;
    int d0 = blockIdx.x * 256, m0 = blockIdx.y * 32;
#pragma unroll
    for (int i = 0; i < 4; i++) {
        int idx = t + i * 256;
        int rr = idx >> 5, c = idx & 31;
        size_t off = (size_t)(m0 + rr) * 64 + c;
        xs[rr][c] = x0[off] + x1[off];
    }
    // combined B/C for scan (cols 32..63), written once per row-block
    if (blockIdx.x == 0) {
#pragma unroll
        for (int i = 0; i < 4; i++) {
            int idx = t + i * 256;
            int rr = idx >> 5, c = 32 + (idx & 31);
            size_t off = (size_t)(m0 + rr) * 64 + c;
            xsum[off] = x0[off] + x1[off];
        }
    }
    int d = d0 + t;
    float4 wr[8];
#pragma unroll
    for (int j = 0; j < 8; j++) wr[j] = *(const float4*)(dt_w + (size_t)d*DTR + j*4);
    float b = dt_b[d];
    __syncthreads();
#pragma unroll 4
    for (int row = 0; row < 32; row++) {
        float acc = b;
#pragma unroll
        for (int j = 0; j < 8; j++) {
            float4 x4 = *(const float4*)&xs[row][j*4];
            acc = fmaf(wr[j].x, x4.x, acc);
            acc = fmaf(wr[j].y, x4.y, acc);
            acc = fmaf(wr[j].z, x4.z, acc);
            acc = fmaf(wr[j].w, x4.w, acc);
        }
        delta[(size_t)(m0 + row) * DI + d] = softplusf(acc);
    }
}

// ======== selective scan + gate: 4 threads per d, 4 states each ========
__global__ __launch_bounds__(128)
void scan_k(const float* __restrict__ delta, const bf* __restrict__ u,
            const float* __restrict__ xsum, const bf* __restrict__ xz,
            const float* __restrict__ Af, const float* __restrict__ Df,
            const float* __restrict__ Ab, const float* __restrict__ Db,
            bf* __restrict__ y) {
    int dir = blockIdx.z;
    delta += (size_t)dir * BL * DI;
    u     += (size_t)dir * BL * DI;
    xsum  += (size_t)dir * BL * 64;
    xz    += (size_t)dir * BL * XZW;
    const float* A_log = dir ? Ab : Af;
    const float* Dv    = dir ? Db : Df;
    int t = threadIdx.x;
    int q = t & 3;                      // quarter: 4 states each
    int d = blockIdx.x * 32 + (t >> 2);
    int b = blockIdx.y;

    float aa[4];
#pragma unroll
    for (int n = 0; n < 4; n++)
        aa[n] = -__expf(A_log[d * DS + q*4 + n]) * 1.4426950408889634f;
    float Dd = Dv[d];
    float h[4];
#pragma unroll
    for (int n = 0; n < 4; n++) h[n] = 0.0f;

    int base = b * SEQL;
    const float* pd = delta + (size_t)base * DI + d;
    const bf*    pu = u     + (size_t)base * DI + d;
    const bf*    pz = xz    + (size_t)base * XZW + DI + d;
    const float* pb = xsum  + (size_t)base * 64 + 32 + q*4;   // B; C at +16
    bf*          py = y + (size_t)base * 2048 + dir*1024 + d;

    float de0 = pd[0], de1 = pd[DI];
    float uu0 = __bfloat162float(pu[0]), uu1 = __bfloat162float(pu[DI]);
    float z0  = __bfloat162float(pz[0]), z1  = __bfloat162float(pz[XZW]);
    float4 B0 = *(const float4*)(pb);
    float4 C0 = *(const float4*)(pb + 16);
    float4 B1 = *(const float4*)(pb + 64);
    float4 C1 = *(const float4*)(pb + 64 + 16);
    for (int l = 0; l < SEQL; l++) {
        float de2 = 0.0f, uu2 = 0.0f, z2 = 0.0f;
        float4 B2, C2;
        if (l + 2 < SEQL) {
            de2 = pd[2*DI];
            uu2 = __bfloat162float(pu[2*DI]);
            z2  = __bfloat162float(pz[2*XZW]);
            B2 = *(const float4*)(pb + 128);
            C2 = *(const float4*)(pb + 128 + 16);
        } else { B2 = B0; C2 = C0; }
        float du = de0 * uu0;
        const float* Bf = (const float*)&B0;
        const float* Cf = (const float*)&C0;
        float a0 = 0.0f, a1 = 0.0f;
#pragma unroll
        for (int n = 0; n < 4; n++) {
            float dA = exp2f(de0 * aa[n]);
            h[n] = fmaf(dA, h[n], du * Bf[n]);
            float tt = h[n] * Cf[n];
            if (n & 1) a1 += tt; else a0 += tt;
        }
        float part = a0 + a1;
        part += __shfl_xor_sync(0xffffffffu, part, 1);
        part += __shfl_xor_sync(0xffffffffu, part, 2);
        if (q == 0) {
            float yy = part + uu0 * Dd;
            float sg = z0 / (1.0f + __expf(-z0));
            py[0] = __float2bfloat16(yy * sg);
        }
        pd += DI; pu += DI; pz += XZW; pb += 64; py += 2048;
        de0 = de1; de1 = de2;
        uu0 = uu1; uu1 = uu2;
        z0 = z1;   z1 = z2;
        B0 = B1; C0 = C1;
        B1 = B2; C1 = C2;
    }
}

// ---------------- launch ----------------
template <typename T>
static T* symp(const void* sym) {
    void* p = nullptr;
    cudaGetSymbolAddress(&p, sym);
    return (T*)p;
}

#define SMEM2_128 (2 * 256 * KST * 2)   // 73728
#define SMEM2_64  (2 * 192 * KST * 2)   // 55296

extern "C" void kernel_launch(void* const* d_in, const int* in_sizes, int n_in,
                              void* d_out, int out_size) {
    const int*           x      = (const int*)d_in[0];
    const unsigned char* m      = (const unsigned char*)d_in[2];
    const float*         emb    = (const float*)d_in[3];
    const float*         conv_w = (const float*)d_in[4];
    const float*         conv_b = (const float*)d_in[5];
    const float*         ln_g   = (const float*)d_in[6];
    const float*         ln_b   = (const float*)d_in[7];
    const float*         proj_b = (const float*)d_in[9];
    float* out = (float*)d_out;

    bf*    h    = symp<bf>(g_h);
    float* tmp  = symp<float>(g_tmp);
    bf*    xz   = symp<bf>(g_xz);
    bf*    u    = symp<bf>(g_u);
    float* dl   = symp<float>(g_delta);
    float* xdbc = symp<float>(g_xdbc);
    float* xs   = symp<float>(g_xs);
    bf*    y    = symp<bf>(g_y);
    bf*    cwt  = symp<bf>(g_cwt);
    bf*    inw  = symp<bf>(g_inw);
    bf*    xw   = symp<bf>(g_xw);
    bf*    owT  = symp<bf>(g_owT);
    bf*    prw  = symp<bf>(g_projw);
    bf*    wfu  = symp<bf>(g_wfuse);

    cudaFuncSetAttribute(conv_bf, cudaFuncAttributeMaxDynamicSharedMemorySize, SMEM2_128);
    cudaFuncSetAttribute((const void*)gemm_bf<128, 0, false>, cudaFuncAttributeMaxDynamicSharedMemorySize, SMEM2_128);
    cudaFuncSetAttribute((const void*)gemm_bf<128, 1, false>, cudaFuncAttributeMaxDynamicSharedMemorySize, SMEM2_128);
    cudaFuncSetAttribute((const void*)gemm_bf<64, 1, true>,   cudaFuncAttributeMaxDynamicSharedMemorySize, SMEM2_64);

    // 1: merged weight conversion
    {
        CvtP p;
        p.s[0] = (const float*)d_in[10];  p.d[0] = inw;
        p.s[1] = (const float*)d_in[19];  p.d[1] = inw + (size_t)XZW*CH;
        p.s[2] = (const float*)d_in[13];  p.d[2] = xw;
        p.s[3] = (const float*)d_in[22];  p.d[3] = xw + (size_t)64*DI;
        p.s[4] = (const float*)d_in[8];   p.d[4] = prw;
        p.owf  = (const float*)d_in[18];
        p.owb  = (const float*)d_in[27];
        cvt_all<<<3*CH + 256 + 2768, 256>>>(conv_w, p);
    }
    // 2: Wfuse[c][dir*1024+e] = sum_k projw[c][dir*CH+k] * owT[dir][e][k]
    gemm_bf<128, 0, false><<<dim3(DI/128, CH/128, 2), 128, SMEM2_128>>>(
        prw, owT, wfu, CH, 2*CH, CH, 2048, 0,
        (size_t)CH, (size_t)DI*CH, (size_t)DI);
    // 3: embedding
    embed_k<<<(BL*CH + 255)/256, 256>>>(x, emb, h);

    // 4-9: conv stack (launch #6 = conv layer 1 for ncu capture)
    for (int layer = 0; layer < 3; layer++) {
        conv_bf<<<dim3(CH/128, BL/128, 2), 128, SMEM2_128>>>(
            h, cwt + (size_t)layer*KW*CH*CH, tmp);
        ln_k<<<BL, 128>>>(tmp, conv_b + layer*CH, ln_g + layer*CH, ln_b + layer*CH, m, h);
    }

    const float* mcwf = (const float*)d_in[11];
    const float* mcbf = (const float*)d_in[12];
    const float* mcwb = (const float*)d_in[20];
    const float* mcbb = (const float*)d_in[21];
    const float* dtwf = (const float*)d_in[14];
    const float* dtbf = (const float*)d_in[15];
    const float* dtwb = (const float*)d_in[23];
    const float* dtbb = (const float*)d_in[24];
    const float* Alf  = (const float*)d_in[16];
    const float* Dvf  = (const float*)d_in[17];
    const float* Alb  = (const float*)d_in[25];
    const float* Dvb  = (const float*)d_in[26];

    // in-proj: xz[dir] = h(rev if dir) @ inw[dir]^T
    gemm_bf<128, 0, false><<<dim3(XZW/128, BL/128, 2), 128, SMEM2_128>>>(
        h, inw, xz, CH, CH, CH, XZW, 1,
        0, (size_t)XZW*CH, (size_t)BL*XZW);
    // depthwise conv + silu
    dwconv_k<<<(2*BL*DI + 255)/256, 256>>>(xz, mcwf, mcbf, mcwb, mcbb, u);
    // xdbc partials = u @ xw^T, split-K=2 (z = dir*2 + kh)
    gemm_bf<64, 1, true><<<dim3(1, BL/128, 4), 128, SMEM2_64>>>(
        u, xw, xdbc, 512, DI, DI, 64, 0,
        (size_t)BL*DI, (size_t)64*DI, (size_t)BL*64);
    // delta (+ B/C combine into xs)
    dt_k<<<dim3(DI/256, BL/32, 2), 256>>>(xdbc, dtwf, dtbf, dtwb, dtbb, dl, xs);
    // selective scan + gate -> y [row][dir*1024+d]
    scan_k<<<dim3(DI/32, BATCH, 2), 128>>>(dl, u, xs, xz, Alf, Dvf, Alb, Dvb, y);
    // fused out-proj + final projection, split-K=2: partials into tmp
    gemm_bf<128, 1, false><<<dim3(CH/128, BL/128, 2), 128, SMEM2_128>>>(
        y, wfu, tmp, 1024, 2048, 2048, CH, 0,
        (size_t)1024, (size_t)1024, (size_t)BL*CH);
    // combine partials + bias + mask -> out
    comb_k<<<(BL*CH/4 + 255)/256, 256>>>(tmp, proj_b, m, out);
}

// round 14
// speedup vs baseline: 1.3921x; 1.0065x over previous
#include <cuda_runtime.h>
#include <cuda_bf16.h>
#include <cstdint>

#define BATCH 4
#define SEQL  1024
#define CH    512
#define KW    5
#define DI    1024
#define DS    16
#define DTR   32
#define BL    (BATCH*SEQL)
#define XZW   (2*DI)

#define BK  64
#define KST 72   // BK + 8 pad (bf16 elems), 144B row stride

typedef __nv_bfloat16 bf;

// ---------------- scratch ----------------
__device__ bf    g_h[BL*CH];
__device__ float g_tmp[2ull*BL*CH];           // split-K partials (conv / final)
__device__ bf    g_xz[2ull*BL*XZW];
__device__ bf    g_u[2ull*BL*DI];
__device__ float g_delta[2ull*BL*DI];
__device__ float g_xdbc[4ull*BL*64];          // [dir][kh][BL][64] split-K partials
__device__ float g_xs[2ull*BL*64];            // combined B/C for scan
__device__ bf    g_y[(size_t)BL*2048];        // [row][dir*1024+d]
__device__ bf    g_cwt[3ull*KW*CH*CH];        // [layer][k][co][ci]
__device__ bf    g_inw[2ull*XZW*CH];
__device__ bf    g_xw[2ull*64*DI];
__device__ bf    g_owT[2ull*DI*CH];           // transposed out-proj weights [dir][e][k]
__device__ bf    g_projw[(size_t)CH*2*CH];
__device__ bf    g_wfuse[(size_t)CH*2048];    // [c][dir*1024+e]

// ---------------- helpers ----------------
__device__ __forceinline__ float siluf(float x) { return x / (1.0f + __expf(-x)); }
__device__ __forceinline__ float softplusf(float x) {
    return fmaxf(x, 0.0f) + log1pf(__expf(-fabsf(x)));
}
__device__ __forceinline__ void cp16u(uint32_t d, const void* s) {
    asm volatile("cp.async.cg.shared.global [%0], [%1], 16;" :: "r"(d), "l"(s));
}
__device__ __forceinline__ void cp16z(uint32_t d, const void* s, int valid) {
    int sz = valid ? 16 : 0;
    asm volatile("cp.async.cg.shared.global [%0], [%1], 16, %2;" :: "r"(d), "l"(s), "r"(sz));
}
__device__ __forceinline__ void cpcommit() { asm volatile("cp.async.commit_group;"); }
template<int N> __device__ __forceinline__ void cpwait() {
    asm volatile("cp.async.wait_group %0;" :: "n"(N));
}
__device__ __forceinline__ void ldsm4(uint32_t* r, uint32_t a) {
    asm volatile("ldmatrix.sync.aligned.m8n8.x4.shared.b16 {%0,%1,%2,%3}, [%4];"
        : "=r"(r[0]), "=r"(r[1]), "=r"(r[2]), "=r"(r[3]) : "r"(a));
}
__device__ __forceinline__ void mma16(float* d, const uint32_t* a, const uint32_t* b) {
    asm volatile(
        "mma.sync.aligned.m16n8k16.row.col.f32.bf16.bf16.f32 "
        "{%0,%1,%2,%3}, {%4,%5,%6,%7}, {%8,%9}, {%0,%1,%2,%3};"
        : "+f"(d[0]), "+f"(d[1]), "+f"(d[2]), "+f"(d[3])
        : "r"(a[0]), "r"(a[1]), "r"(a[2]), "r"(a[3]), "r"(b[0]), "r"(b[1]));
}

// ---------------- merged weight conversion ----------------
struct CvtP { const float* s[5]; bf* d[5]; const float* owf; const float* owb; };
__global__ void cvt_all(const float* __restrict__ conv_w, CvtP p) {
    __shared__ float s[64*65];
    int bx = blockIdx.x;
    if (bx < 3*CH) {
        int co = bx & 511, layer = bx >> 9;
        const float* src = conv_w + (size_t)bx * (CH*KW);
        for (int i = threadIdx.x; i < CH*KW; i += 256) s[i] = src[i];
        __syncthreads();
        bf* dst = g_cwt + (size_t)layer * KW * CH * CH;
        for (int i = threadIdx.x; i < CH*KW; i += 256) {
            int k = i >> 9, ci = i & 511;
            dst[(size_t)k*CH*CH + (size_t)co*CH + ci] = __float2bfloat16(s[ci*KW + k]);
        }
    } else if (bx < 3*CH + 256) {
        int idx = bx - 3*CH;
        int dir = idx >> 7;
        int te = (idx & 127) >> 3, tk = idx & 7;
        const float* ow = dir ? p.owb : p.owf;
        for (int i = threadIdx.x; i < 4096; i += 256) {
            int kk = i >> 6, ee = i & 63;
            s[kk*65 + ee] = ow[(size_t)(tk*64 + kk)*DI + te*64 + ee];
        }
        __syncthreads();
        bf* dst = g_owT + (size_t)dir*DI*CH;
        for (int i = threadIdx.x; i < 4096; i += 256) {
            int ee = i >> 6, kk = i & 63;
            dst[(size_t)(te*64 + ee)*CH + tk*64 + kk] = __float2bfloat16(s[kk*65 + ee]);
        }
    } else {
        const int sz[5] = {262144, 262144, 16384, 16384, 131072};
        int i = (bx - 3*CH - 256) * 256 + threadIdx.x;
        int seg = 0;
#pragma unroll
        for (int q = 0; q < 5; q++) {
            if (seg == q && i >= sz[q]) { i -= sz[q]; seg = q + 1; }
        }
        if (seg >= 5) return;
        float4 v = ((const float4*)p.s[seg])[i];
        __nv_bfloat162* o = (__nv_bfloat162*)p.d[seg];
        o[i*2]   = __floats2bfloat162_rn(v.x, v.y);
        o[i*2+1] = __floats2bfloat162_rn(v.z, v.w);
    }
}

// ---------------- embedding ----------------
__global__ void embed_k(const int* __restrict__ x, const float* __restrict__ emb,
                        bf* __restrict__ out) {
    int i = blockIdx.x * blockDim.x + threadIdx.x;
    if (i >= BL * CH) return;
    int row = i >> 9, c = i & (CH - 1);
    out[i] = __float2bfloat16(emb[x[row] * CH + c]);
}

// ======== bf16 MMA GEMM, 128x128 tile, 8 warps (64x32 warp tile), 2-stage ========
// z-dim generic: A += z*az, Wt += z*wz, Out += z*oz. EPI: 0 bf16 out, 1 fp32 out
template <int EPI>
__global__ __launch_bounds__(256, 2)
void gemm256(const bf* __restrict__ A, const bf* __restrict__ Wt,
             void* __restrict__ OutV,
             int K, int lda, int ldw, int ldo, int revz,
             size_t az, size_t wz, size_t oz) {
    constexpr int SST = 256 * KST * 2;
    extern __shared__ char smem[];

    const int t = threadIdx.x, lane = t & 31, warp = t >> 5;
    const int wm = warp >> 2, wn = warp & 3;      // 2 x 4 warp grid, tile 64x32
    const int m0 = blockIdx.y * 128, n0 = blockIdx.x * 128;
    const int zz = blockIdx.z;
    A  += (size_t)zz * az;
    Wt += (size_t)zz * wz;
    const int rev = revz && zz;

    float acc[4][4][4];
#pragma unroll
    for (int i = 0; i < 4; i++)
#pragma unroll
        for (int j = 0; j < 4; j++)
#pragma unroll
            for (int q = 0; q < 4; q++) acc[i][j][q] = 0.0f;

    const int lr   = t >> 3;         // 0..31, rows lr + 32*i
    const int koff = (t & 7) * 8;
    int ga[4];
#pragma unroll
    for (int i = 0; i < 4; i++) {
        int r = m0 + lr + 32*i;
        ga[i] = rev ? ((r & ~(SEQL-1)) + (SEQL-1) - (r & (SEQL-1))) : r;
    }
    const uint32_t base = (uint32_t)__cvta_generic_to_shared(smem);
    const uint32_t a_st = base + lr * (KST*2) + koff*2;
    const uint32_t b_st = base + 128*(KST*2) + lr * (KST*2) + koff*2;
    const uint32_t a_off = ((wm*64 + ((lane>>3)&1)*8 + (lane&7)) * KST + (lane>>4)*8) * 2;
    const uint32_t b_off = (128*KST + (wn*32 + ((lane>>4)&1)*8 + (lane&7)) * KST
                            + ((lane>>3)&1)*8) * 2;

    auto load = [&](int st, int k0) {
#pragma unroll
        for (int i = 0; i < 4; i++)
            cp16u(a_st + i*32*(KST*2) + st*SST, A + (size_t)ga[i]*lda + k0 + koff);
#pragma unroll
        for (int i = 0; i < 4; i++)
            cp16u(b_st + i*32*(KST*2) + st*SST,
                  Wt + (size_t)(n0 + lr + i*32)*ldw + k0 + koff);
        cpcommit();
    };
    load(0, 0);
    load(1, BK);
    const int nch = K >> 6;
    for (int ch = 0; ch < nch; ch++) {
        cpwait<1>();
        __syncthreads();
        const uint32_t sb = base + (ch & 1) * SST;
#pragma unroll
        for (int ks = 0; ks < 4; ks++) {
            uint32_t af[4][4], bfr[2][4];
#pragma unroll
            for (int mf = 0; mf < 4; mf++)
                ldsm4(af[mf], sb + a_off + mf*16*KST*2 + ks*32);
            ldsm4(bfr[0], sb + b_off + ks*32);
            ldsm4(bfr[1], sb + b_off + 16*KST*2 + ks*32);
#pragma unroll
            for (int mf = 0; mf < 4; mf++)
#pragma unroll
                for (int nf = 0; nf < 4; nf++)
                    mma16(acc[mf][nf], af[mf], &bfr[nf>>1][(nf&1)*2]);
        }
        __syncthreads();
        if (ch + 2 < nch) load(ch & 1, (ch + 2) * BK);
    }
#pragma unroll
    for (int mf = 0; mf < 4; mf++) {
#pragma unroll
        for (int half = 0; half < 2; half++) {
            int r = m0 + wm*64 + mf*16 + (lane>>2) + half*8;
#pragma unroll
            for (int nf = 0; nf < 4; nf++) {
                int c = n0 + wn*32 + nf*8 + (lane&3)*2;
                float v0 = acc[mf][nf][half*2], v1 = acc[mf][nf][half*2+1];
                if (EPI == 0) {
                    bf* Ob = (bf*)OutV + (size_t)zz*oz;
                    *(__nv_bfloat162*)(Ob + (size_t)r*ldo + c) =
                        __floats2bfloat162_rn(v0, v1);
                } else {
                    float* Of = (float*)OutV + (size_t)zz*oz;
                    float2 f = {v0, v1};
                    *(float2*)(Of + (size_t)r*ldo + c) = f;
                }
            }
        }
    }
}

// ======== conv1d GEMM, 256 thr, 8 warps 64x32, split-K via blockIdx.z ========
__global__ __launch_bounds__(256, 2)
void conv256(const bf* __restrict__ In, const bf* __restrict__ Wl,
             float* __restrict__ Out) {
    constexpr int SST = 256 * KST * 2;
    extern __shared__ char smem[];
    const int t = threadIdx.x, lane = t & 31, warp = t >> 5;
    const int wm = warp >> 2, wn = warp & 3;
    const int m0 = blockIdx.y * 128, n0 = blockIdx.x * 128;
    const int kh = blockIdx.z;
    Out += (size_t)kh * BL * CH;

    float acc[4][4][4];
#pragma unroll
    for (int i = 0; i < 4; i++)
#pragma unroll
        for (int j = 0; j < 4; j++)
#pragma unroll
            for (int q = 0; q < 4; q++) acc[i][j][q] = 0.0f;

    const int lr   = t >> 3;
    const int koff = (t & 7) * 8;
    int gr[4], lc[4];
#pragma unroll
    for (int i = 0; i < 4; i++) {
        gr[i] = m0 + lr + 32*i;
        lc[i] = gr[i] & (SEQL - 1);
    }
    const uint32_t base = (uint32_t)__cvta_generic_to_shared(smem);
    const uint32_t a_st = base + lr * (KST*2) + koff*2;
    const uint32_t b_st = base + 128*(KST*2) + lr * (KST*2) + koff*2;
    const uint32_t a_off = ((wm*64 + ((lane>>3)&1)*8 + (lane&7)) * KST + (lane>>4)*8) * 2;
    const uint32_t b_off = (128*KST + (wn*32 + ((lane>>4)&1)*8 + (lane&7)) * KST
                            + ((lane>>3)&1)*8) * 2;

    auto load = [&](int st, int chg) {
        int kk = chg >> 3, ci0 = (chg & 7) << 6;
        int sh = kk - 2;
#pragma unroll
        for (int i = 0; i < 4; i++) {
            int v = (unsigned)(lc[i] + sh) < (unsigned)SEQL;
            int rr = v ? gr[i] + sh : gr[i];
            cp16z(a_st + i*32*(KST*2) + st*SST, In + (size_t)rr*CH + ci0 + koff, v);
        }
#pragma unroll
        for (int i = 0; i < 4; i++)
            cp16u(b_st + i*32*(KST*2) + st*SST,
                  Wl + ((size_t)kk*CH + n0 + lr + i*32)*CH + ci0 + koff);
        cpcommit();
    };
    const int nch = 20;
    const int cb = kh * 20;
    load(0, cb + 0);
    load(1, cb + 1);
    for (int ch = 0; ch < nch; ch++) {
        cpwait<1>();
        __syncthreads();
        const uint32_t sb = base + (ch & 1) * SST;
#pragma unroll
        for (int ks = 0; ks < 4; ks++) {
            uint32_t af[4][4], bfr[2][4];
#pragma unroll
            for (int mf = 0; mf < 4; mf++)
                ldsm4(af[mf], sb + a_off + mf*16*KST*2 + ks*32);
            ldsm4(bfr[0], sb + b_off + ks*32);
            ldsm4(bfr[1], sb + b_off + 16*KST*2 + ks*32);
#pragma unroll
            for (int mf = 0; mf < 4; mf++)
#pragma unroll
                for (int nf = 0; nf < 4; nf++)
                    mma16(acc[mf][nf], af[mf], &bfr[nf>>1][(nf&1)*2]);
        }
        __syncthreads();
        if (ch + 2 < nch) load(ch & 1, cb + ch + 2);
    }
#pragma unroll
    for (int mf = 0; mf < 4; mf++) {
#pragma unroll
        for (int half = 0; half < 2; half++) {
            int r = m0 + wm*64 + mf*16 + (lane>>2) + half*8;
#pragma unroll
            for (int nf = 0; nf < 4; nf++) {
                int c = n0 + wn*32 + nf*8 + (lane&3)*2;
                float2 f = {acc[mf][nf][half*2], acc[mf][nf][half*2+1]};
                *(float2*)(Out + (size_t)r*CH + c) = f;
            }
        }
    }
}

// ======== small GEMM for xdbc (BNT=64, 128 thr), z = dir*2 + kh split-K ========
__global__ __launch_bounds__(128, 2)
void gemm_xd(const bf* __restrict__ A, const bf* __restrict__ Wt,
             float* __restrict__ Out, int K) {
    constexpr int SST = 192 * KST * 2;
    extern __shared__ char smem[];
    const int t = threadIdx.x, lane = t & 31, warp = t >> 5;
    const int wm = warp;               // 4 warps along M, warp tile 32x64
    const int m0 = blockIdx.y * 128;
    const int zz = blockIdx.z;
    const int dir = zz >> 1;
    A  += (size_t)dir * BL * DI + (size_t)(zz & 1) * K;
    Wt += (size_t)dir * 64 * DI + (size_t)(zz & 1) * K;
    Out += (size_t)zz * BL * 64;

    float acc[2][8][4];
#pragma unroll
    for (int i = 0; i < 2; i++)
#pragma unroll
        for (int j = 0; j < 8; j++)
#pragma unroll
            for (int q = 0; q < 4; q++) acc[i][j][q] = 0.0f;

    const int lr   = t >> 3;
    const int koff = (t & 7) * 8;
    const uint32_t base = (uint32_t)__cvta_generic_to_shared(smem);
    const uint32_t a_st = base + lr * (KST*2) + koff*2;
    const uint32_t b_st = base + 128*(KST*2) + lr * (KST*2) + koff*2;
    const uint32_t a_off = ((wm*32 + ((lane>>3)&1)*8 + (lane&7)) * KST + (lane>>4)*8) * 2;
    const uint32_t b_off = (128*KST + (((lane>>4)&1)*8 + (lane&7)) * KST
                            + ((lane>>3)&1)*8) * 2;

    auto load = [&](int st, int k0) {
#pragma unroll
        for (int i = 0; i < 8; i++)
            cp16u(a_st + i*16*(KST*2) + st*SST,
                  A + (size_t)(m0 + lr + 16*i)*DI + k0 + koff);
#pragma unroll
        for (int i = 0; i < 4; i++)
            cp16u(b_st + i*16*(KST*2) + st*SST,
                  Wt + (size_t)(lr + i*16)*DI + k0 + koff);
        cpcommit();
    };
    load(0, 0);
    load(1, BK);
    const int nch = K >> 6;
    for (int ch = 0; ch < nch; ch++) {
        cpwait<1>();
        __syncthreads();
        const uint32_t sb = base + (ch & 1) * SST;
#pragma unroll
        for (int ks = 0; ks < 4; ks++) {
            uint32_t af[2][4], bfr[4][4];
#pragma unroll
            for (int mf = 0; mf < 2; mf++)
                ldsm4(af[mf], sb + a_off + mf*16*KST*2 + ks*32);
#pragma unroll
            for (int g = 0; g < 4; g++)
                ldsm4(bfr[g], sb + b_off + g*16*KST*2 + ks*32);
#pragma unroll
            for (int mf = 0; mf < 2; mf++)
#pragma unroll
                for (int nf = 0; nf < 8; nf++)
                    mma16(acc[mf][nf], af[mf], &bfr[nf>>1][(nf&1)*2]);
        }
        __syncthreads();
        if (ch + 2 < nch) load(ch & 1, (ch + 2) * BK);
    }
#pragma unroll
    for (int mf = 0; mf < 2; mf++) {
#pragma unroll
        for (int half = 0; half < 2; half++) {
            int r = m0 + wm*32 + mf*16 + (lane>>2) + half*8;
#pragma unroll
            for (int nf = 0; nf < 8; nf++) {
                int c = nf*8 + (lane&3)*2;
                float2 f = {acc[mf][nf][half*2], acc[mf][nf][half*2+1]};
                *(float2*)(Out + (size_t)r*64 + c) = f;
            }
        }
    }
}

// ---------------- channel LayerNorm + LeakyReLU + mask (sums split-K + bias) ----------------
__global__ void ln_k(const float* __restrict__ In, const float* __restrict__ cb,
                     const float* __restrict__ gamma, const float* __restrict__ beta,
                     const unsigned char* __restrict__ m, bf* __restrict__ Out) {
    int row = blockIdx.x;
    int t = threadIdx.x;   // 128
    float v[4];
    float s = 0.0f;
#pragma unroll
    for (int i = 0; i < 4; i++) {
        int c = t + i * 128;
        v[i] = In[(size_t)row * CH + c] + In[(size_t)BL*CH + (size_t)row * CH + c] + cb[c];
        s += v[i];
    }
    __shared__ float sm[4];
    for (int o = 16; o > 0; o >>= 1) s += __shfl_xor_sync(~0u, s, o);
    if ((t & 31) == 0) sm[t >> 5] = s;
    __syncthreads();
    float mean = (sm[0] + sm[1] + sm[2] + sm[3]) * (1.0f / CH);
    __syncthreads();
    float s2 = 0.0f;
#pragma unroll
    for (int i = 0; i < 4; i++) { float d = v[i] - mean; s2 += d * d; }
    for (int o = 16; o > 0; o >>= 1) s2 += __shfl_xor_sync(~0u, s2, o);
    if ((t & 31) == 0) sm[t >> 5] = s2;
    __syncthreads();
    float var = (sm[0] + sm[1] + sm[2] + sm[3]) * (1.0f / CH);
    float rstd = rsqrtf(var + 1e-5f);
    unsigned char mm = m[row];
#pragma unroll
    for (int i = 0; i < 4; i++) {
        int c = t + i * 128;
        float h = (v[i] - mean) * rstd * gamma[c] + beta[c];
        h = (h > 0.0f) ? h : 0.2f * h;
        if (mm) h = 0.0f;
        Out[(size_t)row * CH + c] = __float2bfloat16(h);
    }
}

// ---------------- final combine: out = p0 + p1 + bias, masked ----------------
__global__ void comb_k(const float* __restrict__ p, const float* __restrict__ bias,
                       const unsigned char* __restrict__ m, float* __restrict__ out) {
    int i = blockIdx.x * 256 + threadIdx.x;
    if (i >= BL * CH / 4) return;
    int r = i >> 7;
    int c4 = i & 127;
    float4 a = ((const float4*)p)[i];
    float4 b = ((const float4*)p)[BL*CH/4 + i];
    float4 bb = ((const float4*)bias)[c4];
    float4 v;
    v.x = a.x + b.x + bb.x; v.y = a.y + b.y + bb.y;
    v.z = a.z + b.z + bb.z; v.w = a.w + b.w + bb.w;
    if (m[r]) { v.x = 0.0f; v.y = 0.0f; v.z = 0.0f; v.w = 0.0f; }
    ((float4*)out)[i] = v;
}

// ---------------- causal depthwise conv + SiLU (both dirs) ----------------
__global__ void dwconv_k(const bf* __restrict__ xz,
                         const float* __restrict__ cwf, const float* __restrict__ cbf,
                         const float* __restrict__ cwb, const float* __restrict__ cbb,
                         bf* __restrict__ out) {
    int idx = blockIdx.x * blockDim.x + threadIdx.x;
    if (idx >= 2*BL*DI) return;
    int dir = idx >> 22;
    int r = idx & ((1 << 22) - 1);
    int d = r & (DI - 1);
    int row = r >> 10;
    int l = row & (SEQL - 1);
    const bf* xzd = xz + ((size_t)dir << 23);
    const float* cw = dir ? cwb : cwf;
    float acc = (dir ? cbb : cbf)[d];
#pragma unroll
    for (int k = 0; k < 4; k++) {
        int lp = l - 3 + k;
        if (lp >= 0)
            acc = fmaf(cw[d*4 + k], __bfloat162float(xzd[(size_t)(row - l + lp)*XZW + d]), acc);
    }
    out[((size_t)dir << 22) + r] = __float2bfloat16(siluf(acc));
}

// -------- delta = softplus(xdbc @ dt_w.T + dt_b); sums split-K partials;
// -------- blockIdx.x==0 also writes combined B/C columns for the scan --------
__global__ __launch_bounds__(256)
void dt_k(const float* __restrict__ xdbc,
          const float* __restrict__ wf, const float* __restrict__ dbf,
          const float* __restrict__ wb, const float* __restrict__ dbb,
          float* __restrict__ delta, float* __restrict__ xsum) {
    int dir = blockIdx.z;
    const float* x0 = xdbc + (size_t)dir * 2 * BL * 64;
    const float* x1 = x0 + (size_t)BL * 64;
    delta += (size_t)dir * BL * DI;
    xsum  += (size_t)dir * BL * 64;
    const float* dt_w = dir ? wb : wf;
    const float* dt_b = dir ? dbb : dbf;
    __shared__ float xs[32][32];
    int t = threadIdx.x;
    int d0 = blockIdx.x * 256, m0 = blockIdx.y * 32;
#pragma unroll
    for (int i = 0; i < 4; i++) {
        int idx = t + i * 256;
        int rr = idx >> 5, c = idx & 31;
        size_t off = (size_t)(m0 + rr) * 64 + c;
        xs[rr][c] = x0[off] + x1[off];
    }
    if (blockIdx.x == 0) {
#pragma unroll
        for (int i = 0; i < 4; i++) {
            int idx = t + i * 256;
            int rr = idx >> 5, c = 32 + (idx & 31);
            size_t off = (size_t)(m0 + rr) * 64 + c;
            xsum[off] = x0[off] + x1[off];
        }
    }
    int d = d0 + t;
    float4 wr[8];
#pragma unroll
    for (int j = 0; j < 8; j++) wr[j] = *(const float4*)(dt_w + (size_t)d*DTR + j*4);
    float b = dt_b[d];
    __syncthreads();
#pragma unroll 4
    for (int row = 0; row < 32; row++) {
        float acc = b;
#pragma unroll
        for (int j = 0; j < 8; j++) {
            float4 x4 = *(const float4*)&xs[row][j*4];
            acc = fmaf(wr[j].x, x4.x, acc);
            acc = fmaf(wr[j].y, x4.y, acc);
            acc = fmaf(wr[j].z, x4.z, acc);
            acc = fmaf(wr[j].w, x4.w, acc);
        }
        delta[(size_t)(m0 + row) * DI + d] = softplusf(acc);
    }
}

// ======== selective scan + gate: 4 threads per d, 4 states each ========
__global__ __launch_bounds__(128)
void scan_k(const float* __restrict__ delta, const bf* __restrict__ u,
            const float* __restrict__ xsum, const bf* __restrict__ xz,
            const float* __restrict__ Af, const float* __restrict__ Df,
            const float* __restrict__ Ab, const float* __restrict__ Db,
            bf* __restrict__ y) {
    int dir = blockIdx.z;
    delta += (size_t)dir * BL * DI;
    u     += (size_t)dir * BL * DI;
    xsum  += (size_t)dir * BL * 64;
    xz    += (size_t)dir * BL * XZW;
    const float* A_log = dir ? Ab : Af;
    const float* Dv    = dir ? Db : Df;
    int t = threadIdx.x;
    int q = t & 3;
    int d = blockIdx.x * 32 + (t >> 2);
    int b = blockIdx.y;

    float aa[4];
#pragma unroll
    for (int n = 0; n < 4; n++)
        aa[n] = -__expf(A_log[d * DS + q*4 + n]) * 1.4426950408889634f;
    float Dd = Dv[d];
    float h[4];
#pragma unroll
    for (int n = 0; n < 4; n++) h[n] = 0.0f;

    int base = b * SEQL;
    const float* pd = delta + (size_t)base * DI + d;
    const bf*    pu = u     + (size_t)base * DI + d;
    const bf*    pz = xz    + (size_t)base * XZW + DI + d;
    const float* pb = xsum  + (size_t)base * 64 + 32 + q*4;
    bf*          py = y + (size_t)base * 2048 + dir*1024 + d;

    float de0 = pd[0], de1 = pd[DI];
    float uu0 = __bfloat162float(pu[0]), uu1 = __bfloat162float(pu[DI]);
    float z0  = __bfloat162float(pz[0]), z1  = __bfloat162float(pz[XZW]);
    float4 B0 = *(const float4*)(pb);
    float4 C0 = *(const float4*)(pb + 16);
    float4 B1 = *(const float4*)(pb + 64);
    float4 C1 = *(const float4*)(pb + 64 + 16);
    for (int l = 0; l < SEQL; l++) {
        float de2 = 0.0f, uu2 = 0.0f, z2 = 0.0f;
        float4 B2, C2;
        if (l + 2 < SEQL) {
            de2 = pd[2*DI];
            uu2 = __bfloat162float(pu[2*DI]);
            z2  = __bfloat162float(pz[2*XZW]);
            B2 = *(const float4*)(pb + 128);
            C2 = *(const float4*)(pb + 128 + 16);
        } else { B2 = B0; C2 = C0; }
        float du = de0 * uu0;
        const float* Bf = (const float*)&B0;
        const float* Cf = (const float*)&C0;
        float a0 = 0.0f, a1 = 0.0f;
#pragma unroll
        for (int n = 0; n < 4; n++) {
            float dA = exp2f(de0 * aa[n]);
            h[n] = fmaf(dA, h[n], du * Bf[n]);
            float tt = h[n] * Cf[n];
            if (n & 1) a1 += tt; else a0 += tt;
        }
        float part = a0 + a1;
        part += __shfl_xor_sync(0xffffffffu, part, 1);
        part += __shfl_xor_sync(0xffffffffu, part, 2);
        if (q == 0) {
            float yy = part + uu0 * Dd;
            float sg = z0 / (1.0f + __expf(-z0));
            py[0] = __float2bfloat16(yy * sg);
        }
        pd += DI; pu += DI; pz += XZW; pb += 64; py += 2048;
        de0 = de1; de1 = de2;
        uu0 = uu1; uu1 = uu2;
        z0 = z1;   z1 = z2;
        B0 = B1; C0 = C1;
        B1 = B2; C1 = C2;
    }
}

// ---------------- launch ----------------
template <typename T>
static T* symp(const void* sym) {
    void* p = nullptr;
    cudaGetSymbolAddress(&p, sym);
    return (T*)p;
}

#define SMEM2_128 (2 * 256 * KST * 2)   // 73728
#define SMEM2_64  (2 * 192 * KST * 2)   // 55296

extern "C" void kernel_launch(void* const* d_in, const int* in_sizes, int n_in,
                              void* d_out, int out_size) {
    const int*           x      = (const int*)d_in[0];
    const unsigned char* m      = (const unsigned char*)d_in[2];
    const float*         emb    = (const float*)d_in[3];
    const float*         conv_w = (const float*)d_in[4];
    const float*         conv_b = (const float*)d_in[5];
    const float*         ln_g   = (const float*)d_in[6];
    const float*         ln_b   = (const float*)d_in[7];
    const float*         proj_b = (const float*)d_in[9];
    float* out = (float*)d_out;

    bf*    h    = symp<bf>(g_h);
    float* tmp  = symp<float>(g_tmp);
    bf*    xz   = symp<bf>(g_xz);
    bf*    u    = symp<bf>(g_u);
    float* dl   = symp<float>(g_delta);
    float* xdbc = symp<float>(g_xdbc);
    float* xs   = symp<float>(g_xs);
    bf*    y    = symp<bf>(g_y);
    bf*    cwt  = symp<bf>(g_cwt);
    bf*    inw  = symp<bf>(g_inw);
    bf*    xw   = symp<bf>(g_xw);
    bf*    owT  = symp<bf>(g_owT);
    bf*    prw  = symp<bf>(g_projw);
    bf*    wfu  = symp<bf>(g_wfuse);

    cudaFuncSetAttribute(conv256, cudaFuncAttributeMaxDynamicSharedMemorySize, SMEM2_128);
    cudaFuncSetAttribute((const void*)gemm256<0>, cudaFuncAttributeMaxDynamicSharedMemorySize, SMEM2_128);
    cudaFuncSetAttribute((const void*)gemm256<1>, cudaFuncAttributeMaxDynamicSharedMemorySize, SMEM2_128);
    cudaFuncSetAttribute(gemm_xd, cudaFuncAttributeMaxDynamicSharedMemorySize, SMEM2_64);

    // 1: merged weight conversion
    {
        CvtP p;
        p.s[0] = (const float*)d_in[10];  p.d[0] = inw;
        p.s[1] = (const float*)d_in[19];  p.d[1] = inw + (size_t)XZW*CH;
        p.s[2] = (const float*)d_in[13];  p.d[2] = xw;
        p.s[3] = (const float*)d_in[22];  p.d[3] = xw + (size_t)64*DI;
        p.s[4] = (const float*)d_in[8];   p.d[4] = prw;
        p.owf  = (const float*)d_in[18];
        p.owb  = (const float*)d_in[27];
        cvt_all<<<3*CH + 256 + 2768, 256>>>(conv_w, p);
    }
    // 2: Wfuse[c][dir*1024+e] = sum_k projw[c][dir*CH+k] * owT[dir][e][k]
    gemm256<0><<<dim3(DI/128, CH/128, 2), 256, SMEM2_128>>>(
        prw, owT, wfu, CH, 2*CH, CH, 2048, 0,
        (size_t)CH, (size_t)DI*CH, (size_t)DI);
    // 3: embedding
    embed_k<<<(BL*CH + 255)/256, 256>>>(x, emb, h);

    // 4-9: conv stack (launch #6 = conv layer 1 for ncu capture)
    for (int layer = 0; layer < 3; layer++) {
        conv256<<<dim3(CH/128, BL/128, 2), 256, SMEM2_128>>>(
            h, cwt + (size_t)layer*KW*CH*CH, tmp);
        ln_k<<<BL, 128>>>(tmp, conv_b + layer*CH, ln_g + layer*CH, ln_b + layer*CH, m, h);
    }

    const float* mcwf = (const float*)d_in[11];
    const float* mcbf = (const float*)d_in[12];
    const float* mcwb = (const float*)d_in[20];
    const float* mcbb = (const float*)d_in[21];
    const float* dtwf = (const float*)d_in[14];
    const float* dtbf = (const float*)d_in[15];
    const float* dtwb = (const float*)d_in[23];
    const float* dtbb = (const float*)d_in[24];
    const float* Alf  = (const float*)d_in[16];
    const float* Dvf  = (const float*)d_in[17];
    const float* Alb  = (const float*)d_in[25];
    const float* Dvb  = (const float*)d_in[26];

    // in-proj: xz[dir] = h(rev if dir) @ inw[dir]^T
    gemm256<0><<<dim3(XZW/128, BL/128, 2), 256, SMEM2_128>>>(
        h, inw, xz, CH, CH, CH, XZW, 1,
        0, (size_t)XZW*CH, (size_t)BL*XZW);
    // depthwise conv + silu
    dwconv_k<<<(2*BL*DI + 255)/256, 256>>>(xz, mcwf, mcbf, mcwb, mcbb, u);
    // xdbc partials = u @ xw^T, split-K=2 (z = dir*2 + kh)
    gemm_xd<<<dim3(1, BL/128, 4), 128, SMEM2_64>>>(u, xw, xdbc, 512);
    // delta (+ B/C combine into xs)
    dt_k<<<dim3(DI/256, BL/32, 2), 256>>>(xdbc, dtwf, dtbf, dtwb, dtbb, dl, xs);
    // selective scan + gate -> y [row][dir*1024+d]
    scan_k<<<dim3(DI/32, BATCH, 2), 128>>>(dl, u, xs, xz, Alf, Dvf, Alb, Dvb, y);
    // fused out-proj + final projection, split-K=2: partials into tmp
    gemm256<1><<<dim3(CH/128, BL/128, 2), 256, SMEM2_128>>>(
        y, wfu, tmp, 1024, 2048, 2048, CH, 0,
        (size_t)1024, (size_t)1024, (size_t)BL*CH);
    // combine partials + bias + mask -> out
    comb_k<<<(BL*CH/4 + 255)/256, 256>>>(tmp, proj_b, m, out);
}